// round 12
// baseline (speedup 1.0000x reference)
#include <cuda_runtime.h>
#include <cuda_bf16.h>
#include <math.h>
#include <stdint.h>

// ---------------------------------------------------------------------------
// Scratch (__device__ globals; no allocations allowed)
// ---------------------------------------------------------------------------
__device__ float g_Q [(size_t)4096 * 1024];   // out-proj result (a+x)
__device__ float g_K [(size_t)4096 * 1024];   // h = LN1(...)
__device__ float g_V [(size_t)4096 * 1024];   // ffn2 result fp32
__device__ float g_Y [(size_t)4096 * 1024];   // Yhi/Ylo bf16 halves
__device__ unsigned short g_Ahi[(size_t)4096 * 4096];
__device__ unsigned short g_Alo[(size_t)4096 * 4096];
__device__ unsigned short g_Whi[(size_t)12 * 1024 * 1024];
__device__ unsigned short g_Wlo[(size_t)12 * 1024 * 1024];
__device__ unsigned short g_Qhi [(size_t)4096 * 1024];
__device__ unsigned short g_Qlo [(size_t)4096 * 1024];
__device__ unsigned short g_Khi [(size_t)4096 * 1024];
__device__ unsigned short g_Klo [(size_t)4096 * 1024];
__device__ unsigned short g_Vhi [(size_t)4096 * 1024];  // V natural layout
__device__ unsigned short g_Vlo [(size_t)4096 * 1024];

__device__ __forceinline__ uint32_t smem_u32(const void* p) {
    uint32_t a;
    asm("{ .reg .u64 t; cvta.to.shared.u64 t, %1; cvt.u32.u64 %0, t; }"
        : "=r"(a) : "l"(p));
    return a;
}
__device__ __forceinline__ void cpa16(uint32_t s, const void* g) {
    asm volatile("cp.async.cg.shared.global [%0], [%1], 16;"
                 :: "r"(s), "l"(__cvta_generic_to_global(g)) : "memory");
}
__device__ __forceinline__ void cp_commit() {
    asm volatile("cp.async.commit_group;" ::: "memory");
}
template<int N>
__device__ __forceinline__ void cp_wait() {
    asm volatile("cp.async.wait_group %0;" :: "n"(N) : "memory");
}
__device__ __forceinline__ void ldm_x4(uint32_t* r, uint32_t saddr) {
    asm volatile("ldmatrix.sync.aligned.m8n8.x4.shared.b16 {%0,%1,%2,%3}, [%4];"
                 : "=r"(r[0]), "=r"(r[1]), "=r"(r[2]), "=r"(r[3]) : "r"(saddr));
}
__device__ __forceinline__ void ldm_x4_t(uint32_t* r, uint32_t saddr) {
    asm volatile("ldmatrix.sync.aligned.m8n8.x4.trans.shared.b16 {%0,%1,%2,%3}, [%4];"
                 : "=r"(r[0]), "=r"(r[1]), "=r"(r[2]), "=r"(r[3]) : "r"(saddr));
}
__device__ __forceinline__ void mma16816(float* c, const uint32_t* a, const uint32_t* b) {
    asm volatile("mma.sync.aligned.m16n8k16.row.col.f32.bf16.bf16.f32 "
                 "{%0,%1,%2,%3}, {%4,%5,%6,%7}, {%8,%9}, {%0,%1,%2,%3};"
                 : "+f"(c[0]), "+f"(c[1]), "+f"(c[2]), "+f"(c[3])
                 : "r"(a[0]), "r"(a[1]), "r"(a[2]), "r"(a[3]),
                   "r"(b[0]), "r"(b[1]));
}
__device__ __forceinline__ float ex2(float x) {
    float r;
    asm("ex2.approx.f32 %0, %1;" : "=f"(r) : "f"(x));
    return r;
}
__device__ __forceinline__ float gelu_f(float v) {
    return 0.5f * v * (1.0f + erff(v * 0.70710678118654752f));
}
__device__ __forceinline__ void bfsplit2(float x, float y, uint32_t& hi, uint32_t& lo) {
    __nv_bfloat16 hx = __float2bfloat16(x), hy = __float2bfloat16(y);
    hi = ((uint32_t)(*(unsigned short*)&hy) << 16) | (uint32_t)(*(unsigned short*)&hx);
    __nv_bfloat16 lx = __float2bfloat16(x - __bfloat162float(hx));
    __nv_bfloat16 ly = __float2bfloat16(y - __bfloat162float(hy));
    lo = ((uint32_t)(*(unsigned short*)&ly) << 16) | (uint32_t)(*(unsigned short*)&lx);
}

// ---------------------------------------------------------------------------
// Tensor-core dense GEMM (R9 best config — unchanged).
// k-chunk 32, 2-stage, ROWB 80, 2 CTAs/SM, B persistent / A streamed.
// ---------------------------------------------------------------------------
#define ROWB   80
#define TILEB  (128 * ROWB)
#define STAGEB (4 * TILEB)
#define NSTAGE 2
#define TG_SMEM (NSTAGE * STAGEB)    // 81920 -> 2 CTAs/SM

template<int EPI>
__global__ __launch_bounds__(256, 2)
void tgemm_kernel(const unsigned short* __restrict__ Ahi16,
                  const unsigned short* __restrict__ Alo16,
                  const unsigned short* __restrict__ Whi16,
                  const unsigned short* __restrict__ Wlo16,
                  size_t wz,
                  const float* __restrict__ bias0, const float* __restrict__ bias1,
                  const float* __restrict__ bias2,
                  const float* __restrict__ R,
                  float* __restrict__ Cf0, float* __restrict__ Cf1, float* __restrict__ Cf2,
                  unsigned short* __restrict__ Ch0, unsigned short* __restrict__ Ch1,
                  unsigned short* __restrict__ Ch2,
                  unsigned short* __restrict__ Cl0, unsigned short* __restrict__ Cl1,
                  unsigned short* __restrict__ Cl2,
                  int M, int N, int K)
{
    extern __shared__ __align__(128) char smem[];
    const int z = blockIdx.z;
    const unsigned short* Bh = Whi16 + wz * z;
    const unsigned short* Bl = Wlo16 + wz * z;
    const float* bias = (z == 0) ? bias0 : (z == 1) ? bias1 : bias2;
    float*          Cf = (z == 0) ? Cf0 : (z == 1) ? Cf1 : Cf2;
    unsigned short* Ch = (z == 0) ? Ch0 : (z == 1) ? Ch1 : Ch2;
    unsigned short* Cl = (z == 0) ? Cl0 : (z == 1) ? Cl1 : Cl2;

    const uint32_t sbase = smem_u32(smem);
    const int t    = threadIdx.x;
    const int wid  = t >> 5;
    const int lane = t & 31;
    const int m0   = blockIdx.y * 128;
    const int n0   = blockIdx.x * 128;
    const int wm   = (wid & 1) * 64;
    const int wn   = (wid >> 1) * 32;

    const int lrow = t >> 1;
    const int lu   = (t & 1) * 2;
    const unsigned short* pAh = Ahi16 + (size_t)(m0 + lrow) * K + lu * 8;
    const unsigned short* pAl = Alo16 + (size_t)(m0 + lrow) * K + lu * 8;
    const unsigned short* pBh = Bh    + (size_t)(n0 + lrow) * K + lu * 8;
    const unsigned short* pBl = Bl    + (size_t)(n0 + lrow) * K + lu * 8;
    const uint32_t sRow = (uint32_t)lrow * ROWB + lu * 16;

    #define LOAD_STAGE(cc, ss) do {                                        \
        const uint32_t sb_ = sbase + (ss) * STAGEB + sRow;                  \
        const size_t  ko_ = (size_t)(cc) * 32;                              \
        cpa16(sb_ + 0 * TILEB,      pAh + ko_);                             \
        cpa16(sb_ + 0 * TILEB + 16, pAh + ko_ + 8);                         \
        cpa16(sb_ + 1 * TILEB,      pAl + ko_);                             \
        cpa16(sb_ + 1 * TILEB + 16, pAl + ko_ + 8);                         \
        cpa16(sb_ + 2 * TILEB,      pBh + ko_);                             \
        cpa16(sb_ + 2 * TILEB + 16, pBh + ko_ + 8);                         \
        cpa16(sb_ + 3 * TILEB,      pBl + ko_);                             \
        cpa16(sb_ + 3 * TILEB + 16, pBl + ko_ + 8);                         \
    } while (0)

    const uint32_t laneA = (uint32_t)(lane & 15) * ROWB + (lane >> 4) * 16;
    const uint32_t laneB = (uint32_t)((lane & 7) + ((lane >> 4) << 3)) * ROWB
                         + ((lane >> 3) & 1) * 16;

    float acc[4][4][4];
    #pragma unroll
    for (int i = 0; i < 4; ++i)
        #pragma unroll
        for (int j = 0; j < 4; ++j)
            #pragma unroll
            for (int q = 0; q < 4; ++q) acc[i][j][q] = 0.0f;

    const int NC = K >> 5;
    LOAD_STAGE(0, 0); cp_commit();

    for (int c = 0; c < NC; ++c) {
        const int s = c & 1;
        if (c + 1 < NC) LOAD_STAGE(c + 1, s ^ 1);
        cp_commit();
        cp_wait<1>();
        __syncthreads();

        const uint32_t stg = sbase + s * STAGEB;
        #pragma unroll
        for (int ks = 0; ks < 2; ++ks) {
            const uint32_t kb = ks * 32;
            uint32_t bh[4][2], bl[4][2];
            #pragma unroll
            for (int p = 0; p < 2; ++p) {
                uint32_t rb[4], rl[4];
                const uint32_t ra = stg + (uint32_t)(wn + p * 16) * ROWB + laneB + kb;
                ldm_x4(rb, ra + 2 * TILEB);
                ldm_x4(rl, ra + 3 * TILEB);
                bh[p * 2 + 0][0] = rb[0]; bh[p * 2 + 0][1] = rb[1];
                bh[p * 2 + 1][0] = rb[2]; bh[p * 2 + 1][1] = rb[3];
                bl[p * 2 + 0][0] = rl[0]; bl[p * 2 + 0][1] = rl[1];
                bl[p * 2 + 1][0] = rl[2]; bl[p * 2 + 1][1] = rl[3];
            }
            #pragma unroll
            for (int mf = 0; mf < 4; ++mf) {
                uint32_t ah[4], al[4];
                const uint32_t ra = stg + (uint32_t)(wm + mf * 16) * ROWB + laneA + kb;
                ldm_x4(ah, ra + 0 * TILEB);
                ldm_x4(al, ra + 1 * TILEB);
                #pragma unroll
                for (int nf = 0; nf < 4; ++nf) {
                    mma16816(acc[mf][nf], ah, bh[nf]);
                    mma16816(acc[mf][nf], ah, bl[nf]);
                    mma16816(acc[mf][nf], al, bh[nf]);
                }
            }
        }
        __syncthreads();
    }

    const int rbase = lane >> 2;
    const int cbase = (lane & 3) * 2;
    #pragma unroll
    for (int mf = 0; mf < 4; ++mf) {
        #pragma unroll
        for (int nf = 0; nf < 4; ++nf) {
            const int col = n0 + wn + nf * 8 + cbase;
            const float2 bb = *(const float2*)&bias[col];
            #pragma unroll
            for (int h = 0; h < 2; ++h) {
                const int row = m0 + wm + mf * 16 + rbase + h * 8;
                float2 rv;
                rv.x = acc[mf][nf][h * 2 + 0] + bb.x;
                rv.y = acc[mf][nf][h * 2 + 1] + bb.y;
                if (EPI == 1) { rv.x = gelu_f(rv.x); rv.y = gelu_f(rv.y); }
                if (EPI == 2) {
                    const float2 rr = *(const float2*)&R[(size_t)row * N + col];
                    rv.x += rr.x; rv.y += rr.y;
                }
                if (Cf) *(float2*)&Cf[(size_t)row * N + col] = rv;
                if (Ch) {
                    uint32_t hi, lo;
                    bfsplit2(rv.x, rv.y, hi, lo);
                    *(uint32_t*)&Ch[(size_t)row * N + col] = hi;
                    *(uint32_t*)&Cl[(size_t)row * N + col] = lo;
                }
            }
        }
    }
    #undef LOAD_STAGE
}

// ---------------------------------------------------------------------------
// fp32 -> bf16 hi/lo split kernels
// ---------------------------------------------------------------------------
__device__ __forceinline__ void split1(float v, unsigned short& h, unsigned short& l) {
    __nv_bfloat16 hb = __float2bfloat16(v);
    __nv_bfloat16 lb = __float2bfloat16(v - __bfloat162float(hb));
    h = *(unsigned short*)&hb;
    l = *(unsigned short*)&lb;
}

__global__ __launch_bounds__(256)
void split_kernel(const float* __restrict__ X, unsigned short* __restrict__ hi,
                  unsigned short* __restrict__ lo, int n4)
{
    int i = blockIdx.x * 256 + threadIdx.x;
    if (i >= n4) return;
    float4 v = ((const float4*)X)[i];
    ushort4 h, l;
    split1(v.x, h.x, l.x); split1(v.y, h.y, l.y);
    split1(v.z, h.z, l.z); split1(v.w, h.w, l.w);
    ((ushort4*)hi)[i] = h;
    ((ushort4*)lo)[i] = l;
}

// transpose+split; z-fused for up to 4 equal-shaped weights
__global__ __launch_bounds__(256)
void tsplit_kernel(const float* __restrict__ W0, const float* __restrict__ W1,
                   const float* __restrict__ W2, const float* __restrict__ W3,
                   unsigned short* __restrict__ Thi, unsigned short* __restrict__ Tlo,
                   size_t zstride, int K, int N)
{
    __shared__ float s[32][33];
    const int z = blockIdx.z;
    const float* W = (z == 0) ? W0 : (z == 1) ? W1 : (z == 2) ? W2 : W3;
    unsigned short* Th = Thi + zstride * z;
    unsigned short* Tl = Tlo + zstride * z;
    const int tx = threadIdx.x, ty = threadIdx.y;
    const int nb = blockIdx.x * 32, kb = blockIdx.y * 32;
    #pragma unroll
    for (int i = 0; i < 4; ++i)
        s[ty + i * 8][tx] = W[(size_t)(kb + ty + i * 8) * N + nb + tx];
    __syncthreads();
    #pragma unroll
    for (int i = 0; i < 4; ++i) {
        const float v = s[tx][ty + i * 8];
        unsigned short h, l;
        split1(v, h, l);
        const size_t o = (size_t)(nb + ty + i * 8) * K + kb + tx;
        Th[o] = h; Tl[o] = l;
    }
}

// ---------------------------------------------------------------------------
// Flash attention via mma.sync; V natural layout (ldmatrix.trans).
// 128 threads / 128 queries per CTA -> 2 CTAs/SM with FULL tile reuse.
// Each warp owns 32 q-rows (two 16-row fragment groups); K/V fragments
// are loaded once per warp and reused across both groups.
// ---------------------------------------------------------------------------
#define AROWB   144
#define ATT_QLO 18432
#define ATT_KV  36864
#define ATT_STG 36864
#define ATT_MB  (ATT_KV + 2 * ATT_STG)
#define ATT_SMEM (ATT_MB + 512)       // ~108.5 KB -> 2 CTAs/SM (217 KB)
#define SCL2    0.18033688011112042591f   // 0.125 * log2(e)

__global__ __launch_bounds__(128, 2)
void attn_mma_kernel(const unsigned short* __restrict__ Qhi,
                     const unsigned short* __restrict__ Qlo,
                     const unsigned short* __restrict__ Khi,
                     const unsigned short* __restrict__ Klo,
                     const unsigned short* __restrict__ Vhi,
                     const unsigned short* __restrict__ Vlo,
                     const int* __restrict__ mask,
                     unsigned short* __restrict__ Yhi,
                     unsigned short* __restrict__ Ylo)
{
    extern __shared__ __align__(128) char smem[];
    const uint32_t sb = smem_u32(smem);
    const int t    = threadIdx.x;
    const int lane = t & 31;
    const int w    = t >> 5;              // 0..3, owns q-rows w*32..w*32+31
    const int q0   = blockIdx.x * 128;
    const int bh   = blockIdx.y;
    const int tokb = (bh >> 4) * 2048;
    const int colb = (bh & 15) * 64;

    const uint32_t laneA = (uint32_t)(lane & 15) * AROWB + (lane >> 4) * 16;
    const uint32_t laneB = (uint32_t)((lane & 7) + ((lane >> 4) << 3)) * AROWB
                         + ((lane >> 3) & 1) * 16;
    const uint32_t laneBT = (uint32_t)((lane & 7) + ((lane >> 3) & 1) * 8) * AROWB
                          + (lane >> 4) * 16;

    // Q tile: 128 rows x 128B (hi+lo). 128 threads: one row each, 8 chunks.
    {
        const int row = t;
        const size_t g = (size_t)(tokb + q0 + row) * 1024 + colb;
        const uint32_t sr = (uint32_t)row * AROWB;
        #pragma unroll
        for (int i = 0; i < 8; ++i) {
            cpa16(sb + sr + i * 16,           Qhi + g + i * 8);
            cpa16(sb + ATT_QLO + sr + i * 16, Qlo + g + i * 8);
        }
    }

    // KV tiles: 4 x 64 rows x 128B. 128 threads: 2 per row, 4 chunks each.
    auto LOADKV = [&](int tile, int s) {
        const int kv0 = tile * 64;
        const int row = t >> 1;
        const uint32_t st = sb + ATT_KV + s * ATT_STG;
        const size_t gk = (size_t)(tokb + kv0 + row) * 1024 + colb;
        const uint32_t sr = (uint32_t)row * AROWB;
        #pragma unroll
        for (int i = 0; i < 4; ++i) {
            const int ch = (t & 1) * 4 + i;
            cpa16(st +         sr + ch * 16, Khi + gk + ch * 8);
            cpa16(st +  9216 + sr + ch * 16, Klo + gk + ch * 8);
            cpa16(st + 18432 + sr + ch * 16, Vhi + gk + ch * 8);
            cpa16(st + 27648 + sr + ch * 16, Vlo + gk + ch * 8);
        }
        if (t < 64) {
            float* mb = (float*)(smem + ATT_MB) + s * 64;
            mb[t] = (mask[tokb + kv0 + t] == 0) ? -1e30f : 0.0f;
        }
    };

    LOADKV(0, 0); cp_commit();
    LOADKV(1, 1); cp_commit();

    cp_wait<1>();
    __syncthreads();

    // persistent Q fragments for both 16-row groups
    uint32_t qh[2][4][4], ql[2][4][4];
    #pragma unroll
    for (int g = 0; g < 2; ++g)
        #pragma unroll
        for (int fk = 0; fk < 4; ++fk) {
            const uint32_t ra = sb + (uint32_t)(w * 32 + g * 16) * AROWB + laneA + fk * 32;
            ldm_x4(qh[g][fk], ra);
            ldm_x4(ql[g][fk], ra + ATT_QLO);
        }

    float of[2][8][4];
    #pragma unroll
    for (int g = 0; g < 2; ++g)
        #pragma unroll
        for (int i = 0; i < 8; ++i)
            #pragma unroll
            for (int j = 0; j < 4; ++j) of[g][i][j] = 0.0f;
    float mA[2] = {-1e30f, -1e30f}, mB[2] = {-1e30f, -1e30f};
    float lA[2] = {0.0f, 0.0f},     lB[2] = {0.0f, 0.0f};
    const int c0 = (lane & 3) * 2;

    for (int tile = 0; tile < 32; ++tile) {
        const int s = tile & 1;
        if (tile > 0) { cp_wait<1>(); __syncthreads(); }
        const uint32_t kst = sb + ATT_KV + s * ATT_STG;
        const float* mb = (const float*)(smem + ATT_MB) + s * 64;

        // ---- S = Q K^T for both groups; K frags loaded once per warp ----
        float sf[2][8][4];
        #pragma unroll
        for (int g = 0; g < 2; ++g)
            #pragma unroll
            for (int i = 0; i < 8; ++i)
                #pragma unroll
                for (int j = 0; j < 4; ++j) sf[g][i][j] = 0.0f;

        #pragma unroll
        for (int fk = 0; fk < 4; ++fk) {
            uint32_t kh[8][2], kl[8][2];
            #pragma unroll
            for (int p = 0; p < 4; ++p) {
                uint32_t r0[4], r1[4];
                const uint32_t ra = kst + (uint32_t)(p * 16) * AROWB + laneB + fk * 32;
                ldm_x4(r0, ra);
                ldm_x4(r1, ra + 9216);
                kh[p * 2 + 0][0] = r0[0]; kh[p * 2 + 0][1] = r0[1];
                kh[p * 2 + 1][0] = r0[2]; kh[p * 2 + 1][1] = r0[3];
                kl[p * 2 + 0][0] = r1[0]; kl[p * 2 + 0][1] = r1[1];
                kl[p * 2 + 1][0] = r1[2]; kl[p * 2 + 1][1] = r1[3];
            }
            #pragma unroll
            for (int g = 0; g < 2; ++g)
                #pragma unroll
                for (int nf = 0; nf < 8; ++nf) {
                    mma16816(sf[g][nf], qh[g][fk], kh[nf]);
                    mma16816(sf[g][nf], qh[g][fk], kl[nf]);
                    mma16816(sf[g][nf], ql[g][fk], kh[nf]);
                }
        }

        // ---- online softmax per group (exp2 domain) ----
        #pragma unroll
        for (int g = 0; g < 2; ++g) {
            float pmA = -1e30f, pmB = -1e30f;
            #pragma unroll
            for (int nf = 0; nf < 8; ++nf) {
                const float m0 = mb[nf * 8 + c0];
                const float m1 = mb[nf * 8 + c0 + 1];
                sf[g][nf][0] = fmaf(sf[g][nf][0], SCL2, m0);
                sf[g][nf][1] = fmaf(sf[g][nf][1], SCL2, m1);
                sf[g][nf][2] = fmaf(sf[g][nf][2], SCL2, m0);
                sf[g][nf][3] = fmaf(sf[g][nf][3], SCL2, m1);
                pmA = fmaxf(pmA, fmaxf(sf[g][nf][0], sf[g][nf][1]));
                pmB = fmaxf(pmB, fmaxf(sf[g][nf][2], sf[g][nf][3]));
            }
            pmA = fmaxf(pmA, __shfl_xor_sync(0xffffffffu, pmA, 1));
            pmA = fmaxf(pmA, __shfl_xor_sync(0xffffffffu, pmA, 2));
            pmB = fmaxf(pmB, __shfl_xor_sync(0xffffffffu, pmB, 1));
            pmB = fmaxf(pmB, __shfl_xor_sync(0xffffffffu, pmB, 2));
            const float mnA = fmaxf(mA[g], pmA), mnB = fmaxf(mB[g], pmB);
            const float alA = ex2(mA[g] - mnA), alB = ex2(mB[g] - mnB);
            mA[g] = mnA; mB[g] = mnB;
            float rsA = 0.0f, rsB = 0.0f;
            #pragma unroll
            for (int nf = 0; nf < 8; ++nf) {
                sf[g][nf][0] = ex2(sf[g][nf][0] - mnA);
                sf[g][nf][1] = ex2(sf[g][nf][1] - mnA);
                sf[g][nf][2] = ex2(sf[g][nf][2] - mnB);
                sf[g][nf][3] = ex2(sf[g][nf][3] - mnB);
                rsA += sf[g][nf][0] + sf[g][nf][1];
                rsB += sf[g][nf][2] + sf[g][nf][3];
            }
            rsA += __shfl_xor_sync(0xffffffffu, rsA, 1);
            rsA += __shfl_xor_sync(0xffffffffu, rsA, 2);
            rsB += __shfl_xor_sync(0xffffffffu, rsB, 1);
            rsB += __shfl_xor_sync(0xffffffffu, rsB, 2);
            lA[g] = lA[g] * alA + rsA;
            lB[g] = lB[g] * alB + rsB;
            #pragma unroll
            for (int nf = 0; nf < 8; ++nf) {
                of[g][nf][0] *= alA; of[g][nf][1] *= alA;
                of[g][nf][2] *= alB; of[g][nf][3] *= alB;
            }
        }

        // ---- O += P @ V for both groups; V frags loaded once per warp ----
        #pragma unroll
        for (int fk = 0; fk < 4; ++fk) {
            uint32_t vh[8][2], vl[8][2];
            #pragma unroll
            for (int p = 0; p < 4; ++p) {
                uint32_t r0[4], r1[4];
                const uint32_t ra = kst + 18432 + (uint32_t)(fk * 16) * AROWB
                                  + laneBT + p * 32;
                ldm_x4_t(r0, ra);
                ldm_x4_t(r1, ra + 9216);
                vh[p * 2 + 0][0] = r0[0]; vh[p * 2 + 0][1] = r0[1];
                vh[p * 2 + 1][0] = r0[2]; vh[p * 2 + 1][1] = r0[3];
                vl[p * 2 + 0][0] = r1[0]; vl[p * 2 + 0][1] = r1[1];
                vl[p * 2 + 1][0] = r1[2]; vl[p * 2 + 1][1] = r1[3];
            }
            #pragma unroll
            for (int g = 0; g < 2; ++g) {
                uint32_t aHi[4], aLo[4];
                bfsplit2(sf[g][2 * fk][0],     sf[g][2 * fk][1],     aHi[0], aLo[0]);
                bfsplit2(sf[g][2 * fk][2],     sf[g][2 * fk][3],     aHi[1], aLo[1]);
                bfsplit2(sf[g][2 * fk + 1][0], sf[g][2 * fk + 1][1], aHi[2], aLo[2]);
                bfsplit2(sf[g][2 * fk + 1][2], sf[g][2 * fk + 1][3], aHi[3], aLo[3]);
                #pragma unroll
                for (int nf = 0; nf < 8; ++nf) {
                    mma16816(of[g][nf], aHi, vh[nf]);
                    mma16816(of[g][nf], aHi, vl[nf]);
                    mma16816(of[g][nf], aLo, vh[nf]);
                }
            }
        }

        __syncthreads();
        if (tile + 2 < 32) LOADKV(tile + 2, s);
        cp_commit();
    }

    const int rA = lane >> 2;
    #pragma unroll
    for (int g = 0; g < 2; ++g) {
        const float iA = 1.0f / lA[g], iB = 1.0f / lB[g];
        const int rowA = tokb + q0 + w * 32 + g * 16 + rA;
        #pragma unroll
        for (int nf = 0; nf < 8; ++nf) {
            const int col = colb + nf * 8 + c0;
            uint32_t h0, l0, h1, l1;
            bfsplit2(of[g][nf][0] * iA, of[g][nf][1] * iA, h0, l0);
            bfsplit2(of[g][nf][2] * iB, of[g][nf][3] * iB, h1, l1);
            *(uint32_t*)&Yhi[(size_t)rowA * 1024 + col]       = h0;
            *(uint32_t*)&Ylo[(size_t)rowA * 1024 + col]       = l0;
            *(uint32_t*)&Yhi[(size_t)(rowA + 8) * 1024 + col] = h1;
            *(uint32_t*)&Ylo[(size_t)(rowA + 8) * 1024 + col] = l1;
        }
    }
}

// ---------------------------------------------------------------------------
// LayerNorm: one row per CTA; optional fused bf16 hi/lo split output
// ---------------------------------------------------------------------------
__global__ __launch_bounds__(256)
void ln_kernel(const float* __restrict__ X, const float* __restrict__ w,
               const float* __restrict__ b, float* __restrict__ out,
               unsigned short* __restrict__ hi, unsigned short* __restrict__ lo)
{
    __shared__ float red[2][8];
    const int t = threadIdx.x;
    const size_t row = blockIdx.x;
    float4 xv = *(const float4*)&X[row * 1024 + t * 4];
    float s  = xv.x + xv.y + xv.z + xv.w;
    float s2 = xv.x * xv.x + xv.y * xv.y + xv.z * xv.z + xv.w * xv.w;
    #pragma unroll
    for (int off = 16; off; off >>= 1) {
        s  += __shfl_xor_sync(0xffffffffu, s,  off);
        s2 += __shfl_xor_sync(0xffffffffu, s2, off);
    }
    if ((t & 31) == 0) { red[0][t >> 5] = s; red[1][t >> 5] = s2; }
    __syncthreads();
    float S = 0.0f, S2 = 0.0f;
    #pragma unroll
    for (int i = 0; i < 8; ++i) { S += red[0][i]; S2 += red[1][i]; }
    const float mean = S * (1.0f / 1024.0f);
    const float var  = S2 * (1.0f / 1024.0f) - mean * mean;
    const float rstd = rsqrtf(var + 1e-5f);
    float4 wv = *(const float4*)&w[t * 4];
    float4 bv = *(const float4*)&b[t * 4];
    float4 r;
    r.x = (xv.x - mean) * rstd * wv.x + bv.x;
    r.y = (xv.y - mean) * rstd * wv.y + bv.y;
    r.z = (xv.z - mean) * rstd * wv.z + bv.z;
    r.w = (xv.w - mean) * rstd * wv.w + bv.w;
    if (out) *(float4*)&out[row * 1024 + t * 4] = r;
    if (hi) {
        uint32_t h0, l0, h1, l1;
        bfsplit2(r.x, r.y, h0, l0);
        bfsplit2(r.z, r.w, h1, l1);
        uint2 hv = make_uint2(h0, h1), lv = make_uint2(l0, l1);
        *(uint2*)&hi[row * 1024 + t * 4] = hv;
        *(uint2*)&lo[row * 1024 + t * 4] = lv;
    }
}

// ---------------------------------------------------------------------------
// launch
// ---------------------------------------------------------------------------
extern "C" void kernel_launch(void* const* d_in, const int* in_sizes, int n_in,
                              void* d_out, int out_size)
{
    (void)in_sizes; (void)n_in; (void)out_size;
    const float* x    = (const float*)d_in[0];
    const int*   mask = (const int*)  d_in[1];
    const float* WQ   = (const float*)d_in[2];
    const float* bQ   = (const float*)d_in[3];
    const float* WK   = (const float*)d_in[4];
    const float* bK   = (const float*)d_in[5];
    const float* WV   = (const float*)d_in[6];
    const float* bV   = (const float*)d_in[7];
    const float* WY   = (const float*)d_in[8];
    const float* bY   = (const float*)d_in[9];
    const float* ln1w = (const float*)d_in[10];
    const float* ln1b = (const float*)d_in[11];
    const float* ln2w = (const float*)d_in[12];
    const float* ln2b = (const float*)d_in[13];
    const float* W1   = (const float*)d_in[14];
    const float* b1   = (const float*)d_in[15];
    const float* W2   = (const float*)d_in[16];
    const float* b2   = (const float*)d_in[17];
    float* out = (float*)d_out;

    float *Qp, *Kp, *Vp, *Yp;
    unsigned short *Ahi, *Alo, *Whi, *Wlo;
    unsigned short *Qhi, *Qlo, *Khi, *Klo, *Vhi, *Vlo;
    cudaGetSymbolAddress((void**)&Qp,  g_Q);
    cudaGetSymbolAddress((void**)&Kp,  g_K);
    cudaGetSymbolAddress((void**)&Vp,  g_V);
    cudaGetSymbolAddress((void**)&Yp,  g_Y);
    cudaGetSymbolAddress((void**)&Ahi, g_Ahi);
    cudaGetSymbolAddress((void**)&Alo, g_Alo);
    cudaGetSymbolAddress((void**)&Whi, g_Whi);
    cudaGetSymbolAddress((void**)&Wlo, g_Wlo);
    cudaGetSymbolAddress((void**)&Qhi, g_Qhi);
    cudaGetSymbolAddress((void**)&Qlo, g_Qlo);
    cudaGetSymbolAddress((void**)&Khi, g_Khi);
    cudaGetSymbolAddress((void**)&Klo, g_Klo);
    cudaGetSymbolAddress((void**)&Vhi, g_Vhi);
    cudaGetSymbolAddress((void**)&Vlo, g_Vlo);

    unsigned short* Yhi = (unsigned short*)Yp;
    unsigned short* Ylo = (unsigned short*)Yp + (size_t)4096 * 1024;

    const size_t MB = (size_t)1024 * 1024;

    cudaFuncSetAttribute(tgemm_kernel<0>,
                         cudaFuncAttributeMaxDynamicSharedMemorySize, TG_SMEM);
    cudaFuncSetAttribute(tgemm_kernel<1>,
                         cudaFuncAttributeMaxDynamicSharedMemorySize, TG_SMEM);
    cudaFuncSetAttribute(tgemm_kernel<2>,
                         cudaFuncAttributeMaxDynamicSharedMemorySize, TG_SMEM);
    cudaFuncSetAttribute(attn_mma_kernel,
                         cudaFuncAttributeMaxDynamicSharedMemorySize, ATT_SMEM);

    dim3 blk(256);
    dim3 tsb(32, 8);

    // weight transposes
    tsplit_kernel<<<dim3(32, 32, 4), tsb>>>(WQ, WK, WV, WY, Whi, Wlo, MB, 1024, 1024);
    tsplit_kernel<<<dim3(128, 32, 1), tsb>>>(W1, W1, W1, W1, Whi + 4 * MB, Wlo + 4 * MB,
                                             0, 1024, 4096);
    tsplit_kernel<<<dim3(32, 128, 1), tsb>>>(W2, W2, W2, W2, Whi + 8 * MB, Wlo + 8 * MB,
                                             0, 4096, 1024);

    // x split
    split_kernel<<<4096, blk>>>(x, Ahi, Alo, (4096 * 1024) / 4);

    // QKV: all three outputs as bf16 splits (V natural layout)
    tgemm_kernel<0><<<dim3(8, 32, 3), blk, TG_SMEM>>>(
        Ahi, Alo, Whi, Wlo, MB, bQ, bK, bV, nullptr,
        nullptr, nullptr, nullptr,
        Qhi, Khi, Vhi,
        Qlo, Klo, Vlo,
        4096, 1024, 1024);

    // attention -> Yhi/Ylo bf16 (128 q/CTA, 128 threads, 2 CTAs/SM)
    attn_mma_kernel<<<dim3(16, 32), dim3(128), ATT_SMEM>>>(
        Qhi, Qlo, Khi, Klo, Vhi, Vlo, mask, Yhi, Ylo);

    // out-proj + residual x -> fp32 g_Q
    tgemm_kernel<2><<<dim3(8, 32, 1), blk, TG_SMEM>>>(
        Yhi, Ylo, Whi + 3 * MB, Wlo + 3 * MB, 0, bY, bY, bY, x,
        Qp, nullptr, nullptr,
        nullptr, nullptr, nullptr,
        nullptr, nullptr, nullptr,
        4096, 1024, 1024);

    // h = LN1 -> fp32 g_K + bf16 split (Qhi/Qlo reused)
    ln_kernel<<<4096, blk>>>(Qp, ln1w, ln1b, Kp, Qhi, Qlo);

    // FFN1: gelu(h@W1+b1) -> bf16 split only
    tgemm_kernel<1><<<dim3(32, 32, 1), blk, TG_SMEM>>>(
        Qhi, Qlo, Whi + 4 * MB, Wlo + 4 * MB, 0, b1, b1, b1, nullptr,
        nullptr, nullptr, nullptr,
        Ahi, nullptr, nullptr,
        Alo, nullptr, nullptr,
        4096, 4096, 1024);

    // FFN2: ff@W2+b2+h -> fp32 g_V
    tgemm_kernel<2><<<dim3(8, 32, 1), blk, TG_SMEM>>>(
        Ahi, Alo, Whi + 8 * MB, Wlo + 8 * MB, 0, b2, b2, b2, Kp,
        Vp, nullptr, nullptr,
        nullptr, nullptr, nullptr,
        nullptr, nullptr, nullptr,
        4096, 1024, 4096);

    // out = LN2
    ln_kernel<<<4096, blk>>>(Vp, ln2w, ln2b, out, nullptr, nullptr);
}

// round 13
// speedup vs baseline: 1.0489x; 1.0489x over previous
#include <cuda_runtime.h>
#include <cuda_bf16.h>
#include <math.h>
#include <stdint.h>

// ---------------------------------------------------------------------------
// Scratch (__device__ globals; no allocations allowed)
// ---------------------------------------------------------------------------
__device__ float g_Q [(size_t)4096 * 1024];   // out-proj result (a+x)
__device__ float g_K [(size_t)4096 * 1024];   // h = LN1(...)
__device__ float g_V [(size_t)4096 * 1024];   // ffn2 result fp32
__device__ float g_Y [(size_t)4096 * 1024];   // Yhi/Ylo bf16 halves
__device__ unsigned short g_Ahi[(size_t)4096 * 4096];
__device__ unsigned short g_Alo[(size_t)4096 * 4096];
__device__ unsigned short g_Whi[(size_t)12 * 1024 * 1024];
__device__ unsigned short g_Wlo[(size_t)12 * 1024 * 1024];
__device__ unsigned short g_Qhi [(size_t)4096 * 1024];
__device__ unsigned short g_Qlo [(size_t)4096 * 1024];
__device__ unsigned short g_Khi [(size_t)4096 * 1024];
__device__ unsigned short g_Klo [(size_t)4096 * 1024];
__device__ unsigned short g_Vhi [(size_t)4096 * 1024];  // V natural layout
__device__ unsigned short g_Vlo [(size_t)4096 * 1024];

__device__ __forceinline__ uint32_t smem_u32(const void* p) {
    uint32_t a;
    asm("{ .reg .u64 t; cvta.to.shared.u64 t, %1; cvt.u32.u64 %0, t; }"
        : "=r"(a) : "l"(p));
    return a;
}
__device__ __forceinline__ void cpa16(uint32_t s, const void* g) {
    asm volatile("cp.async.cg.shared.global [%0], [%1], 16;"
                 :: "r"(s), "l"(__cvta_generic_to_global(g)) : "memory");
}
__device__ __forceinline__ void cp_commit() {
    asm volatile("cp.async.commit_group;" ::: "memory");
}
template<int N>
__device__ __forceinline__ void cp_wait() {
    asm volatile("cp.async.wait_group %0;" :: "n"(N) : "memory");
}
__device__ __forceinline__ void ldm_x4(uint32_t* r, uint32_t saddr) {
    asm volatile("ldmatrix.sync.aligned.m8n8.x4.shared.b16 {%0,%1,%2,%3}, [%4];"
                 : "=r"(r[0]), "=r"(r[1]), "=r"(r[2]), "=r"(r[3]) : "r"(saddr));
}
__device__ __forceinline__ void ldm_x4_t(uint32_t* r, uint32_t saddr) {
    asm volatile("ldmatrix.sync.aligned.m8n8.x4.trans.shared.b16 {%0,%1,%2,%3}, [%4];"
                 : "=r"(r[0]), "=r"(r[1]), "=r"(r[2]), "=r"(r[3]) : "r"(saddr));
}
__device__ __forceinline__ void mma16816(float* c, const uint32_t* a, const uint32_t* b) {
    asm volatile("mma.sync.aligned.m16n8k16.row.col.f32.bf16.bf16.f32 "
                 "{%0,%1,%2,%3}, {%4,%5,%6,%7}, {%8,%9}, {%0,%1,%2,%3};"
                 : "+f"(c[0]), "+f"(c[1]), "+f"(c[2]), "+f"(c[3])
                 : "r"(a[0]), "r"(a[1]), "r"(a[2]), "r"(a[3]),
                   "r"(b[0]), "r"(b[1]));
}
__device__ __forceinline__ float ex2(float x) {
    float r;
    asm("ex2.approx.f32 %0, %1;" : "=f"(r) : "f"(x));
    return r;
}
__device__ __forceinline__ float gelu_f(float v) {
    return 0.5f * v * (1.0f + erff(v * 0.70710678118654752f));
}
__device__ __forceinline__ void bfsplit2(float x, float y, uint32_t& hi, uint32_t& lo) {
    __nv_bfloat16 hx = __float2bfloat16(x), hy = __float2bfloat16(y);
    hi = ((uint32_t)(*(unsigned short*)&hy) << 16) | (uint32_t)(*(unsigned short*)&hx);
    __nv_bfloat16 lx = __float2bfloat16(x - __bfloat162float(hx));
    __nv_bfloat16 ly = __float2bfloat16(y - __bfloat162float(hy));
    lo = ((uint32_t)(*(unsigned short*)&ly) << 16) | (uint32_t)(*(unsigned short*)&lx);
}

// ---------------------------------------------------------------------------
// Tensor-core dense GEMM. k-chunk 32, 2-stage, ROWB 80, 2 CTAs/SM.
// SINGLE __syncthreads per k-chunk: loads issued right after the barrier
// into the stage whose readers finished before it.
// ---------------------------------------------------------------------------
#define ROWB   80
#define TILEB  (128 * ROWB)
#define STAGEB (4 * TILEB)
#define NSTAGE 2
#define TG_SMEM (NSTAGE * STAGEB)    // 81920 -> 2 CTAs/SM

template<int EPI>
__global__ __launch_bounds__(256, 2)
void tgemm_kernel(const unsigned short* __restrict__ Ahi16,
                  const unsigned short* __restrict__ Alo16,
                  const unsigned short* __restrict__ Whi16,
                  const unsigned short* __restrict__ Wlo16,
                  size_t wz,
                  const float* __restrict__ bias0, const float* __restrict__ bias1,
                  const float* __restrict__ bias2,
                  const float* __restrict__ R,
                  float* __restrict__ Cf0, float* __restrict__ Cf1, float* __restrict__ Cf2,
                  unsigned short* __restrict__ Ch0, unsigned short* __restrict__ Ch1,
                  unsigned short* __restrict__ Ch2,
                  unsigned short* __restrict__ Cl0, unsigned short* __restrict__ Cl1,
                  unsigned short* __restrict__ Cl2,
                  int M, int N, int K)
{
    extern __shared__ __align__(128) char smem[];
    const int z = blockIdx.z;
    const unsigned short* Bh = Whi16 + wz * z;
    const unsigned short* Bl = Wlo16 + wz * z;
    const float* bias = (z == 0) ? bias0 : (z == 1) ? bias1 : bias2;
    float*          Cf = (z == 0) ? Cf0 : (z == 1) ? Cf1 : Cf2;
    unsigned short* Ch = (z == 0) ? Ch0 : (z == 1) ? Ch1 : Ch2;
    unsigned short* Cl = (z == 0) ? Cl0 : (z == 1) ? Cl1 : Cl2;

    const uint32_t sbase = smem_u32(smem);
    const int t    = threadIdx.x;
    const int wid  = t >> 5;
    const int lane = t & 31;
    const int m0   = blockIdx.y * 128;
    const int n0   = blockIdx.x * 128;
    const int wm   = (wid & 1) * 64;
    const int wn   = (wid >> 1) * 32;

    const int lrow = t >> 1;
    const int lu   = (t & 1) * 2;
    const unsigned short* pAh = Ahi16 + (size_t)(m0 + lrow) * K + lu * 8;
    const unsigned short* pAl = Alo16 + (size_t)(m0 + lrow) * K + lu * 8;
    const unsigned short* pBh = Bh    + (size_t)(n0 + lrow) * K + lu * 8;
    const unsigned short* pBl = Bl    + (size_t)(n0 + lrow) * K + lu * 8;
    const uint32_t sRow = (uint32_t)lrow * ROWB + lu * 16;

    #define LOAD_STAGE(cc, ss) do {                                        \
        const uint32_t sb_ = sbase + (ss) * STAGEB + sRow;                  \
        const size_t  ko_ = (size_t)(cc) * 32;                              \
        cpa16(sb_ + 0 * TILEB,      pAh + ko_);                             \
        cpa16(sb_ + 0 * TILEB + 16, pAh + ko_ + 8);                         \
        cpa16(sb_ + 1 * TILEB,      pAl + ko_);                             \
        cpa16(sb_ + 1 * TILEB + 16, pAl + ko_ + 8);                         \
        cpa16(sb_ + 2 * TILEB,      pBh + ko_);                             \
        cpa16(sb_ + 2 * TILEB + 16, pBh + ko_ + 8);                         \
        cpa16(sb_ + 3 * TILEB,      pBl + ko_);                             \
        cpa16(sb_ + 3 * TILEB + 16, pBl + ko_ + 8);                         \
    } while (0)

    const uint32_t laneA = (uint32_t)(lane & 15) * ROWB + (lane >> 4) * 16;
    const uint32_t laneB = (uint32_t)((lane & 7) + ((lane >> 4) << 3)) * ROWB
                         + ((lane >> 3) & 1) * 16;

    float acc[4][4][4];
    #pragma unroll
    for (int i = 0; i < 4; ++i)
        #pragma unroll
        for (int j = 0; j < 4; ++j)
            #pragma unroll
            for (int q = 0; q < 4; ++q) acc[i][j][q] = 0.0f;

    const int NC = K >> 5;
    LOAD_STAGE(0, 0); cp_commit();

    for (int c = 0; c < NC; ++c) {
        const int s = c & 1;
        cp_wait<0>();          // chunk c's data complete
        __syncthreads();       // all warps finished reading stage s^1 (iter c-1)
        if (c + 1 < NC) LOAD_STAGE(c + 1, s ^ 1);
        cp_commit();

        const uint32_t stg = sbase + s * STAGEB;
        #pragma unroll
        for (int ks = 0; ks < 2; ++ks) {
            const uint32_t kb = ks * 32;
            uint32_t bh[4][2], bl[4][2];
            #pragma unroll
            for (int p = 0; p < 2; ++p) {
                uint32_t rb[4], rl[4];
                const uint32_t ra = stg + (uint32_t)(wn + p * 16) * ROWB + laneB + kb;
                ldm_x4(rb, ra + 2 * TILEB);
                ldm_x4(rl, ra + 3 * TILEB);
                bh[p * 2 + 0][0] = rb[0]; bh[p * 2 + 0][1] = rb[1];
                bh[p * 2 + 1][0] = rb[2]; bh[p * 2 + 1][1] = rb[3];
                bl[p * 2 + 0][0] = rl[0]; bl[p * 2 + 0][1] = rl[1];
                bl[p * 2 + 1][0] = rl[2]; bl[p * 2 + 1][1] = rl[3];
            }
            #pragma unroll
            for (int mf = 0; mf < 4; ++mf) {
                uint32_t ah[4], al[4];
                const uint32_t ra = stg + (uint32_t)(wm + mf * 16) * ROWB + laneA + kb;
                ldm_x4(ah, ra + 0 * TILEB);
                ldm_x4(al, ra + 1 * TILEB);
                #pragma unroll
                for (int nf = 0; nf < 4; ++nf) {
                    mma16816(acc[mf][nf], ah, bh[nf]);
                    mma16816(acc[mf][nf], ah, bl[nf]);
                    mma16816(acc[mf][nf], al, bh[nf]);
                }
            }
        }
    }

    const int rbase = lane >> 2;
    const int cbase = (lane & 3) * 2;
    #pragma unroll
    for (int mf = 0; mf < 4; ++mf) {
        #pragma unroll
        for (int nf = 0; nf < 4; ++nf) {
            const int col = n0 + wn + nf * 8 + cbase;
            const float2 bb = *(const float2*)&bias[col];
            #pragma unroll
            for (int h = 0; h < 2; ++h) {
                const int row = m0 + wm + mf * 16 + rbase + h * 8;
                float2 rv;
                rv.x = acc[mf][nf][h * 2 + 0] + bb.x;
                rv.y = acc[mf][nf][h * 2 + 1] + bb.y;
                if (EPI == 1) { rv.x = gelu_f(rv.x); rv.y = gelu_f(rv.y); }
                if (EPI == 2) {
                    const float2 rr = *(const float2*)&R[(size_t)row * N + col];
                    rv.x += rr.x; rv.y += rr.y;
                }
                if (Cf) *(float2*)&Cf[(size_t)row * N + col] = rv;
                if (Ch) {
                    uint32_t hi, lo;
                    bfsplit2(rv.x, rv.y, hi, lo);
                    *(uint32_t*)&Ch[(size_t)row * N + col] = hi;
                    *(uint32_t*)&Cl[(size_t)row * N + col] = lo;
                }
            }
        }
    }
    #undef LOAD_STAGE
}

// ---------------------------------------------------------------------------
// fp32 -> bf16 hi/lo split kernels
// ---------------------------------------------------------------------------
__device__ __forceinline__ void split1(float v, unsigned short& h, unsigned short& l) {
    __nv_bfloat16 hb = __float2bfloat16(v);
    __nv_bfloat16 lb = __float2bfloat16(v - __bfloat162float(hb));
    h = *(unsigned short*)&hb;
    l = *(unsigned short*)&lb;
}

__global__ __launch_bounds__(256)
void split_kernel(const float* __restrict__ X, unsigned short* __restrict__ hi,
                  unsigned short* __restrict__ lo, int n4)
{
    int i = blockIdx.x * 256 + threadIdx.x;
    if (i >= n4) return;
    float4 v = ((const float4*)X)[i];
    ushort4 h, l;
    split1(v.x, h.x, l.x); split1(v.y, h.y, l.y);
    split1(v.z, h.z, l.z); split1(v.w, h.w, l.w);
    ((ushort4*)hi)[i] = h;
    ((ushort4*)lo)[i] = l;
}

// transpose+split; z-fused for up to 4 equal-shaped weights
__global__ __launch_bounds__(256)
void tsplit_kernel(const float* __restrict__ W0, const float* __restrict__ W1,
                   const float* __restrict__ W2, const float* __restrict__ W3,
                   unsigned short* __restrict__ Thi, unsigned short* __restrict__ Tlo,
                   size_t zstride, int K, int N)
{
    __shared__ float s[32][33];
    const int z = blockIdx.z;
    const float* W = (z == 0) ? W0 : (z == 1) ? W1 : (z == 2) ? W2 : W3;
    unsigned short* Th = Thi + zstride * z;
    unsigned short* Tl = Tlo + zstride * z;
    const int tx = threadIdx.x, ty = threadIdx.y;
    const int nb = blockIdx.x * 32, kb = blockIdx.y * 32;
    #pragma unroll
    for (int i = 0; i < 4; ++i)
        s[ty + i * 8][tx] = W[(size_t)(kb + ty + i * 8) * N + nb + tx];
    __syncthreads();
    #pragma unroll
    for (int i = 0; i < 4; ++i) {
        const float v = s[tx][ty + i * 8];
        unsigned short h, l;
        split1(v, h, l);
        const size_t o = (size_t)(nb + ty + i * 8) * K + kb + tx;
        Th[o] = h; Tl[o] = l;
    }
}

// ---------------------------------------------------------------------------
// Flash attention via mma.sync; V natural layout (ldmatrix.trans).
// R9 best config: 256 threads / 128 queries, 2-stage KV pipeline.
// Softmax in exp2 domain (scale folded: 0.125 * log2(e)).
// ---------------------------------------------------------------------------
#define AROWB   144
#define ATT_QLO 18432
#define ATT_KV  36864
#define ATT_STG 36864
#define ATT_MB  (ATT_KV + 2 * ATT_STG)
#define ATT_SMEM (ATT_MB + 512)
#define SCL2    0.18033688011112042591f   // 0.125 * log2(e)

__global__ __launch_bounds__(256, 1)
void attn_mma_kernel(const unsigned short* __restrict__ Qhi,
                     const unsigned short* __restrict__ Qlo,
                     const unsigned short* __restrict__ Khi,
                     const unsigned short* __restrict__ Klo,
                     const unsigned short* __restrict__ Vhi,
                     const unsigned short* __restrict__ Vlo,
                     const int* __restrict__ mask,
                     unsigned short* __restrict__ Yhi,
                     unsigned short* __restrict__ Ylo)
{
    extern __shared__ __align__(128) char smem[];
    const uint32_t sb = smem_u32(smem);
    const int t    = threadIdx.x;
    const int lane = t & 31;
    const int w    = t >> 5;
    const int q0   = blockIdx.x * 128;
    const int bh   = blockIdx.y;
    const int tokb = (bh >> 4) * 2048;
    const int colb = (bh & 15) * 64;

    const uint32_t laneA = (uint32_t)(lane & 15) * AROWB + (lane >> 4) * 16;
    const uint32_t laneB = (uint32_t)((lane & 7) + ((lane >> 4) << 3)) * AROWB
                         + ((lane >> 3) & 1) * 16;
    const uint32_t laneBT = (uint32_t)((lane & 7) + ((lane >> 3) & 1) * 8) * AROWB
                          + (lane >> 4) * 16;

    {
        const int row = t >> 1;
        const size_t g = (size_t)(tokb + q0 + row) * 1024 + colb;
        const uint32_t sr = (uint32_t)row * AROWB;
        #pragma unroll
        for (int i = 0; i < 4; ++i) {
            const int ch = (t & 1) * 4 + i;
            cpa16(sb + sr + ch * 16,           Qhi + g + ch * 8);
            cpa16(sb + ATT_QLO + sr + ch * 16, Qlo + g + ch * 8);
        }
    }

    auto LOADKV = [&](int tile, int s) {
        const int kv0 = tile * 64;
        const int row = t >> 2;
        const int q2  = t & 3;
        const uint32_t st = sb + ATT_KV + s * ATT_STG;
        const size_t gk = (size_t)(tokb + kv0 + row) * 1024 + colb;
        const uint32_t sr = (uint32_t)row * AROWB;
        #pragma unroll
        for (int i = 0; i < 2; ++i) {
            const int ch = q2 * 2 + i;
            cpa16(st +         sr + ch * 16, Khi + gk + ch * 8);
            cpa16(st +  9216 + sr + ch * 16, Klo + gk + ch * 8);
            cpa16(st + 18432 + sr + ch * 16, Vhi + gk + ch * 8);
            cpa16(st + 27648 + sr + ch * 16, Vlo + gk + ch * 8);
        }
        if (t < 64) {
            float* mb = (float*)(smem + ATT_MB) + s * 64;
            mb[t] = (mask[tokb + kv0 + t] == 0) ? -1e30f : 0.0f;
        }
    };

    LOADKV(0, 0); cp_commit();
    LOADKV(1, 1); cp_commit();

    cp_wait<1>();
    __syncthreads();

    uint32_t qh[4][4], ql[4][4];
    #pragma unroll
    for (int fk = 0; fk < 4; ++fk) {
        const uint32_t ra = sb + (uint32_t)(w * 16) * AROWB + laneA + fk * 32;
        ldm_x4(qh[fk], ra);
        ldm_x4(ql[fk], ra + ATT_QLO);
    }

    float of[8][4];
    #pragma unroll
    for (int i = 0; i < 8; ++i)
        #pragma unroll
        for (int j = 0; j < 4; ++j) of[i][j] = 0.0f;
    float mA = -1e30f, mB = -1e30f, lA = 0.0f, lB = 0.0f;
    const int c0 = (lane & 3) * 2;

    for (int tile = 0; tile < 32; ++tile) {
        const int s = tile & 1;
        if (tile > 0) { cp_wait<1>(); __syncthreads(); }
        const uint32_t kst = sb + ATT_KV + s * ATT_STG;
        const float* mb = (const float*)(smem + ATT_MB) + s * 64;

        float sf[8][4];
        #pragma unroll
        for (int i = 0; i < 8; ++i)
            #pragma unroll
            for (int j = 0; j < 4; ++j) sf[i][j] = 0.0f;

        #pragma unroll
        for (int fk = 0; fk < 4; ++fk) {
            uint32_t kh[8][2], kl[8][2];
            #pragma unroll
            for (int p = 0; p < 4; ++p) {
                uint32_t r0[4], r1[4];
                const uint32_t ra = kst + (uint32_t)(p * 16) * AROWB + laneB + fk * 32;
                ldm_x4(r0, ra);
                ldm_x4(r1, ra + 9216);
                kh[p * 2 + 0][0] = r0[0]; kh[p * 2 + 0][1] = r0[1];
                kh[p * 2 + 1][0] = r0[2]; kh[p * 2 + 1][1] = r0[3];
                kl[p * 2 + 0][0] = r1[0]; kl[p * 2 + 0][1] = r1[1];
                kl[p * 2 + 1][0] = r1[2]; kl[p * 2 + 1][1] = r1[3];
            }
            #pragma unroll
            for (int nf = 0; nf < 8; ++nf) {
                mma16816(sf[nf], qh[fk], kh[nf]);
                mma16816(sf[nf], qh[fk], kl[nf]);
                mma16816(sf[nf], ql[fk], kh[nf]);
            }
        }

        // online softmax in exp2 domain
        float pmA = -1e30f, pmB = -1e30f;
        #pragma unroll
        for (int nf = 0; nf < 8; ++nf) {
            const float m0 = mb[nf * 8 + c0];
            const float m1 = mb[nf * 8 + c0 + 1];
            sf[nf][0] = fmaf(sf[nf][0], SCL2, m0);
            sf[nf][1] = fmaf(sf[nf][1], SCL2, m1);
            sf[nf][2] = fmaf(sf[nf][2], SCL2, m0);
            sf[nf][3] = fmaf(sf[nf][3], SCL2, m1);
            pmA = fmaxf(pmA, fmaxf(sf[nf][0], sf[nf][1]));
            pmB = fmaxf(pmB, fmaxf(sf[nf][2], sf[nf][3]));
        }
        pmA = fmaxf(pmA, __shfl_xor_sync(0xffffffffu, pmA, 1));
        pmA = fmaxf(pmA, __shfl_xor_sync(0xffffffffu, pmA, 2));
        pmB = fmaxf(pmB, __shfl_xor_sync(0xffffffffu, pmB, 1));
        pmB = fmaxf(pmB, __shfl_xor_sync(0xffffffffu, pmB, 2));
        const float mnA = fmaxf(mA, pmA), mnB = fmaxf(mB, pmB);
        const float alA = ex2(mA - mnA), alB = ex2(mB - mnB);
        mA = mnA; mB = mnB;
        float rsA = 0.0f, rsB = 0.0f;
        #pragma unroll
        for (int nf = 0; nf < 8; ++nf) {
            sf[nf][0] = ex2(sf[nf][0] - mnA);
            sf[nf][1] = ex2(sf[nf][1] - mnA);
            sf[nf][2] = ex2(sf[nf][2] - mnB);
            sf[nf][3] = ex2(sf[nf][3] - mnB);
            rsA += sf[nf][0] + sf[nf][1];
            rsB += sf[nf][2] + sf[nf][3];
        }
        rsA += __shfl_xor_sync(0xffffffffu, rsA, 1);
        rsA += __shfl_xor_sync(0xffffffffu, rsA, 2);
        rsB += __shfl_xor_sync(0xffffffffu, rsB, 1);
        rsB += __shfl_xor_sync(0xffffffffu, rsB, 2);
        lA = lA * alA + rsA;
        lB = lB * alB + rsB;
        #pragma unroll
        for (int nf = 0; nf < 8; ++nf) {
            of[nf][0] *= alA; of[nf][1] *= alA;
            of[nf][2] *= alB; of[nf][3] *= alB;
        }

        #pragma unroll
        for (int fk = 0; fk < 4; ++fk) {
            uint32_t aHi[4], aLo[4];
            bfsplit2(sf[2 * fk][0],     sf[2 * fk][1],     aHi[0], aLo[0]);
            bfsplit2(sf[2 * fk][2],     sf[2 * fk][3],     aHi[1], aLo[1]);
            bfsplit2(sf[2 * fk + 1][0], sf[2 * fk + 1][1], aHi[2], aLo[2]);
            bfsplit2(sf[2 * fk + 1][2], sf[2 * fk + 1][3], aHi[3], aLo[3]);
            uint32_t vh[8][2], vl[8][2];
            #pragma unroll
            for (int p = 0; p < 4; ++p) {
                uint32_t r0[4], r1[4];
                const uint32_t ra = kst + 18432 + (uint32_t)(fk * 16) * AROWB
                                  + laneBT + p * 32;
                ldm_x4_t(r0, ra);
                ldm_x4_t(r1, ra + 9216);
                vh[p * 2 + 0][0] = r0[0]; vh[p * 2 + 0][1] = r0[1];
                vh[p * 2 + 1][0] = r0[2]; vh[p * 2 + 1][1] = r0[3];
                vl[p * 2 + 0][0] = r1[0]; vl[p * 2 + 0][1] = r1[1];
                vl[p * 2 + 1][0] = r1[2]; vl[p * 2 + 1][1] = r1[3];
            }
            #pragma unroll
            for (int nf = 0; nf < 8; ++nf) {
                mma16816(of[nf], aHi, vh[nf]);
                mma16816(of[nf], aHi, vl[nf]);
                mma16816(of[nf], aLo, vh[nf]);
            }
        }

        __syncthreads();
        if (tile + 2 < 32) LOADKV(tile + 2, s);
        cp_commit();
    }

    const float iA = 1.0f / lA, iB = 1.0f / lB;
    const int rA = lane >> 2;
    const int rowA = tokb + q0 + w * 16 + rA;
    #pragma unroll
    for (int nf = 0; nf < 8; ++nf) {
        const int col = colb + nf * 8 + c0;
        uint32_t h0, l0, h1, l1;
        bfsplit2(of[nf][0] * iA, of[nf][1] * iA, h0, l0);
        bfsplit2(of[nf][2] * iB, of[nf][3] * iB, h1, l1);
        *(uint32_t*)&Yhi[(size_t)rowA * 1024 + col]       = h0;
        *(uint32_t*)&Ylo[(size_t)rowA * 1024 + col]       = l0;
        *(uint32_t*)&Yhi[(size_t)(rowA + 8) * 1024 + col] = h1;
        *(uint32_t*)&Ylo[(size_t)(rowA + 8) * 1024 + col] = l1;
    }
}

// ---------------------------------------------------------------------------
// LayerNorm: one row per CTA; optional fused bf16 hi/lo split output
// ---------------------------------------------------------------------------
__global__ __launch_bounds__(256)
void ln_kernel(const float* __restrict__ X, const float* __restrict__ w,
               const float* __restrict__ b, float* __restrict__ out,
               unsigned short* __restrict__ hi, unsigned short* __restrict__ lo)
{
    __shared__ float red[2][8];
    const int t = threadIdx.x;
    const size_t row = blockIdx.x;
    float4 xv = *(const float4*)&X[row * 1024 + t * 4];
    float s  = xv.x + xv.y + xv.z + xv.w;
    float s2 = xv.x * xv.x + xv.y * xv.y + xv.z * xv.z + xv.w * xv.w;
    #pragma unroll
    for (int off = 16; off; off >>= 1) {
        s  += __shfl_xor_sync(0xffffffffu, s,  off);
        s2 += __shfl_xor_sync(0xffffffffu, s2, off);
    }
    if ((t & 31) == 0) { red[0][t >> 5] = s; red[1][t >> 5] = s2; }
    __syncthreads();
    float S = 0.0f, S2 = 0.0f;
    #pragma unroll
    for (int i = 0; i < 8; ++i) { S += red[0][i]; S2 += red[1][i]; }
    const float mean = S * (1.0f / 1024.0f);
    const float var  = S2 * (1.0f / 1024.0f) - mean * mean;
    const float rstd = rsqrtf(var + 1e-5f);
    float4 wv = *(const float4*)&w[t * 4];
    float4 bv = *(const float4*)&b[t * 4];
    float4 r;
    r.x = (xv.x - mean) * rstd * wv.x + bv.x;
    r.y = (xv.y - mean) * rstd * wv.y + bv.y;
    r.z = (xv.z - mean) * rstd * wv.z + bv.z;
    r.w = (xv.w - mean) * rstd * wv.w + bv.w;
    if (out) *(float4*)&out[row * 1024 + t * 4] = r;
    if (hi) {
        uint32_t h0, l0, h1, l1;
        bfsplit2(r.x, r.y, h0, l0);
        bfsplit2(r.z, r.w, h1, l1);
        uint2 hv = make_uint2(h0, h1), lv = make_uint2(l0, l1);
        *(uint2*)&hi[row * 1024 + t * 4] = hv;
        *(uint2*)&lo[row * 1024 + t * 4] = lv;
    }
}

// ---------------------------------------------------------------------------
// launch
// ---------------------------------------------------------------------------
extern "C" void kernel_launch(void* const* d_in, const int* in_sizes, int n_in,
                              void* d_out, int out_size)
{
    (void)in_sizes; (void)n_in; (void)out_size;
    const float* x    = (const float*)d_in[0];
    const int*   mask = (const int*)  d_in[1];
    const float* WQ   = (const float*)d_in[2];
    const float* bQ   = (const float*)d_in[3];
    const float* WK   = (const float*)d_in[4];
    const float* bK   = (const float*)d_in[5];
    const float* WV   = (const float*)d_in[6];
    const float* bV   = (const float*)d_in[7];
    const float* WY   = (const float*)d_in[8];
    const float* bY   = (const float*)d_in[9];
    const float* ln1w = (const float*)d_in[10];
    const float* ln1b = (const float*)d_in[11];
    const float* ln2w = (const float*)d_in[12];
    const float* ln2b = (const float*)d_in[13];
    const float* W1   = (const float*)d_in[14];
    const float* b1   = (const float*)d_in[15];
    const float* W2   = (const float*)d_in[16];
    const float* b2   = (const float*)d_in[17];
    float* out = (float*)d_out;

    float *Qp, *Kp, *Vp, *Yp;
    unsigned short *Ahi, *Alo, *Whi, *Wlo;
    unsigned short *Qhi, *Qlo, *Khi, *Klo, *Vhi, *Vlo;
    cudaGetSymbolAddress((void**)&Qp,  g_Q);
    cudaGetSymbolAddress((void**)&Kp,  g_K);
    cudaGetSymbolAddress((void**)&Vp,  g_V);
    cudaGetSymbolAddress((void**)&Yp,  g_Y);
    cudaGetSymbolAddress((void**)&Ahi, g_Ahi);
    cudaGetSymbolAddress((void**)&Alo, g_Alo);
    cudaGetSymbolAddress((void**)&Whi, g_Whi);
    cudaGetSymbolAddress((void**)&Wlo, g_Wlo);
    cudaGetSymbolAddress((void**)&Qhi, g_Qhi);
    cudaGetSymbolAddress((void**)&Qlo, g_Qlo);
    cudaGetSymbolAddress((void**)&Khi, g_Khi);
    cudaGetSymbolAddress((void**)&Klo, g_Klo);
    cudaGetSymbolAddress((void**)&Vhi, g_Vhi);
    cudaGetSymbolAddress((void**)&Vlo, g_Vlo);

    unsigned short* Yhi = (unsigned short*)Yp;
    unsigned short* Ylo = (unsigned short*)Yp + (size_t)4096 * 1024;

    const size_t MB = (size_t)1024 * 1024;

    cudaFuncSetAttribute(tgemm_kernel<0>,
                         cudaFuncAttributeMaxDynamicSharedMemorySize, TG_SMEM);
    cudaFuncSetAttribute(tgemm_kernel<1>,
                         cudaFuncAttributeMaxDynamicSharedMemorySize, TG_SMEM);
    cudaFuncSetAttribute(tgemm_kernel<2>,
                         cudaFuncAttributeMaxDynamicSharedMemorySize, TG_SMEM);
    cudaFuncSetAttribute(attn_mma_kernel,
                         cudaFuncAttributeMaxDynamicSharedMemorySize, ATT_SMEM);

    dim3 blk(256);
    dim3 tsb(32, 8);

    // weight transposes
    tsplit_kernel<<<dim3(32, 32, 4), tsb>>>(WQ, WK, WV, WY, Whi, Wlo, MB, 1024, 1024);
    tsplit_kernel<<<dim3(128, 32, 1), tsb>>>(W1, W1, W1, W1, Whi + 4 * MB, Wlo + 4 * MB,
                                             0, 1024, 4096);
    tsplit_kernel<<<dim3(32, 128, 1), tsb>>>(W2, W2, W2, W2, Whi + 8 * MB, Wlo + 8 * MB,
                                             0, 4096, 1024);

    // x split
    split_kernel<<<4096, blk>>>(x, Ahi, Alo, (4096 * 1024) / 4);

    // QKV: all three outputs as bf16 splits (V natural layout)
    tgemm_kernel<0><<<dim3(8, 32, 3), blk, TG_SMEM>>>(
        Ahi, Alo, Whi, Wlo, MB, bQ, bK, bV, nullptr,
        nullptr, nullptr, nullptr,
        Qhi, Khi, Vhi,
        Qlo, Klo, Vlo,
        4096, 1024, 1024);

    // attention -> Yhi/Ylo bf16 (128 queries per CTA, R9 config)
    attn_mma_kernel<<<dim3(16, 32), blk, ATT_SMEM>>>(
        Qhi, Qlo, Khi, Klo, Vhi, Vlo, mask, Yhi, Ylo);

    // out-proj + residual x -> fp32 g_Q
    tgemm_kernel<2><<<dim3(8, 32, 1), blk, TG_SMEM>>>(
        Yhi, Ylo, Whi + 3 * MB, Wlo + 3 * MB, 0, bY, bY, bY, x,
        Qp, nullptr, nullptr,
        nullptr, nullptr, nullptr,
        nullptr, nullptr, nullptr,
        4096, 1024, 1024);

    // h = LN1 -> fp32 g_K + bf16 split (Qhi/Qlo reused)
    ln_kernel<<<4096, blk>>>(Qp, ln1w, ln1b, Kp, Qhi, Qlo);

    // FFN1: gelu(h@W1+b1) -> bf16 split only
    tgemm_kernel<1><<<dim3(32, 32, 1), blk, TG_SMEM>>>(
        Qhi, Qlo, Whi + 4 * MB, Wlo + 4 * MB, 0, b1, b1, b1, nullptr,
        nullptr, nullptr, nullptr,
        Ahi, nullptr, nullptr,
        Alo, nullptr, nullptr,
        4096, 4096, 1024);

    // FFN2: ff@W2+b2+h -> fp32 g_V
    tgemm_kernel<2><<<dim3(8, 32, 1), blk, TG_SMEM>>>(
        Ahi, Alo, Whi + 8 * MB, Wlo + 8 * MB, 0, b2, b2, b2, Kp,
        Vp, nullptr, nullptr,
        nullptr, nullptr, nullptr,
        nullptr, nullptr, nullptr,
        4096, 1024, 4096);

    // out = LN2
    ln_kernel<<<4096, blk>>>(Vp, ln2w, ln2b, out, nullptr, nullptr);
}

// round 14
// speedup vs baseline: 1.0521x; 1.0030x over previous
#include <cuda_runtime.h>
#include <cuda_bf16.h>
#include <math.h>
#include <stdint.h>

// ---------------------------------------------------------------------------
// Scratch (__device__ globals; no allocations allowed)
// ---------------------------------------------------------------------------
__device__ float g_Q [(size_t)4096 * 1024];   // out-proj result (a+x)
__device__ float g_K [(size_t)4096 * 1024];   // h = LN1(...)
__device__ float g_V [(size_t)4096 * 1024];   // ffn2 result fp32
__device__ float g_Y [(size_t)4096 * 1024];   // Yhi/Ylo bf16 halves
__device__ unsigned short g_Ahi[(size_t)4096 * 4096];
__device__ unsigned short g_Alo[(size_t)4096 * 4096];
__device__ unsigned short g_Whi[(size_t)12 * 1024 * 1024];
__device__ unsigned short g_Wlo[(size_t)12 * 1024 * 1024];
__device__ unsigned short g_Qhi [(size_t)4096 * 1024];
__device__ unsigned short g_Qlo [(size_t)4096 * 1024];
__device__ unsigned short g_Khi [(size_t)4096 * 1024];
__device__ unsigned short g_Klo [(size_t)4096 * 1024];
__device__ unsigned short g_Vhi [(size_t)4096 * 1024];  // V natural layout
__device__ unsigned short g_Vlo [(size_t)4096 * 1024];

__device__ __forceinline__ uint32_t smem_u32(const void* p) {
    uint32_t a;
    asm("{ .reg .u64 t; cvta.to.shared.u64 t, %1; cvt.u32.u64 %0, t; }"
        : "=r"(a) : "l"(p));
    return a;
}
__device__ __forceinline__ void cpa16(uint32_t s, const void* g) {
    asm volatile("cp.async.cg.shared.global [%0], [%1], 16;"
                 :: "r"(s), "l"(__cvta_generic_to_global(g)) : "memory");
}
__device__ __forceinline__ void cp_commit() {
    asm volatile("cp.async.commit_group;" ::: "memory");
}
template<int N>
__device__ __forceinline__ void cp_wait() {
    asm volatile("cp.async.wait_group %0;" :: "n"(N) : "memory");
}
__device__ __forceinline__ void ldm_x4(uint32_t* r, uint32_t saddr) {
    asm volatile("ldmatrix.sync.aligned.m8n8.x4.shared.b16 {%0,%1,%2,%3}, [%4];"
                 : "=r"(r[0]), "=r"(r[1]), "=r"(r[2]), "=r"(r[3]) : "r"(saddr));
}
__device__ __forceinline__ void ldm_x4_t(uint32_t* r, uint32_t saddr) {
    asm volatile("ldmatrix.sync.aligned.m8n8.x4.trans.shared.b16 {%0,%1,%2,%3}, [%4];"
                 : "=r"(r[0]), "=r"(r[1]), "=r"(r[2]), "=r"(r[3]) : "r"(saddr));
}
__device__ __forceinline__ void mma16816(float* c, const uint32_t* a, const uint32_t* b) {
    asm volatile("mma.sync.aligned.m16n8k16.row.col.f32.bf16.bf16.f32 "
                 "{%0,%1,%2,%3}, {%4,%5,%6,%7}, {%8,%9}, {%0,%1,%2,%3};"
                 : "+f"(c[0]), "+f"(c[1]), "+f"(c[2]), "+f"(c[3])
                 : "r"(a[0]), "r"(a[1]), "r"(a[2]), "r"(a[3]),
                   "r"(b[0]), "r"(b[1]));
}
__device__ __forceinline__ float ex2(float x) {
    float r;
    asm("ex2.approx.f32 %0, %1;" : "=f"(r) : "f"(x));
    return r;
}
__device__ __forceinline__ float gelu_f(float v) {
    return 0.5f * v * (1.0f + erff(v * 0.70710678118654752f));
}
__device__ __forceinline__ void bfsplit2(float x, float y, uint32_t& hi, uint32_t& lo) {
    __nv_bfloat16 hx = __float2bfloat16(x), hy = __float2bfloat16(y);
    hi = ((uint32_t)(*(unsigned short*)&hy) << 16) | (uint32_t)(*(unsigned short*)&hx);
    __nv_bfloat16 lx = __float2bfloat16(x - __bfloat162float(hx));
    __nv_bfloat16 ly = __float2bfloat16(y - __bfloat162float(hy));
    lo = ((uint32_t)(*(unsigned short*)&ly) << 16) | (uint32_t)(*(unsigned short*)&lx);
}

// ---------------------------------------------------------------------------
// Tensor-core dense GEMM (R13 best config — unchanged).
// k-chunk 32, 2-stage, ROWB 80, 2 CTAs/SM, single __syncthreads per chunk.
// ---------------------------------------------------------------------------
#define ROWB   80
#define TILEB  (128 * ROWB)
#define STAGEB (4 * TILEB)
#define NSTAGE 2
#define TG_SMEM (NSTAGE * STAGEB)    // 81920 -> 2 CTAs/SM

template<int EPI>
__global__ __launch_bounds__(256, 2)
void tgemm_kernel(const unsigned short* __restrict__ Ahi16,
                  const unsigned short* __restrict__ Alo16,
                  const unsigned short* __restrict__ Whi16,
                  const unsigned short* __restrict__ Wlo16,
                  size_t wz,
                  const float* __restrict__ bias0, const float* __restrict__ bias1,
                  const float* __restrict__ bias2,
                  const float* __restrict__ R,
                  float* __restrict__ Cf0, float* __restrict__ Cf1, float* __restrict__ Cf2,
                  unsigned short* __restrict__ Ch0, unsigned short* __restrict__ Ch1,
                  unsigned short* __restrict__ Ch2,
                  unsigned short* __restrict__ Cl0, unsigned short* __restrict__ Cl1,
                  unsigned short* __restrict__ Cl2,
                  int M, int N, int K)
{
    extern __shared__ __align__(128) char smem[];
    const int z = blockIdx.z;
    const unsigned short* Bh = Whi16 + wz * z;
    const unsigned short* Bl = Wlo16 + wz * z;
    const float* bias = (z == 0) ? bias0 : (z == 1) ? bias1 : bias2;
    float*          Cf = (z == 0) ? Cf0 : (z == 1) ? Cf1 : Cf2;
    unsigned short* Ch = (z == 0) ? Ch0 : (z == 1) ? Ch1 : Ch2;
    unsigned short* Cl = (z == 0) ? Cl0 : (z == 1) ? Cl1 : Cl2;

    const uint32_t sbase = smem_u32(smem);
    const int t    = threadIdx.x;
    const int wid  = t >> 5;
    const int lane = t & 31;
    const int m0   = blockIdx.y * 128;
    const int n0   = blockIdx.x * 128;
    const int wm   = (wid & 1) * 64;
    const int wn   = (wid >> 1) * 32;

    const int lrow = t >> 1;
    const int lu   = (t & 1) * 2;
    const unsigned short* pAh = Ahi16 + (size_t)(m0 + lrow) * K + lu * 8;
    const unsigned short* pAl = Alo16 + (size_t)(m0 + lrow) * K + lu * 8;
    const unsigned short* pBh = Bh    + (size_t)(n0 + lrow) * K + lu * 8;
    const unsigned short* pBl = Bl    + (size_t)(n0 + lrow) * K + lu * 8;
    const uint32_t sRow = (uint32_t)lrow * ROWB + lu * 16;

    #define LOAD_STAGE(cc, ss) do {                                        \
        const uint32_t sb_ = sbase + (ss) * STAGEB + sRow;                  \
        const size_t  ko_ = (size_t)(cc) * 32;                              \
        cpa16(sb_ + 0 * TILEB,      pAh + ko_);                             \
        cpa16(sb_ + 0 * TILEB + 16, pAh + ko_ + 8);                         \
        cpa16(sb_ + 1 * TILEB,      pAl + ko_);                             \
        cpa16(sb_ + 1 * TILEB + 16, pAl + ko_ + 8);                         \
        cpa16(sb_ + 2 * TILEB,      pBh + ko_);                             \
        cpa16(sb_ + 2 * TILEB + 16, pBh + ko_ + 8);                         \
        cpa16(sb_ + 3 * TILEB,      pBl + ko_);                             \
        cpa16(sb_ + 3 * TILEB + 16, pBl + ko_ + 8);                         \
    } while (0)

    const uint32_t laneA = (uint32_t)(lane & 15) * ROWB + (lane >> 4) * 16;
    const uint32_t laneB = (uint32_t)((lane & 7) + ((lane >> 4) << 3)) * ROWB
                         + ((lane >> 3) & 1) * 16;

    float acc[4][4][4];
    #pragma unroll
    for (int i = 0; i < 4; ++i)
        #pragma unroll
        for (int j = 0; j < 4; ++j)
            #pragma unroll
            for (int q = 0; q < 4; ++q) acc[i][j][q] = 0.0f;

    const int NC = K >> 5;
    LOAD_STAGE(0, 0); cp_commit();

    for (int c = 0; c < NC; ++c) {
        const int s = c & 1;
        cp_wait<0>();
        __syncthreads();
        if (c + 1 < NC) LOAD_STAGE(c + 1, s ^ 1);
        cp_commit();

        const uint32_t stg = sbase + s * STAGEB;
        #pragma unroll
        for (int ks = 0; ks < 2; ++ks) {
            const uint32_t kb = ks * 32;
            uint32_t bh[4][2], bl[4][2];
            #pragma unroll
            for (int p = 0; p < 2; ++p) {
                uint32_t rb[4], rl[4];
                const uint32_t ra = stg + (uint32_t)(wn + p * 16) * ROWB + laneB + kb;
                ldm_x4(rb, ra + 2 * TILEB);
                ldm_x4(rl, ra + 3 * TILEB);
                bh[p * 2 + 0][0] = rb[0]; bh[p * 2 + 0][1] = rb[1];
                bh[p * 2 + 1][0] = rb[2]; bh[p * 2 + 1][1] = rb[3];
                bl[p * 2 + 0][0] = rl[0]; bl[p * 2 + 0][1] = rl[1];
                bl[p * 2 + 1][0] = rl[2]; bl[p * 2 + 1][1] = rl[3];
            }
            #pragma unroll
            for (int mf = 0; mf < 4; ++mf) {
                uint32_t ah[4], al[4];
                const uint32_t ra = stg + (uint32_t)(wm + mf * 16) * ROWB + laneA + kb;
                ldm_x4(ah, ra + 0 * TILEB);
                ldm_x4(al, ra + 1 * TILEB);
                #pragma unroll
                for (int nf = 0; nf < 4; ++nf) {
                    mma16816(acc[mf][nf], ah, bh[nf]);
                    mma16816(acc[mf][nf], ah, bl[nf]);
                    mma16816(acc[mf][nf], al, bh[nf]);
                }
            }
        }
    }

    const int rbase = lane >> 2;
    const int cbase = (lane & 3) * 2;
    #pragma unroll
    for (int mf = 0; mf < 4; ++mf) {
        #pragma unroll
        for (int nf = 0; nf < 4; ++nf) {
            const int col = n0 + wn + nf * 8 + cbase;
            const float2 bb = *(const float2*)&bias[col];
            #pragma unroll
            for (int h = 0; h < 2; ++h) {
                const int row = m0 + wm + mf * 16 + rbase + h * 8;
                float2 rv;
                rv.x = acc[mf][nf][h * 2 + 0] + bb.x;
                rv.y = acc[mf][nf][h * 2 + 1] + bb.y;
                if (EPI == 1) { rv.x = gelu_f(rv.x); rv.y = gelu_f(rv.y); }
                if (EPI == 2) {
                    const float2 rr = *(const float2*)&R[(size_t)row * N + col];
                    rv.x += rr.x; rv.y += rr.y;
                }
                if (Cf) *(float2*)&Cf[(size_t)row * N + col] = rv;
                if (Ch) {
                    uint32_t hi, lo;
                    bfsplit2(rv.x, rv.y, hi, lo);
                    *(uint32_t*)&Ch[(size_t)row * N + col] = hi;
                    *(uint32_t*)&Cl[(size_t)row * N + col] = lo;
                }
            }
        }
    }
    #undef LOAD_STAGE
}

// ---------------------------------------------------------------------------
// fp32 -> bf16 hi/lo split kernels
// ---------------------------------------------------------------------------
__device__ __forceinline__ void split1(float v, unsigned short& h, unsigned short& l) {
    __nv_bfloat16 hb = __float2bfloat16(v);
    __nv_bfloat16 lb = __float2bfloat16(v - __bfloat162float(hb));
    h = *(unsigned short*)&hb;
    l = *(unsigned short*)&lb;
}

__global__ __launch_bounds__(256)
void split_kernel(const float* __restrict__ X, unsigned short* __restrict__ hi,
                  unsigned short* __restrict__ lo, int n4)
{
    int i = blockIdx.x * 256 + threadIdx.x;
    if (i >= n4) return;
    float4 v = ((const float4*)X)[i];
    ushort4 h, l;
    split1(v.x, h.x, l.x); split1(v.y, h.y, l.y);
    split1(v.z, h.z, l.z); split1(v.w, h.w, l.w);
    ((ushort4*)hi)[i] = h;
    ((ushort4*)lo)[i] = l;
}

// transpose+split; z-fused for up to 4 equal-shaped weights
__global__ __launch_bounds__(256)
void tsplit_kernel(const float* __restrict__ W0, const float* __restrict__ W1,
                   const float* __restrict__ W2, const float* __restrict__ W3,
                   unsigned short* __restrict__ Thi, unsigned short* __restrict__ Tlo,
                   size_t zstride, int K, int N)
{
    __shared__ float s[32][33];
    const int z = blockIdx.z;
    const float* W = (z == 0) ? W0 : (z == 1) ? W1 : (z == 2) ? W2 : W3;
    unsigned short* Th = Thi + zstride * z;
    unsigned short* Tl = Tlo + zstride * z;
    const int tx = threadIdx.x, ty = threadIdx.y;
    const int nb = blockIdx.x * 32, kb = blockIdx.y * 32;
    #pragma unroll
    for (int i = 0; i < 4; ++i)
        s[ty + i * 8][tx] = W[(size_t)(kb + ty + i * 8) * N + nb + tx];
    __syncthreads();
    #pragma unroll
    for (int i = 0; i < 4; ++i) {
        const float v = s[tx][ty + i * 8];
        unsigned short h, l;
        split1(v, h, l);
        const size_t o = (size_t)(nb + ty + i * 8) * K + kb + tx;
        Th[o] = h; Tl[o] = l;
    }
}

// ---------------------------------------------------------------------------
// Flash attention via mma.sync; V natural layout (ldmatrix.trans).
// 256 threads / 128 queries, 3-stage KV pipeline, SINGLE sync per tile
// (same restructure as the dense GEMM: loads issued right after the barrier
// into the stage whose readers finished before it).
// ---------------------------------------------------------------------------
#define AROWB   144
#define ATT_QLO 18432
#define ATT_KV  36864
#define ATT_STG 36864
#define ATT_NST 3
#define ATT_MB  (ATT_KV + ATT_NST * ATT_STG)   // 147456
#define ATT_SMEM (ATT_MB + 1024)
#define SCL2    0.18033688011112042591f   // 0.125 * log2(e)

__global__ __launch_bounds__(256, 1)
void attn_mma_kernel(const unsigned short* __restrict__ Qhi,
                     const unsigned short* __restrict__ Qlo,
                     const unsigned short* __restrict__ Khi,
                     const unsigned short* __restrict__ Klo,
                     const unsigned short* __restrict__ Vhi,
                     const unsigned short* __restrict__ Vlo,
                     const int* __restrict__ mask,
                     unsigned short* __restrict__ Yhi,
                     unsigned short* __restrict__ Ylo)
{
    extern __shared__ __align__(128) char smem[];
    const uint32_t sb = smem_u32(smem);
    const int t    = threadIdx.x;
    const int lane = t & 31;
    const int w    = t >> 5;
    const int q0   = blockIdx.x * 128;
    const int bh   = blockIdx.y;
    const int tokb = (bh >> 4) * 2048;
    const int colb = (bh & 15) * 64;

    const uint32_t laneA = (uint32_t)(lane & 15) * AROWB + (lane >> 4) * 16;
    const uint32_t laneB = (uint32_t)((lane & 7) + ((lane >> 4) << 3)) * AROWB
                         + ((lane >> 3) & 1) * 16;
    const uint32_t laneBT = (uint32_t)((lane & 7) + ((lane >> 3) & 1) * 8) * AROWB
                          + (lane >> 4) * 16;

    {
        const int row = t >> 1;
        const size_t g = (size_t)(tokb + q0 + row) * 1024 + colb;
        const uint32_t sr = (uint32_t)row * AROWB;
        #pragma unroll
        for (int i = 0; i < 4; ++i) {
            const int ch = (t & 1) * 4 + i;
            cpa16(sb + sr + ch * 16,           Qhi + g + ch * 8);
            cpa16(sb + ATT_QLO + sr + ch * 16, Qlo + g + ch * 8);
        }
    }

    auto LOADKV = [&](int tile, int s) {
        const int kv0 = tile * 64;
        const int row = t >> 2;
        const int q2  = t & 3;
        const uint32_t st = sb + ATT_KV + s * ATT_STG;
        const size_t gk = (size_t)(tokb + kv0 + row) * 1024 + colb;
        const uint32_t sr = (uint32_t)row * AROWB;
        #pragma unroll
        for (int i = 0; i < 2; ++i) {
            const int ch = q2 * 2 + i;
            cpa16(st +         sr + ch * 16, Khi + gk + ch * 8);
            cpa16(st +  9216 + sr + ch * 16, Klo + gk + ch * 8);
            cpa16(st + 18432 + sr + ch * 16, Vhi + gk + ch * 8);
            cpa16(st + 27648 + sr + ch * 16, Vlo + gk + ch * 8);
        }
        if (t < 64) {
            float* mb = (float*)(smem + ATT_MB) + s * 64;
            mb[t] = (mask[tokb + kv0 + t] == 0) ? -1e30f : 0.0f;
        }
    };

    // prologue: Q + tile0 in group 0, tile1 in group 1
    LOADKV(0, 0); cp_commit();
    LOADKV(1, 1); cp_commit();

    // Q fragments loaded after the first wait inside the loop (tile 0 iter)
    uint32_t qh[4][4], ql[4][4];

    float of[8][4];
    #pragma unroll
    for (int i = 0; i < 8; ++i)
        #pragma unroll
        for (int j = 0; j < 4; ++j) of[i][j] = 0.0f;
    float mA = -1e30f, mB = -1e30f, lA = 0.0f, lB = 0.0f;
    const int c0 = (lane & 3) * 2;

    for (int tile = 0; tile < 32; ++tile) {
        const int s = tile % ATT_NST;
        cp_wait<1>();          // tile's group complete (tile+1 still pending)
        __syncthreads();       // readers of stage (tile+2)%3 (iter tile-1) done
        if (tile + 2 < 32) LOADKV(tile + 2, (tile + 2) % ATT_NST);
        cp_commit();

        if (tile == 0) {
            #pragma unroll
            for (int fk = 0; fk < 4; ++fk) {
                const uint32_t ra = sb + (uint32_t)(w * 16) * AROWB + laneA + fk * 32;
                ldm_x4(qh[fk], ra);
                ldm_x4(ql[fk], ra + ATT_QLO);
            }
        }

        const uint32_t kst = sb + ATT_KV + s * ATT_STG;
        const float* mb = (const float*)(smem + ATT_MB) + s * 64;

        float sf[8][4];
        #pragma unroll
        for (int i = 0; i < 8; ++i)
            #pragma unroll
            for (int j = 0; j < 4; ++j) sf[i][j] = 0.0f;

        #pragma unroll
        for (int fk = 0; fk < 4; ++fk) {
            uint32_t kh[8][2], kl[8][2];
            #pragma unroll
            for (int p = 0; p < 4; ++p) {
                uint32_t r0[4], r1[4];
                const uint32_t ra = kst + (uint32_t)(p * 16) * AROWB + laneB + fk * 32;
                ldm_x4(r0, ra);
                ldm_x4(r1, ra + 9216);
                kh[p * 2 + 0][0] = r0[0]; kh[p * 2 + 0][1] = r0[1];
                kh[p * 2 + 1][0] = r0[2]; kh[p * 2 + 1][1] = r0[3];
                kl[p * 2 + 0][0] = r1[0]; kl[p * 2 + 0][1] = r1[1];
                kl[p * 2 + 1][0] = r1[2]; kl[p * 2 + 1][1] = r1[3];
            }
            #pragma unroll
            for (int nf = 0; nf < 8; ++nf) {
                mma16816(sf[nf], qh[fk], kh[nf]);
                mma16816(sf[nf], qh[fk], kl[nf]);
                mma16816(sf[nf], ql[fk], kh[nf]);
            }
        }

        // online softmax in exp2 domain
        float pmA = -1e30f, pmB = -1e30f;
        #pragma unroll
        for (int nf = 0; nf < 8; ++nf) {
            const float m0 = mb[nf * 8 + c0];
            const float m1 = mb[nf * 8 + c0 + 1];
            sf[nf][0] = fmaf(sf[nf][0], SCL2, m0);
            sf[nf][1] = fmaf(sf[nf][1], SCL2, m1);
            sf[nf][2] = fmaf(sf[nf][2], SCL2, m0);
            sf[nf][3] = fmaf(sf[nf][3], SCL2, m1);
            pmA = fmaxf(pmA, fmaxf(sf[nf][0], sf[nf][1]));
            pmB = fmaxf(pmB, fmaxf(sf[nf][2], sf[nf][3]));
        }
        pmA = fmaxf(pmA, __shfl_xor_sync(0xffffffffu, pmA, 1));
        pmA = fmaxf(pmA, __shfl_xor_sync(0xffffffffu, pmA, 2));
        pmB = fmaxf(pmB, __shfl_xor_sync(0xffffffffu, pmB, 1));
        pmB = fmaxf(pmB, __shfl_xor_sync(0xffffffffu, pmB, 2));
        const float mnA = fmaxf(mA, pmA), mnB = fmaxf(mB, pmB);
        const float alA = ex2(mA - mnA), alB = ex2(mB - mnB);
        mA = mnA; mB = mnB;
        float rsA = 0.0f, rsB = 0.0f;
        #pragma unroll
        for (int nf = 0; nf < 8; ++nf) {
            sf[nf][0] = ex2(sf[nf][0] - mnA);
            sf[nf][1] = ex2(sf[nf][1] - mnA);
            sf[nf][2] = ex2(sf[nf][2] - mnB);
            sf[nf][3] = ex2(sf[nf][3] - mnB);
            rsA += sf[nf][0] + sf[nf][1];
            rsB += sf[nf][2] + sf[nf][3];
        }
        rsA += __shfl_xor_sync(0xffffffffu, rsA, 1);
        rsA += __shfl_xor_sync(0xffffffffu, rsA, 2);
        rsB += __shfl_xor_sync(0xffffffffu, rsB, 1);
        rsB += __shfl_xor_sync(0xffffffffu, rsB, 2);
        lA = lA * alA + rsA;
        lB = lB * alB + rsB;
        #pragma unroll
        for (int nf = 0; nf < 8; ++nf) {
            of[nf][0] *= alA; of[nf][1] *= alA;
            of[nf][2] *= alB; of[nf][3] *= alB;
        }

        #pragma unroll
        for (int fk = 0; fk < 4; ++fk) {
            uint32_t aHi[4], aLo[4];
            bfsplit2(sf[2 * fk][0],     sf[2 * fk][1],     aHi[0], aLo[0]);
            bfsplit2(sf[2 * fk][2],     sf[2 * fk][3],     aHi[1], aLo[1]);
            bfsplit2(sf[2 * fk + 1][0], sf[2 * fk + 1][1], aHi[2], aLo[2]);
            bfsplit2(sf[2 * fk + 1][2], sf[2 * fk + 1][3], aHi[3], aLo[3]);
            uint32_t vh[8][2], vl[8][2];
            #pragma unroll
            for (int p = 0; p < 4; ++p) {
                uint32_t r0[4], r1[4];
                const uint32_t ra = kst + 18432 + (uint32_t)(fk * 16) * AROWB
                                  + laneBT + p * 32;
                ldm_x4_t(r0, ra);
                ldm_x4_t(r1, ra + 9216);
                vh[p * 2 + 0][0] = r0[0]; vh[p * 2 + 0][1] = r0[1];
                vh[p * 2 + 1][0] = r0[2]; vh[p * 2 + 1][1] = r0[3];
                vl[p * 2 + 0][0] = r1[0]; vl[p * 2 + 0][1] = r1[1];
                vl[p * 2 + 1][0] = r1[2]; vl[p * 2 + 1][1] = r1[3];
            }
            #pragma unroll
            for (int nf = 0; nf < 8; ++nf) {
                mma16816(of[nf], aHi, vh[nf]);
                mma16816(of[nf], aHi, vl[nf]);
                mma16816(of[nf], aLo, vh[nf]);
            }
        }
    }

    const float iA = 1.0f / lA, iB = 1.0f / lB;
    const int rA = lane >> 2;
    const int rowA = tokb + q0 + w * 16 + rA;
    #pragma unroll
    for (int nf = 0; nf < 8; ++nf) {
        const int col = colb + nf * 8 + c0;
        uint32_t h0, l0, h1, l1;
        bfsplit2(of[nf][0] * iA, of[nf][1] * iA, h0, l0);
        bfsplit2(of[nf][2] * iB, of[nf][3] * iB, h1, l1);
        *(uint32_t*)&Yhi[(size_t)rowA * 1024 + col]       = h0;
        *(uint32_t*)&Ylo[(size_t)rowA * 1024 + col]       = l0;
        *(uint32_t*)&Yhi[(size_t)(rowA + 8) * 1024 + col] = h1;
        *(uint32_t*)&Ylo[(size_t)(rowA + 8) * 1024 + col] = l1;
    }
}

// ---------------------------------------------------------------------------
// LayerNorm: one row per CTA; optional fused bf16 hi/lo split output
// ---------------------------------------------------------------------------
__global__ __launch_bounds__(256)
void ln_kernel(const float* __restrict__ X, const float* __restrict__ w,
               const float* __restrict__ b, float* __restrict__ out,
               unsigned short* __restrict__ hi, unsigned short* __restrict__ lo)
{
    __shared__ float red[2][8];
    const int t = threadIdx.x;
    const size_t row = blockIdx.x;
    float4 xv = *(const float4*)&X[row * 1024 + t * 4];
    float s  = xv.x + xv.y + xv.z + xv.w;
    float s2 = xv.x * xv.x + xv.y * xv.y + xv.z * xv.z + xv.w * xv.w;
    #pragma unroll
    for (int off = 16; off; off >>= 1) {
        s  += __shfl_xor_sync(0xffffffffu, s,  off);
        s2 += __shfl_xor_sync(0xffffffffu, s2, off);
    }
    if ((t & 31) == 0) { red[0][t >> 5] = s; red[1][t >> 5] = s2; }
    __syncthreads();
    float S = 0.0f, S2 = 0.0f;
    #pragma unroll
    for (int i = 0; i < 8; ++i) { S += red[0][i]; S2 += red[1][i]; }
    const float mean = S * (1.0f / 1024.0f);
    const float var  = S2 * (1.0f / 1024.0f) - mean * mean;
    const float rstd = rsqrtf(var + 1e-5f);
    float4 wv = *(const float4*)&w[t * 4];
    float4 bv = *(const float4*)&b[t * 4];
    float4 r;
    r.x = (xv.x - mean) * rstd * wv.x + bv.x;
    r.y = (xv.y - mean) * rstd * wv.y + bv.y;
    r.z = (xv.z - mean) * rstd * wv.z + bv.z;
    r.w = (xv.w - mean) * rstd * wv.w + bv.w;
    if (out) *(float4*)&out[row * 1024 + t * 4] = r;
    if (hi) {
        uint32_t h0, l0, h1, l1;
        bfsplit2(r.x, r.y, h0, l0);
        bfsplit2(r.z, r.w, h1, l1);
        uint2 hv = make_uint2(h0, h1), lv = make_uint2(l0, l1);
        *(uint2*)&hi[row * 1024 + t * 4] = hv;
        *(uint2*)&lo[row * 1024 + t * 4] = lv;
    }
}

// ---------------------------------------------------------------------------
// launch
// ---------------------------------------------------------------------------
extern "C" void kernel_launch(void* const* d_in, const int* in_sizes, int n_in,
                              void* d_out, int out_size)
{
    (void)in_sizes; (void)n_in; (void)out_size;
    const float* x    = (const float*)d_in[0];
    const int*   mask = (const int*)  d_in[1];
    const float* WQ   = (const float*)d_in[2];
    const float* bQ   = (const float*)d_in[3];
    const float* WK   = (const float*)d_in[4];
    const float* bK   = (const float*)d_in[5];
    const float* WV   = (const float*)d_in[6];
    const float* bV   = (const float*)d_in[7];
    const float* WY   = (const float*)d_in[8];
    const float* bY   = (const float*)d_in[9];
    const float* ln1w = (const float*)d_in[10];
    const float* ln1b = (const float*)d_in[11];
    const float* ln2w = (const float*)d_in[12];
    const float* ln2b = (const float*)d_in[13];
    const float* W1   = (const float*)d_in[14];
    const float* b1   = (const float*)d_in[15];
    const float* W2   = (const float*)d_in[16];
    const float* b2   = (const float*)d_in[17];
    float* out = (float*)d_out;

    float *Qp, *Kp, *Vp, *Yp;
    unsigned short *Ahi, *Alo, *Whi, *Wlo;
    unsigned short *Qhi, *Qlo, *Khi, *Klo, *Vhi, *Vlo;
    cudaGetSymbolAddress((void**)&Qp,  g_Q);
    cudaGetSymbolAddress((void**)&Kp,  g_K);
    cudaGetSymbolAddress((void**)&Vp,  g_V);
    cudaGetSymbolAddress((void**)&Yp,  g_Y);
    cudaGetSymbolAddress((void**)&Ahi, g_Ahi);
    cudaGetSymbolAddress((void**)&Alo, g_Alo);
    cudaGetSymbolAddress((void**)&Whi, g_Whi);
    cudaGetSymbolAddress((void**)&Wlo, g_Wlo);
    cudaGetSymbolAddress((void**)&Qhi, g_Qhi);
    cudaGetSymbolAddress((void**)&Qlo, g_Qlo);
    cudaGetSymbolAddress((void**)&Khi, g_Khi);
    cudaGetSymbolAddress((void**)&Klo, g_Klo);
    cudaGetSymbolAddress((void**)&Vhi, g_Vhi);
    cudaGetSymbolAddress((void**)&Vlo, g_Vlo);

    unsigned short* Yhi = (unsigned short*)Yp;
    unsigned short* Ylo = (unsigned short*)Yp + (size_t)4096 * 1024;

    const size_t MB = (size_t)1024 * 1024;

    cudaFuncSetAttribute(tgemm_kernel<0>,
                         cudaFuncAttributeMaxDynamicSharedMemorySize, TG_SMEM);
    cudaFuncSetAttribute(tgemm_kernel<1>,
                         cudaFuncAttributeMaxDynamicSharedMemorySize, TG_SMEM);
    cudaFuncSetAttribute(tgemm_kernel<2>,
                         cudaFuncAttributeMaxDynamicSharedMemorySize, TG_SMEM);
    cudaFuncSetAttribute(attn_mma_kernel,
                         cudaFuncAttributeMaxDynamicSharedMemorySize, ATT_SMEM);

    dim3 blk(256);
    dim3 tsb(32, 8);

    // weight transposes
    tsplit_kernel<<<dim3(32, 32, 4), tsb>>>(WQ, WK, WV, WY, Whi, Wlo, MB, 1024, 1024);
    tsplit_kernel<<<dim3(128, 32, 1), tsb>>>(W1, W1, W1, W1, Whi + 4 * MB, Wlo + 4 * MB,
                                             0, 1024, 4096);
    tsplit_kernel<<<dim3(32, 128, 1), tsb>>>(W2, W2, W2, W2, Whi + 8 * MB, Wlo + 8 * MB,
                                             0, 4096, 1024);

    // x split
    split_kernel<<<4096, blk>>>(x, Ahi, Alo, (4096 * 1024) / 4);

    // QKV: all three outputs as bf16 splits (V natural layout)
    tgemm_kernel<0><<<dim3(8, 32, 3), blk, TG_SMEM>>>(
        Ahi, Alo, Whi, Wlo, MB, bQ, bK, bV, nullptr,
        nullptr, nullptr, nullptr,
        Qhi, Khi, Vhi,
        Qlo, Klo, Vlo,
        4096, 1024, 1024);

    // attention -> Yhi/Ylo bf16 (128 q/CTA, 3-stage single-sync pipeline)
    attn_mma_kernel<<<dim3(16, 32), blk, ATT_SMEM>>>(
        Qhi, Qlo, Khi, Klo, Vhi, Vlo, mask, Yhi, Ylo);

    // out-proj + residual x -> fp32 g_Q
    tgemm_kernel<2><<<dim3(8, 32, 1), blk, TG_SMEM>>>(
        Yhi, Ylo, Whi + 3 * MB, Wlo + 3 * MB, 0, bY, bY, bY, x,
        Qp, nullptr, nullptr,
        nullptr, nullptr, nullptr,
        nullptr, nullptr, nullptr,
        4096, 1024, 1024);

    // h = LN1 -> fp32 g_K + bf16 split (Qhi/Qlo reused)
    ln_kernel<<<4096, blk>>>(Qp, ln1w, ln1b, Kp, Qhi, Qlo);

    // FFN1: gelu(h@W1+b1) -> bf16 split only
    tgemm_kernel<1><<<dim3(32, 32, 1), blk, TG_SMEM>>>(
        Qhi, Qlo, Whi + 4 * MB, Wlo + 4 * MB, 0, b1, b1, b1, nullptr,
        nullptr, nullptr, nullptr,
        Ahi, nullptr, nullptr,
        Alo, nullptr, nullptr,
        4096, 4096, 1024);

    // FFN2: ff@W2+b2+h -> fp32 g_V
    tgemm_kernel<2><<<dim3(8, 32, 1), blk, TG_SMEM>>>(
        Ahi, Alo, Whi + 8 * MB, Wlo + 8 * MB, 0, b2, b2, b2, Kp,
        Vp, nullptr, nullptr,
        nullptr, nullptr, nullptr,
        nullptr, nullptr, nullptr,
        4096, 1024, 4096);

    // out = LN2
    ln_kernel<<<4096, blk>>>(Vp, ln2w, ln2b, out, nullptr, nullptr);
}

// round 15
// speedup vs baseline: 1.0586x; 1.0062x over previous
#include <cuda_runtime.h>
#include <cuda_bf16.h>
#include <math.h>
#include <stdint.h>

// ---------------------------------------------------------------------------
// Scratch (__device__ globals; no allocations allowed)
// ---------------------------------------------------------------------------
__device__ float g_Q [(size_t)4096 * 1024];   // out-proj result (a+x)
__device__ float g_K [(size_t)4096 * 1024];   // h = LN1(...)
__device__ float g_V [(size_t)4096 * 1024];   // ffn2 result fp32
__device__ float g_Y [(size_t)4096 * 1024];   // Yhi/Ylo bf16 halves
__device__ unsigned short g_Ahi[(size_t)4096 * 4096];
__device__ unsigned short g_Alo[(size_t)4096 * 4096];
__device__ unsigned short g_Whi[(size_t)12 * 1024 * 1024];
__device__ unsigned short g_Wlo[(size_t)12 * 1024 * 1024];
__device__ unsigned short g_Qhi [(size_t)4096 * 1024];
__device__ unsigned short g_Qlo [(size_t)4096 * 1024];
__device__ unsigned short g_Khi [(size_t)4096 * 1024];
__device__ unsigned short g_Klo [(size_t)4096 * 1024];
__device__ unsigned short g_Vhi [(size_t)4096 * 1024];  // V natural layout
__device__ unsigned short g_Vlo [(size_t)4096 * 1024];

__device__ __forceinline__ uint32_t smem_u32(const void* p) {
    uint32_t a;
    asm("{ .reg .u64 t; cvta.to.shared.u64 t, %1; cvt.u32.u64 %0, t; }"
        : "=r"(a) : "l"(p));
    return a;
}
__device__ __forceinline__ void cpa16(uint32_t s, const void* g) {
    asm volatile("cp.async.cg.shared.global [%0], [%1], 16;"
                 :: "r"(s), "l"(__cvta_generic_to_global(g)) : "memory");
}
__device__ __forceinline__ void cp_commit() {
    asm volatile("cp.async.commit_group;" ::: "memory");
}
template<int N>
__device__ __forceinline__ void cp_wait() {
    asm volatile("cp.async.wait_group %0;" :: "n"(N) : "memory");
}
__device__ __forceinline__ void ldm_x4(uint32_t* r, uint32_t saddr) {
    asm volatile("ldmatrix.sync.aligned.m8n8.x4.shared.b16 {%0,%1,%2,%3}, [%4];"
                 : "=r"(r[0]), "=r"(r[1]), "=r"(r[2]), "=r"(r[3]) : "r"(saddr));
}
__device__ __forceinline__ void ldm_x4_t(uint32_t* r, uint32_t saddr) {
    asm volatile("ldmatrix.sync.aligned.m8n8.x4.trans.shared.b16 {%0,%1,%2,%3}, [%4];"
                 : "=r"(r[0]), "=r"(r[1]), "=r"(r[2]), "=r"(r[3]) : "r"(saddr));
}
__device__ __forceinline__ void mma16816(float* c, const uint32_t* a, const uint32_t* b) {
    asm volatile("mma.sync.aligned.m16n8k16.row.col.f32.bf16.bf16.f32 "
                 "{%0,%1,%2,%3}, {%4,%5,%6,%7}, {%8,%9}, {%0,%1,%2,%3};"
                 : "+f"(c[0]), "+f"(c[1]), "+f"(c[2]), "+f"(c[3])
                 : "r"(a[0]), "r"(a[1]), "r"(a[2]), "r"(a[3]),
                   "r"(b[0]), "r"(b[1]));
}
__device__ __forceinline__ float ex2(float x) {
    float r;
    asm("ex2.approx.f32 %0, %1;" : "=f"(r) : "f"(x));
    return r;
}
__device__ __forceinline__ float gelu_f(float v) {
    return 0.5f * v * (1.0f + erff(v * 0.70710678118654752f));
}
__device__ __forceinline__ void bfsplit2(float x, float y, uint32_t& hi, uint32_t& lo) {
    __nv_bfloat16 hx = __float2bfloat16(x), hy = __float2bfloat16(y);
    hi = ((uint32_t)(*(unsigned short*)&hy) << 16) | (uint32_t)(*(unsigned short*)&hx);
    __nv_bfloat16 lx = __float2bfloat16(x - __bfloat162float(hx));
    __nv_bfloat16 ly = __float2bfloat16(y - __bfloat162float(hy));
    lo = ((uint32_t)(*(unsigned short*)&ly) << 16) | (uint32_t)(*(unsigned short*)&lx);
}
__device__ __forceinline__ void split1(float v, unsigned short& h, unsigned short& l) {
    __nv_bfloat16 hb = __float2bfloat16(v);
    __nv_bfloat16 lb = __float2bfloat16(v - __bfloat162float(hb));
    h = *(unsigned short*)&hb;
    l = *(unsigned short*)&lb;
}

// ---------------------------------------------------------------------------
// Tensor-core dense GEMM (R13/R14 best config — unchanged).
// k-chunk 32, 2-stage, ROWB 80, 2 CTAs/SM, single __syncthreads per chunk.
// ---------------------------------------------------------------------------
#define ROWB   80
#define TILEB  (128 * ROWB)
#define STAGEB (4 * TILEB)
#define NSTAGE 2
#define TG_SMEM (NSTAGE * STAGEB)    // 81920 -> 2 CTAs/SM

template<int EPI>
__global__ __launch_bounds__(256, 2)
void tgemm_kernel(const unsigned short* __restrict__ Ahi16,
                  const unsigned short* __restrict__ Alo16,
                  const unsigned short* __restrict__ Whi16,
                  const unsigned short* __restrict__ Wlo16,
                  size_t wz,
                  const float* __restrict__ bias0, const float* __restrict__ bias1,
                  const float* __restrict__ bias2,
                  const float* __restrict__ R,
                  float* __restrict__ Cf0, float* __restrict__ Cf1, float* __restrict__ Cf2,
                  unsigned short* __restrict__ Ch0, unsigned short* __restrict__ Ch1,
                  unsigned short* __restrict__ Ch2,
                  unsigned short* __restrict__ Cl0, unsigned short* __restrict__ Cl1,
                  unsigned short* __restrict__ Cl2,
                  int M, int N, int K)
{
    extern __shared__ __align__(128) char smem[];
    const int z = blockIdx.z;
    const unsigned short* Bh = Whi16 + wz * z;
    const unsigned short* Bl = Wlo16 + wz * z;
    const float* bias = (z == 0) ? bias0 : (z == 1) ? bias1 : bias2;
    float*          Cf = (z == 0) ? Cf0 : (z == 1) ? Cf1 : Cf2;
    unsigned short* Ch = (z == 0) ? Ch0 : (z == 1) ? Ch1 : Ch2;
    unsigned short* Cl = (z == 0) ? Cl0 : (z == 1) ? Cl1 : Cl2;

    const uint32_t sbase = smem_u32(smem);
    const int t    = threadIdx.x;
    const int wid  = t >> 5;
    const int lane = t & 31;
    const int m0   = blockIdx.y * 128;
    const int n0   = blockIdx.x * 128;
    const int wm   = (wid & 1) * 64;
    const int wn   = (wid >> 1) * 32;

    const int lrow = t >> 1;
    const int lu   = (t & 1) * 2;
    const unsigned short* pAh = Ahi16 + (size_t)(m0 + lrow) * K + lu * 8;
    const unsigned short* pAl = Alo16 + (size_t)(m0 + lrow) * K + lu * 8;
    const unsigned short* pBh = Bh    + (size_t)(n0 + lrow) * K + lu * 8;
    const unsigned short* pBl = Bl    + (size_t)(n0 + lrow) * K + lu * 8;
    const uint32_t sRow = (uint32_t)lrow * ROWB + lu * 16;

    #define LOAD_STAGE(cc, ss) do {                                        \
        const uint32_t sb_ = sbase + (ss) * STAGEB + sRow;                  \
        const size_t  ko_ = (size_t)(cc) * 32;                              \
        cpa16(sb_ + 0 * TILEB,      pAh + ko_);                             \
        cpa16(sb_ + 0 * TILEB + 16, pAh + ko_ + 8);                         \
        cpa16(sb_ + 1 * TILEB,      pAl + ko_);                             \
        cpa16(sb_ + 1 * TILEB + 16, pAl + ko_ + 8);                         \
        cpa16(sb_ + 2 * TILEB,      pBh + ko_);                             \
        cpa16(sb_ + 2 * TILEB + 16, pBh + ko_ + 8);                         \
        cpa16(sb_ + 3 * TILEB,      pBl + ko_);                             \
        cpa16(sb_ + 3 * TILEB + 16, pBl + ko_ + 8);                         \
    } while (0)

    const uint32_t laneA = (uint32_t)(lane & 15) * ROWB + (lane >> 4) * 16;
    const uint32_t laneB = (uint32_t)((lane & 7) + ((lane >> 4) << 3)) * ROWB
                         + ((lane >> 3) & 1) * 16;

    float acc[4][4][4];
    #pragma unroll
    for (int i = 0; i < 4; ++i)
        #pragma unroll
        for (int j = 0; j < 4; ++j)
            #pragma unroll
            for (int q = 0; q < 4; ++q) acc[i][j][q] = 0.0f;

    const int NC = K >> 5;
    LOAD_STAGE(0, 0); cp_commit();

    for (int c = 0; c < NC; ++c) {
        const int s = c & 1;
        cp_wait<0>();
        __syncthreads();
        if (c + 1 < NC) LOAD_STAGE(c + 1, s ^ 1);
        cp_commit();

        const uint32_t stg = sbase + s * STAGEB;
        #pragma unroll
        for (int ks = 0; ks < 2; ++ks) {
            const uint32_t kb = ks * 32;
            uint32_t bh[4][2], bl[4][2];
            #pragma unroll
            for (int p = 0; p < 2; ++p) {
                uint32_t rb[4], rl[4];
                const uint32_t ra = stg + (uint32_t)(wn + p * 16) * ROWB + laneB + kb;
                ldm_x4(rb, ra + 2 * TILEB);
                ldm_x4(rl, ra + 3 * TILEB);
                bh[p * 2 + 0][0] = rb[0]; bh[p * 2 + 0][1] = rb[1];
                bh[p * 2 + 1][0] = rb[2]; bh[p * 2 + 1][1] = rb[3];
                bl[p * 2 + 0][0] = rl[0]; bl[p * 2 + 0][1] = rl[1];
                bl[p * 2 + 1][0] = rl[2]; bl[p * 2 + 1][1] = rl[3];
            }
            #pragma unroll
            for (int mf = 0; mf < 4; ++mf) {
                uint32_t ah[4], al[4];
                const uint32_t ra = stg + (uint32_t)(wm + mf * 16) * ROWB + laneA + kb;
                ldm_x4(ah, ra + 0 * TILEB);
                ldm_x4(al, ra + 1 * TILEB);
                #pragma unroll
                for (int nf = 0; nf < 4; ++nf) {
                    mma16816(acc[mf][nf], ah, bh[nf]);
                    mma16816(acc[mf][nf], ah, bl[nf]);
                    mma16816(acc[mf][nf], al, bh[nf]);
                }
            }
        }
    }

    const int rbase = lane >> 2;
    const int cbase = (lane & 3) * 2;
    #pragma unroll
    for (int mf = 0; mf < 4; ++mf) {
        #pragma unroll
        for (int nf = 0; nf < 4; ++nf) {
            const int col = n0 + wn + nf * 8 + cbase;
            const float2 bb = *(const float2*)&bias[col];
            #pragma unroll
            for (int h = 0; h < 2; ++h) {
                const int row = m0 + wm + mf * 16 + rbase + h * 8;
                float2 rv;
                rv.x = acc[mf][nf][h * 2 + 0] + bb.x;
                rv.y = acc[mf][nf][h * 2 + 1] + bb.y;
                if (EPI == 1) { rv.x = gelu_f(rv.x); rv.y = gelu_f(rv.y); }
                if (EPI == 2) {
                    const float2 rr = *(const float2*)&R[(size_t)row * N + col];
                    rv.x += rr.x; rv.y += rr.y;
                }
                if (Cf) *(float2*)&Cf[(size_t)row * N + col] = rv;
                if (Ch) {
                    uint32_t hi, lo;
                    bfsplit2(rv.x, rv.y, hi, lo);
                    *(uint32_t*)&Ch[(size_t)row * N + col] = hi;
                    *(uint32_t*)&Cl[(size_t)row * N + col] = lo;
                }
            }
        }
    }
    #undef LOAD_STAGE
}

// ---------------------------------------------------------------------------
// Fused prep kernel: one launch does all weight transposes + x split.
// blockIdx.x segments (4096 blocks each):
//   [0,4096)      : WQ/WK/WV/WY transpose+split (1024 blocks per weight)
//   [4096,8192)   : W1 transpose+split (K=1024, N=4096)
//   [8192,12288)  : W2 transpose+split (K=4096, N=1024)
//   [12288,16384) : x fp32 -> bf16 hi/lo split
// ---------------------------------------------------------------------------
__global__ __launch_bounds__(256)
void prep_kernel(const float* __restrict__ WQ, const float* __restrict__ WK,
                 const float* __restrict__ WV, const float* __restrict__ WY,
                 const float* __restrict__ W1, const float* __restrict__ W2,
                 const float* __restrict__ x,
                 unsigned short* __restrict__ Whi, unsigned short* __restrict__ Wlo,
                 unsigned short* __restrict__ Ahi, unsigned short* __restrict__ Alo)
{
    __shared__ float s[32][33];
    const int bx = blockIdx.x;
    const int t  = threadIdx.x;
    const size_t MB = (size_t)1024 * 1024;

    if (bx >= 12288) {                        // x split
        const int i = (bx - 12288) * 256 + t;
        float4 v = ((const float4*)x)[i];
        ushort4 h, l;
        split1(v.x, h.x, l.x); split1(v.y, h.y, l.y);
        split1(v.z, h.z, l.z); split1(v.w, h.w, l.w);
        ((ushort4*)Ahi)[i] = h;
        ((ushort4*)Alo)[i] = l;
        return;
    }

    const float* W;
    unsigned short *Th, *Tl;
    int K, N, nb, kb;
    if (bx < 4096) {                          // 4 DxD weights
        const int z   = bx >> 10;
        const int blk = bx & 1023;
        W  = (z == 0) ? WQ : (z == 1) ? WK : (z == 2) ? WV : WY;
        Th = Whi + MB * z;  Tl = Wlo + MB * z;
        K = 1024; N = 1024;
        nb = (blk & 31) * 32; kb = (blk >> 5) * 32;
    } else if (bx < 8192) {                   // W1: K=1024, N=4096
        const int blk = bx - 4096;
        W = W1; Th = Whi + 4 * MB; Tl = Wlo + 4 * MB;
        K = 1024; N = 4096;
        nb = (blk & 127) * 32; kb = (blk >> 7) * 32;
    } else {                                  // W2: K=4096, N=1024
        const int blk = bx - 8192;
        W = W2; Th = Whi + 8 * MB; Tl = Wlo + 8 * MB;
        K = 4096; N = 1024;
        nb = (blk & 31) * 32; kb = (blk >> 5) * 32;
    }

    const int tx = t & 31, ty = t >> 5;
    #pragma unroll
    for (int i = 0; i < 4; ++i)
        s[ty + i * 8][tx] = W[(size_t)(kb + ty + i * 8) * N + nb + tx];
    __syncthreads();
    #pragma unroll
    for (int i = 0; i < 4; ++i) {
        const float v = s[tx][ty + i * 8];
        unsigned short h, l;
        split1(v, h, l);
        const size_t o = (size_t)(nb + ty + i * 8) * K + kb + tx;
        Th[o] = h; Tl[o] = l;
    }
}

// ---------------------------------------------------------------------------
// Flash attention via mma.sync; V natural layout (ldmatrix.trans).
// 256 threads / 128 queries, 3-stage KV pipeline, single sync per tile.
// (R14 best config — unchanged.)
// ---------------------------------------------------------------------------
#define AROWB   144
#define ATT_QLO 18432
#define ATT_KV  36864
#define ATT_STG 36864
#define ATT_NST 3
#define ATT_MB  (ATT_KV + ATT_NST * ATT_STG)   // 147456
#define ATT_SMEM (ATT_MB + 1024)
#define SCL2    0.18033688011112042591f   // 0.125 * log2(e)

__global__ __launch_bounds__(256, 1)
void attn_mma_kernel(const unsigned short* __restrict__ Qhi,
                     const unsigned short* __restrict__ Qlo,
                     const unsigned short* __restrict__ Khi,
                     const unsigned short* __restrict__ Klo,
                     const unsigned short* __restrict__ Vhi,
                     const unsigned short* __restrict__ Vlo,
                     const int* __restrict__ mask,
                     unsigned short* __restrict__ Yhi,
                     unsigned short* __restrict__ Ylo)
{
    extern __shared__ __align__(128) char smem[];
    const uint32_t sb = smem_u32(smem);
    const int t    = threadIdx.x;
    const int lane = t & 31;
    const int w    = t >> 5;
    const int q0   = blockIdx.x * 128;
    const int bh   = blockIdx.y;
    const int tokb = (bh >> 4) * 2048;
    const int colb = (bh & 15) * 64;

    const uint32_t laneA = (uint32_t)(lane & 15) * AROWB + (lane >> 4) * 16;
    const uint32_t laneB = (uint32_t)((lane & 7) + ((lane >> 4) << 3)) * AROWB
                         + ((lane >> 3) & 1) * 16;
    const uint32_t laneBT = (uint32_t)((lane & 7) + ((lane >> 3) & 1) * 8) * AROWB
                          + (lane >> 4) * 16;

    {
        const int row = t >> 1;
        const size_t g = (size_t)(tokb + q0 + row) * 1024 + colb;
        const uint32_t sr = (uint32_t)row * AROWB;
        #pragma unroll
        for (int i = 0; i < 4; ++i) {
            const int ch = (t & 1) * 4 + i;
            cpa16(sb + sr + ch * 16,           Qhi + g + ch * 8);
            cpa16(sb + ATT_QLO + sr + ch * 16, Qlo + g + ch * 8);
        }
    }

    auto LOADKV = [&](int tile, int s) {
        const int kv0 = tile * 64;
        const int row = t >> 2;
        const int q2  = t & 3;
        const uint32_t st = sb + ATT_KV + s * ATT_STG;
        const size_t gk = (size_t)(tokb + kv0 + row) * 1024 + colb;
        const uint32_t sr = (uint32_t)row * AROWB;
        #pragma unroll
        for (int i = 0; i < 2; ++i) {
            const int ch = q2 * 2 + i;
            cpa16(st +         sr + ch * 16, Khi + gk + ch * 8);
            cpa16(st +  9216 + sr + ch * 16, Klo + gk + ch * 8);
            cpa16(st + 18432 + sr + ch * 16, Vhi + gk + ch * 8);
            cpa16(st + 27648 + sr + ch * 16, Vlo + gk + ch * 8);
        }
        if (t < 64) {
            float* mb = (float*)(smem + ATT_MB) + s * 64;
            mb[t] = (mask[tokb + kv0 + t] == 0) ? -1e30f : 0.0f;
        }
    };

    LOADKV(0, 0); cp_commit();
    LOADKV(1, 1); cp_commit();

    uint32_t qh[4][4], ql[4][4];

    float of[8][4];
    #pragma unroll
    for (int i = 0; i < 8; ++i)
        #pragma unroll
        for (int j = 0; j < 4; ++j) of[i][j] = 0.0f;
    float mA = -1e30f, mB = -1e30f, lA = 0.0f, lB = 0.0f;
    const int c0 = (lane & 3) * 2;

    for (int tile = 0; tile < 32; ++tile) {
        const int s = tile % ATT_NST;
        cp_wait<1>();
        __syncthreads();
        if (tile + 2 < 32) LOADKV(tile + 2, (tile + 2) % ATT_NST);
        cp_commit();

        if (tile == 0) {
            #pragma unroll
            for (int fk = 0; fk < 4; ++fk) {
                const uint32_t ra = sb + (uint32_t)(w * 16) * AROWB + laneA + fk * 32;
                ldm_x4(qh[fk], ra);
                ldm_x4(ql[fk], ra + ATT_QLO);
            }
        }

        const uint32_t kst = sb + ATT_KV + s * ATT_STG;
        const float* mb = (const float*)(smem + ATT_MB) + s * 64;

        float sf[8][4];
        #pragma unroll
        for (int i = 0; i < 8; ++i)
            #pragma unroll
            for (int j = 0; j < 4; ++j) sf[i][j] = 0.0f;

        #pragma unroll
        for (int fk = 0; fk < 4; ++fk) {
            uint32_t kh[8][2], kl[8][2];
            #pragma unroll
            for (int p = 0; p < 4; ++p) {
                uint32_t r0[4], r1[4];
                const uint32_t ra = kst + (uint32_t)(p * 16) * AROWB + laneB + fk * 32;
                ldm_x4(r0, ra);
                ldm_x4(r1, ra + 9216);
                kh[p * 2 + 0][0] = r0[0]; kh[p * 2 + 0][1] = r0[1];
                kh[p * 2 + 1][0] = r0[2]; kh[p * 2 + 1][1] = r0[3];
                kl[p * 2 + 0][0] = r1[0]; kl[p * 2 + 0][1] = r1[1];
                kl[p * 2 + 1][0] = r1[2]; kl[p * 2 + 1][1] = r1[3];
            }
            #pragma unroll
            for (int nf = 0; nf < 8; ++nf) {
                mma16816(sf[nf], qh[fk], kh[nf]);
                mma16816(sf[nf], qh[fk], kl[nf]);
                mma16816(sf[nf], ql[fk], kh[nf]);
            }
        }

        // online softmax in exp2 domain
        float pmA = -1e30f, pmB = -1e30f;
        #pragma unroll
        for (int nf = 0; nf < 8; ++nf) {
            const float m0 = mb[nf * 8 + c0];
            const float m1 = mb[nf * 8 + c0 + 1];
            sf[nf][0] = fmaf(sf[nf][0], SCL2, m0);
            sf[nf][1] = fmaf(sf[nf][1], SCL2, m1);
            sf[nf][2] = fmaf(sf[nf][2], SCL2, m0);
            sf[nf][3] = fmaf(sf[nf][3], SCL2, m1);
            pmA = fmaxf(pmA, fmaxf(sf[nf][0], sf[nf][1]));
            pmB = fmaxf(pmB, fmaxf(sf[nf][2], sf[nf][3]));
        }
        pmA = fmaxf(pmA, __shfl_xor_sync(0xffffffffu, pmA, 1));
        pmA = fmaxf(pmA, __shfl_xor_sync(0xffffffffu, pmA, 2));
        pmB = fmaxf(pmB, __shfl_xor_sync(0xffffffffu, pmB, 1));
        pmB = fmaxf(pmB, __shfl_xor_sync(0xffffffffu, pmB, 2));
        const float mnA = fmaxf(mA, pmA), mnB = fmaxf(mB, pmB);
        const float alA = ex2(mA - mnA), alB = ex2(mB - mnB);
        mA = mnA; mB = mnB;
        float rsA = 0.0f, rsB = 0.0f;
        #pragma unroll
        for (int nf = 0; nf < 8; ++nf) {
            sf[nf][0] = ex2(sf[nf][0] - mnA);
            sf[nf][1] = ex2(sf[nf][1] - mnA);
            sf[nf][2] = ex2(sf[nf][2] - mnB);
            sf[nf][3] = ex2(sf[nf][3] - mnB);
            rsA += sf[nf][0] + sf[nf][1];
            rsB += sf[nf][2] + sf[nf][3];
        }
        rsA += __shfl_xor_sync(0xffffffffu, rsA, 1);
        rsA += __shfl_xor_sync(0xffffffffu, rsA, 2);
        rsB += __shfl_xor_sync(0xffffffffu, rsB, 1);
        rsB += __shfl_xor_sync(0xffffffffu, rsB, 2);
        lA = lA * alA + rsA;
        lB = lB * alB + rsB;
        #pragma unroll
        for (int nf = 0; nf < 8; ++nf) {
            of[nf][0] *= alA; of[nf][1] *= alA;
            of[nf][2] *= alB; of[nf][3] *= alB;
        }

        #pragma unroll
        for (int fk = 0; fk < 4; ++fk) {
            uint32_t aHi[4], aLo[4];
            bfsplit2(sf[2 * fk][0],     sf[2 * fk][1],     aHi[0], aLo[0]);
            bfsplit2(sf[2 * fk][2],     sf[2 * fk][3],     aHi[1], aLo[1]);
            bfsplit2(sf[2 * fk + 1][0], sf[2 * fk + 1][1], aHi[2], aLo[2]);
            bfsplit2(sf[2 * fk + 1][2], sf[2 * fk + 1][3], aHi[3], aLo[3]);
            uint32_t vh[8][2], vl[8][2];
            #pragma unroll
            for (int p = 0; p < 4; ++p) {
                uint32_t r0[4], r1[4];
                const uint32_t ra = kst + 18432 + (uint32_t)(fk * 16) * AROWB
                                  + laneBT + p * 32;
                ldm_x4_t(r0, ra);
                ldm_x4_t(r1, ra + 9216);
                vh[p * 2 + 0][0] = r0[0]; vh[p * 2 + 0][1] = r0[1];
                vh[p * 2 + 1][0] = r0[2]; vh[p * 2 + 1][1] = r0[3];
                vl[p * 2 + 0][0] = r1[0]; vl[p * 2 + 0][1] = r1[1];
                vl[p * 2 + 1][0] = r1[2]; vl[p * 2 + 1][1] = r1[3];
            }
            #pragma unroll
            for (int nf = 0; nf < 8; ++nf) {
                mma16816(of[nf], aHi, vh[nf]);
                mma16816(of[nf], aHi, vl[nf]);
                mma16816(of[nf], aLo, vh[nf]);
            }
        }
    }

    const float iA = 1.0f / lA, iB = 1.0f / lB;
    const int rA = lane >> 2;
    const int rowA = tokb + q0 + w * 16 + rA;
    #pragma unroll
    for (int nf = 0; nf < 8; ++nf) {
        const int col = colb + nf * 8 + c0;
        uint32_t h0, l0, h1, l1;
        bfsplit2(of[nf][0] * iA, of[nf][1] * iA, h0, l0);
        bfsplit2(of[nf][2] * iB, of[nf][3] * iB, h1, l1);
        *(uint32_t*)&Yhi[(size_t)rowA * 1024 + col]       = h0;
        *(uint32_t*)&Ylo[(size_t)rowA * 1024 + col]       = l0;
        *(uint32_t*)&Yhi[(size_t)(rowA + 8) * 1024 + col] = h1;
        *(uint32_t*)&Ylo[(size_t)(rowA + 8) * 1024 + col] = l1;
    }
}

// ---------------------------------------------------------------------------
// LayerNorm: one row per CTA; optional fused bf16 hi/lo split output
// ---------------------------------------------------------------------------
__global__ __launch_bounds__(256)
void ln_kernel(const float* __restrict__ X, const float* __restrict__ w,
               const float* __restrict__ b, float* __restrict__ out,
               unsigned short* __restrict__ hi, unsigned short* __restrict__ lo)
{
    __shared__ float red[2][8];
    const int t = threadIdx.x;
    const size_t row = blockIdx.x;
    float4 xv = *(const float4*)&X[row * 1024 + t * 4];
    float s  = xv.x + xv.y + xv.z + xv.w;
    float s2 = xv.x * xv.x + xv.y * xv.y + xv.z * xv.z + xv.w * xv.w;
    #pragma unroll
    for (int off = 16; off; off >>= 1) {
        s  += __shfl_xor_sync(0xffffffffu, s,  off);
        s2 += __shfl_xor_sync(0xffffffffu, s2, off);
    }
    if ((t & 31) == 0) { red[0][t >> 5] = s; red[1][t >> 5] = s2; }
    __syncthreads();
    float S = 0.0f, S2 = 0.0f;
    #pragma unroll
    for (int i = 0; i < 8; ++i) { S += red[0][i]; S2 += red[1][i]; }
    const float mean = S * (1.0f / 1024.0f);
    const float var  = S2 * (1.0f / 1024.0f) - mean * mean;
    const float rstd = rsqrtf(var + 1e-5f);
    float4 wv = *(const float4*)&w[t * 4];
    float4 bv = *(const float4*)&b[t * 4];
    float4 r;
    r.x = (xv.x - mean) * rstd * wv.x + bv.x;
    r.y = (xv.y - mean) * rstd * wv.y + bv.y;
    r.z = (xv.z - mean) * rstd * wv.z + bv.z;
    r.w = (xv.w - mean) * rstd * wv.w + bv.w;
    if (out) *(float4*)&out[row * 1024 + t * 4] = r;
    if (hi) {
        uint32_t h0, l0, h1, l1;
        bfsplit2(r.x, r.y, h0, l0);
        bfsplit2(r.z, r.w, h1, l1);
        uint2 hv = make_uint2(h0, h1), lv = make_uint2(l0, l1);
        *(uint2*)&hi[row * 1024 + t * 4] = hv;
        *(uint2*)&lo[row * 1024 + t * 4] = lv;
    }
}

// ---------------------------------------------------------------------------
// launch
// ---------------------------------------------------------------------------
extern "C" void kernel_launch(void* const* d_in, const int* in_sizes, int n_in,
                              void* d_out, int out_size)
{
    (void)in_sizes; (void)n_in; (void)out_size;
    const float* x    = (const float*)d_in[0];
    const int*   mask = (const int*)  d_in[1];
    const float* WQ   = (const float*)d_in[2];
    const float* bQ   = (const float*)d_in[3];
    const float* WK   = (const float*)d_in[4];
    const float* bK   = (const float*)d_in[5];
    const float* WV   = (const float*)d_in[6];
    const float* bV   = (const float*)d_in[7];
    const float* WY   = (const float*)d_in[8];
    const float* bY   = (const float*)d_in[9];
    const float* ln1w = (const float*)d_in[10];
    const float* ln1b = (const float*)d_in[11];
    const float* ln2w = (const float*)d_in[12];
    const float* ln2b = (const float*)d_in[13];
    const float* W1   = (const float*)d_in[14];
    const float* b1   = (const float*)d_in[15];
    const float* W2   = (const float*)d_in[16];
    const float* b2   = (const float*)d_in[17];
    float* out = (float*)d_out;

    float *Qp, *Kp, *Vp, *Yp;
    unsigned short *Ahi, *Alo, *Whi, *Wlo;
    unsigned short *Qhi, *Qlo, *Khi, *Klo, *Vhi, *Vlo;
    cudaGetSymbolAddress((void**)&Qp,  g_Q);
    cudaGetSymbolAddress((void**)&Kp,  g_K);
    cudaGetSymbolAddress((void**)&Vp,  g_V);
    cudaGetSymbolAddress((void**)&Yp,  g_Y);
    cudaGetSymbolAddress((void**)&Ahi, g_Ahi);
    cudaGetSymbolAddress((void**)&Alo, g_Alo);
    cudaGetSymbolAddress((void**)&Whi, g_Whi);
    cudaGetSymbolAddress((void**)&Wlo, g_Wlo);
    cudaGetSymbolAddress((void**)&Qhi, g_Qhi);
    cudaGetSymbolAddress((void**)&Qlo, g_Qlo);
    cudaGetSymbolAddress((void**)&Khi, g_Khi);
    cudaGetSymbolAddress((void**)&Klo, g_Klo);
    cudaGetSymbolAddress((void**)&Vhi, g_Vhi);
    cudaGetSymbolAddress((void**)&Vlo, g_Vlo);

    unsigned short* Yhi = (unsigned short*)Yp;
    unsigned short* Ylo = (unsigned short*)Yp + (size_t)4096 * 1024;

    const size_t MB = (size_t)1024 * 1024;

    cudaFuncSetAttribute(tgemm_kernel<0>,
                         cudaFuncAttributeMaxDynamicSharedMemorySize, TG_SMEM);
    cudaFuncSetAttribute(tgemm_kernel<1>,
                         cudaFuncAttributeMaxDynamicSharedMemorySize, TG_SMEM);
    cudaFuncSetAttribute(tgemm_kernel<2>,
                         cudaFuncAttributeMaxDynamicSharedMemorySize, TG_SMEM);
    cudaFuncSetAttribute(attn_mma_kernel,
                         cudaFuncAttributeMaxDynamicSharedMemorySize, ATT_SMEM);

    dim3 blk(256);

    // all prep (6 weight transposes + x split) in ONE launch
    prep_kernel<<<16384, blk>>>(WQ, WK, WV, WY, W1, W2, x, Whi, Wlo, Ahi, Alo);

    // QKV: all three outputs as bf16 splits (V natural layout)
    tgemm_kernel<0><<<dim3(8, 32, 3), blk, TG_SMEM>>>(
        Ahi, Alo, Whi, Wlo, MB, bQ, bK, bV, nullptr,
        nullptr, nullptr, nullptr,
        Qhi, Khi, Vhi,
        Qlo, Klo, Vlo,
        4096, 1024, 1024);

    // attention -> Yhi/Ylo bf16 (128 q/CTA, 3-stage single-sync pipeline)
    attn_mma_kernel<<<dim3(16, 32), blk, ATT_SMEM>>>(
        Qhi, Qlo, Khi, Klo, Vhi, Vlo, mask, Yhi, Ylo);

    // out-proj + residual x -> fp32 g_Q
    tgemm_kernel<2><<<dim3(8, 32, 1), blk, TG_SMEM>>>(
        Yhi, Ylo, Whi + 3 * MB, Wlo + 3 * MB, 0, bY, bY, bY, x,
        Qp, nullptr, nullptr,
        nullptr, nullptr, nullptr,
        nullptr, nullptr, nullptr,
        4096, 1024, 1024);

    // h = LN1 -> fp32 g_K + bf16 split (Qhi/Qlo reused)
    ln_kernel<<<4096, blk>>>(Qp, ln1w, ln1b, Kp, Qhi, Qlo);

    // FFN1: gelu(h@W1+b1) -> bf16 split only
    tgemm_kernel<1><<<dim3(32, 32, 1), blk, TG_SMEM>>>(
        Qhi, Qlo, Whi + 4 * MB, Wlo + 4 * MB, 0, b1, b1, b1, nullptr,
        nullptr, nullptr, nullptr,
        Ahi, nullptr, nullptr,
        Alo, nullptr, nullptr,
        4096, 4096, 1024);

    // FFN2: ff@W2+b2+h -> fp32 g_V
    tgemm_kernel<2><<<dim3(8, 32, 1), blk, TG_SMEM>>>(
        Ahi, Alo, Whi + 8 * MB, Wlo + 8 * MB, 0, b2, b2, b2, Kp,
        Vp, nullptr, nullptr,
        nullptr, nullptr, nullptr,
        nullptr, nullptr, nullptr,
        4096, 1024, 4096);

    // out = LN2
    ln_kernel<<<4096, blk>>>(Vp, ln2w, ln2b, out, nullptr, nullptr);
}

// round 16
// speedup vs baseline: 1.0953x; 1.0347x over previous
#include <cuda_runtime.h>
#include <cuda_bf16.h>
#include <math.h>
#include <stdint.h>

// ---------------------------------------------------------------------------
// Scratch (__device__ globals; no allocations allowed)
// ---------------------------------------------------------------------------
__device__ float g_Q [(size_t)4096 * 1024];   // out-proj result (a+x)
__device__ float g_K [(size_t)4096 * 1024];   // h = LN1(...)
__device__ float g_V [(size_t)4096 * 1024];   // ffn2 result fp32
__device__ float g_Y [(size_t)4096 * 1024];   // Yhi/Ylo bf16 halves
__device__ unsigned short g_Ahi[(size_t)4096 * 4096];
__device__ unsigned short g_Alo[(size_t)4096 * 4096];
__device__ unsigned short g_Whi[(size_t)12 * 1024 * 1024];
__device__ unsigned short g_Wlo[(size_t)12 * 1024 * 1024];
__device__ unsigned short g_Qhi [(size_t)4096 * 1024];
__device__ unsigned short g_Qlo [(size_t)4096 * 1024];
__device__ unsigned short g_Khi [(size_t)4096 * 1024];
__device__ unsigned short g_Klo [(size_t)4096 * 1024];
__device__ unsigned short g_Vhi [(size_t)4096 * 1024];  // V natural layout
__device__ unsigned short g_Vlo [(size_t)4096 * 1024];

__device__ __forceinline__ uint32_t smem_u32(const void* p) {
    uint32_t a;
    asm("{ .reg .u64 t; cvta.to.shared.u64 t, %1; cvt.u32.u64 %0, t; }"
        : "=r"(a) : "l"(p));
    return a;
}
__device__ __forceinline__ void cpa16(uint32_t s, const void* g) {
    asm volatile("cp.async.cg.shared.global [%0], [%1], 16;"
                 :: "r"(s), "l"(__cvta_generic_to_global(g)) : "memory");
}
__device__ __forceinline__ void cp_commit() {
    asm volatile("cp.async.commit_group;" ::: "memory");
}
template<int N>
__device__ __forceinline__ void cp_wait() {
    asm volatile("cp.async.wait_group %0;" :: "n"(N) : "memory");
}
__device__ __forceinline__ void ldm_x4(uint32_t* r, uint32_t saddr) {
    asm volatile("ldmatrix.sync.aligned.m8n8.x4.shared.b16 {%0,%1,%2,%3}, [%4];"
                 : "=r"(r[0]), "=r"(r[1]), "=r"(r[2]), "=r"(r[3]) : "r"(saddr));
}
__device__ __forceinline__ void ldm_x4_t(uint32_t* r, uint32_t saddr) {
    asm volatile("ldmatrix.sync.aligned.m8n8.x4.trans.shared.b16 {%0,%1,%2,%3}, [%4];"
                 : "=r"(r[0]), "=r"(r[1]), "=r"(r[2]), "=r"(r[3]) : "r"(saddr));
}
__device__ __forceinline__ void mma16816(float* c, const uint32_t* a, const uint32_t* b) {
    asm volatile("mma.sync.aligned.m16n8k16.row.col.f32.bf16.bf16.f32 "
                 "{%0,%1,%2,%3}, {%4,%5,%6,%7}, {%8,%9}, {%0,%1,%2,%3};"
                 : "+f"(c[0]), "+f"(c[1]), "+f"(c[2]), "+f"(c[3])
                 : "r"(a[0]), "r"(a[1]), "r"(a[2]), "r"(a[3]),
                   "r"(b[0]), "r"(b[1]));
}
__device__ __forceinline__ float ex2(float x) {
    float r;
    asm("ex2.approx.f32 %0, %1;" : "=f"(r) : "f"(x));
    return r;
}
__device__ __forceinline__ uint32_t cvt_bf16x2(float lo, float hi) {
    uint32_t r;
    asm("cvt.rn.bf16x2.f32 %0, %1, %2;" : "=r"(r) : "f"(hi), "f"(lo));
    return r;
}
__device__ __forceinline__ float gelu_f(float v) {
    return 0.5f * v * (1.0f + erff(v * 0.70710678118654752f));
}
__device__ __forceinline__ void bfsplit2(float x, float y, uint32_t& hi, uint32_t& lo) {
    __nv_bfloat16 hx = __float2bfloat16(x), hy = __float2bfloat16(y);
    hi = ((uint32_t)(*(unsigned short*)&hy) << 16) | (uint32_t)(*(unsigned short*)&hx);
    __nv_bfloat16 lx = __float2bfloat16(x - __bfloat162float(hx));
    __nv_bfloat16 ly = __float2bfloat16(y - __bfloat162float(hy));
    lo = ((uint32_t)(*(unsigned short*)&ly) << 16) | (uint32_t)(*(unsigned short*)&lx);
}
__device__ __forceinline__ void split1(float v, unsigned short& h, unsigned short& l) {
    __nv_bfloat16 hb = __float2bfloat16(v);
    __nv_bfloat16 lb = __float2bfloat16(v - __bfloat162float(hb));
    h = *(unsigned short*)&hb;
    l = *(unsigned short*)&lb;
}

// ---------------------------------------------------------------------------
// Tensor-core dense GEMM (R13/R15 best config — unchanged).
// k-chunk 32, 2-stage, ROWB 80, 2 CTAs/SM, single __syncthreads per chunk.
// ---------------------------------------------------------------------------
#define ROWB   80
#define TILEB  (128 * ROWB)
#define STAGEB (4 * TILEB)
#define NSTAGE 2
#define TG_SMEM (NSTAGE * STAGEB)    // 81920 -> 2 CTAs/SM

template<int EPI>
__global__ __launch_bounds__(256, 2)
void tgemm_kernel(const unsigned short* __restrict__ Ahi16,
                  const unsigned short* __restrict__ Alo16,
                  const unsigned short* __restrict__ Whi16,
                  const unsigned short* __restrict__ Wlo16,
                  size_t wz,
                  const float* __restrict__ bias0, const float* __restrict__ bias1,
                  const float* __restrict__ bias2,
                  const float* __restrict__ R,
                  float* __restrict__ Cf0, float* __restrict__ Cf1, float* __restrict__ Cf2,
                  unsigned short* __restrict__ Ch0, unsigned short* __restrict__ Ch1,
                  unsigned short* __restrict__ Ch2,
                  unsigned short* __restrict__ Cl0, unsigned short* __restrict__ Cl1,
                  unsigned short* __restrict__ Cl2,
                  int M, int N, int K)
{
    extern __shared__ __align__(128) char smem[];
    const int z = blockIdx.z;
    const unsigned short* Bh = Whi16 + wz * z;
    const unsigned short* Bl = Wlo16 + wz * z;
    const float* bias = (z == 0) ? bias0 : (z == 1) ? bias1 : bias2;
    float*          Cf = (z == 0) ? Cf0 : (z == 1) ? Cf1 : Cf2;
    unsigned short* Ch = (z == 0) ? Ch0 : (z == 1) ? Ch1 : Ch2;
    unsigned short* Cl = (z == 0) ? Cl0 : (z == 1) ? Cl1 : Cl2;

    const uint32_t sbase = smem_u32(smem);
    const int t    = threadIdx.x;
    const int wid  = t >> 5;
    const int lane = t & 31;
    const int m0   = blockIdx.y * 128;
    const int n0   = blockIdx.x * 128;
    const int wm   = (wid & 1) * 64;
    const int wn   = (wid >> 1) * 32;

    const int lrow = t >> 1;
    const int lu   = (t & 1) * 2;
    const unsigned short* pAh = Ahi16 + (size_t)(m0 + lrow) * K + lu * 8;
    const unsigned short* pAl = Alo16 + (size_t)(m0 + lrow) * K + lu * 8;
    const unsigned short* pBh = Bh    + (size_t)(n0 + lrow) * K + lu * 8;
    const unsigned short* pBl = Bl    + (size_t)(n0 + lrow) * K + lu * 8;
    const uint32_t sRow = (uint32_t)lrow * ROWB + lu * 16;

    #define LOAD_STAGE(cc, ss) do {                                        \
        const uint32_t sb_ = sbase + (ss) * STAGEB + sRow;                  \
        const size_t  ko_ = (size_t)(cc) * 32;                              \
        cpa16(sb_ + 0 * TILEB,      pAh + ko_);                             \
        cpa16(sb_ + 0 * TILEB + 16, pAh + ko_ + 8);                         \
        cpa16(sb_ + 1 * TILEB,      pAl + ko_);                             \
        cpa16(sb_ + 1 * TILEB + 16, pAl + ko_ + 8);                         \
        cpa16(sb_ + 2 * TILEB,      pBh + ko_);                             \
        cpa16(sb_ + 2 * TILEB + 16, pBh + ko_ + 8);                         \
        cpa16(sb_ + 3 * TILEB,      pBl + ko_);                             \
        cpa16(sb_ + 3 * TILEB + 16, pBl + ko_ + 8);                         \
    } while (0)

    const uint32_t laneA = (uint32_t)(lane & 15) * ROWB + (lane >> 4) * 16;
    const uint32_t laneB = (uint32_t)((lane & 7) + ((lane >> 4) << 3)) * ROWB
                         + ((lane >> 3) & 1) * 16;

    float acc[4][4][4];
    #pragma unroll
    for (int i = 0; i < 4; ++i)
        #pragma unroll
        for (int j = 0; j < 4; ++j)
            #pragma unroll
            for (int q = 0; q < 4; ++q) acc[i][j][q] = 0.0f;

    const int NC = K >> 5;
    LOAD_STAGE(0, 0); cp_commit();

    for (int c = 0; c < NC; ++c) {
        const int s = c & 1;
        cp_wait<0>();
        __syncthreads();
        if (c + 1 < NC) LOAD_STAGE(c + 1, s ^ 1);
        cp_commit();

        const uint32_t stg = sbase + s * STAGEB;
        #pragma unroll
        for (int ks = 0; ks < 2; ++ks) {
            const uint32_t kb = ks * 32;
            uint32_t bh[4][2], bl[4][2];
            #pragma unroll
            for (int p = 0; p < 2; ++p) {
                uint32_t rb[4], rl[4];
                const uint32_t ra = stg + (uint32_t)(wn + p * 16) * ROWB + laneB + kb;
                ldm_x4(rb, ra + 2 * TILEB);
                ldm_x4(rl, ra + 3 * TILEB);
                bh[p * 2 + 0][0] = rb[0]; bh[p * 2 + 0][1] = rb[1];
                bh[p * 2 + 1][0] = rb[2]; bh[p * 2 + 1][1] = rb[3];
                bl[p * 2 + 0][0] = rl[0]; bl[p * 2 + 0][1] = rl[1];
                bl[p * 2 + 1][0] = rl[2]; bl[p * 2 + 1][1] = rl[3];
            }
            #pragma unroll
            for (int mf = 0; mf < 4; ++mf) {
                uint32_t ah[4], al[4];
                const uint32_t ra = stg + (uint32_t)(wm + mf * 16) * ROWB + laneA + kb;
                ldm_x4(ah, ra + 0 * TILEB);
                ldm_x4(al, ra + 1 * TILEB);
                #pragma unroll
                for (int nf = 0; nf < 4; ++nf) {
                    mma16816(acc[mf][nf], ah, bh[nf]);
                    mma16816(acc[mf][nf], ah, bl[nf]);
                    mma16816(acc[mf][nf], al, bh[nf]);
                }
            }
        }
    }

    const int rbase = lane >> 2;
    const int cbase = (lane & 3) * 2;
    #pragma unroll
    for (int mf = 0; mf < 4; ++mf) {
        #pragma unroll
        for (int nf = 0; nf < 4; ++nf) {
            const int col = n0 + wn + nf * 8 + cbase;
            const float2 bb = *(const float2*)&bias[col];
            #pragma unroll
            for (int h = 0; h < 2; ++h) {
                const int row = m0 + wm + mf * 16 + rbase + h * 8;
                float2 rv;
                rv.x = acc[mf][nf][h * 2 + 0] + bb.x;
                rv.y = acc[mf][nf][h * 2 + 1] + bb.y;
                if (EPI == 1) { rv.x = gelu_f(rv.x); rv.y = gelu_f(rv.y); }
                if (EPI == 2) {
                    const float2 rr = *(const float2*)&R[(size_t)row * N + col];
                    rv.x += rr.x; rv.y += rr.y;
                }
                if (Cf) *(float2*)&Cf[(size_t)row * N + col] = rv;
                if (Ch) {
                    uint32_t hi, lo;
                    bfsplit2(rv.x, rv.y, hi, lo);
                    *(uint32_t*)&Ch[(size_t)row * N + col] = hi;
                    *(uint32_t*)&Cl[(size_t)row * N + col] = lo;
                }
            }
        }
    }
    #undef LOAD_STAGE
}

// ---------------------------------------------------------------------------
// Fused prep kernel (R15 — unchanged): all weight transposes + x split.
// ---------------------------------------------------------------------------
__global__ __launch_bounds__(256)
void prep_kernel(const float* __restrict__ WQ, const float* __restrict__ WK,
                 const float* __restrict__ WV, const float* __restrict__ WY,
                 const float* __restrict__ W1, const float* __restrict__ W2,
                 const float* __restrict__ x,
                 unsigned short* __restrict__ Whi, unsigned short* __restrict__ Wlo,
                 unsigned short* __restrict__ Ahi, unsigned short* __restrict__ Alo)
{
    __shared__ float s[32][33];
    const int bx = blockIdx.x;
    const int t  = threadIdx.x;
    const size_t MB = (size_t)1024 * 1024;

    if (bx >= 12288) {                        // x split
        const int i = (bx - 12288) * 256 + t;
        float4 v = ((const float4*)x)[i];
        ushort4 h, l;
        split1(v.x, h.x, l.x); split1(v.y, h.y, l.y);
        split1(v.z, h.z, l.z); split1(v.w, h.w, l.w);
        ((ushort4*)Ahi)[i] = h;
        ((ushort4*)Alo)[i] = l;
        return;
    }

    const float* W;
    unsigned short *Th, *Tl;
    int K, N, nb, kb;
    if (bx < 4096) {
        const int z   = bx >> 10;
        const int blk = bx & 1023;
        W  = (z == 0) ? WQ : (z == 1) ? WK : (z == 2) ? WV : WY;
        Th = Whi + MB * z;  Tl = Wlo + MB * z;
        K = 1024; N = 1024;
        nb = (blk & 31) * 32; kb = (blk >> 5) * 32;
    } else if (bx < 8192) {
        const int blk = bx - 4096;
        W = W1; Th = Whi + 4 * MB; Tl = Wlo + 4 * MB;
        K = 1024; N = 4096;
        nb = (blk & 127) * 32; kb = (blk >> 7) * 32;
    } else {
        const int blk = bx - 8192;
        W = W2; Th = Whi + 8 * MB; Tl = Wlo + 8 * MB;
        K = 4096; N = 1024;
        nb = (blk & 31) * 32; kb = (blk >> 5) * 32;
    }

    const int tx = t & 31, ty = t >> 5;
    #pragma unroll
    for (int i = 0; i < 4; ++i)
        s[ty + i * 8][tx] = W[(size_t)(kb + ty + i * 8) * N + nb + tx];
    __syncthreads();
    #pragma unroll
    for (int i = 0; i < 4; ++i) {
        const float v = s[tx][ty + i * 8];
        unsigned short h, l;
        split1(v, h, l);
        const size_t o = (size_t)(nb + ty + i * 8) * K + kb + tx;
        Th[o] = h; Tl[o] = l;
    }
}

// ---------------------------------------------------------------------------
// Flash attention via mma.sync; V natural layout (ldmatrix.trans).
// 256 threads / 128 queries, 3-stage KV pipeline, single sync per tile.
// PV uses 2-product (Phi*Vhi + Phi*Vlo): P rounded to bf16 directly.
// ---------------------------------------------------------------------------
#define AROWB   144
#define ATT_QLO 18432
#define ATT_KV  36864
#define ATT_STG 36864
#define ATT_NST 3
#define ATT_MB  (ATT_KV + ATT_NST * ATT_STG)   // 147456
#define ATT_SMEM (ATT_MB + 1024)
#define SCL2    0.18033688011112042591f   // 0.125 * log2(e)

__global__ __launch_bounds__(256, 1)
void attn_mma_kernel(const unsigned short* __restrict__ Qhi,
                     const unsigned short* __restrict__ Qlo,
                     const unsigned short* __restrict__ Khi,
                     const unsigned short* __restrict__ Klo,
                     const unsigned short* __restrict__ Vhi,
                     const unsigned short* __restrict__ Vlo,
                     const int* __restrict__ mask,
                     unsigned short* __restrict__ Yhi,
                     unsigned short* __restrict__ Ylo)
{
    extern __shared__ __align__(128) char smem[];
    const uint32_t sb = smem_u32(smem);
    const int t    = threadIdx.x;
    const int lane = t & 31;
    const int w    = t >> 5;
    const int q0   = blockIdx.x * 128;
    const int bh   = blockIdx.y;
    const int tokb = (bh >> 4) * 2048;
    const int colb = (bh & 15) * 64;

    const uint32_t laneA = (uint32_t)(lane & 15) * AROWB + (lane >> 4) * 16;
    const uint32_t laneB = (uint32_t)((lane & 7) + ((lane >> 4) << 3)) * AROWB
                         + ((lane >> 3) & 1) * 16;
    const uint32_t laneBT = (uint32_t)((lane & 7) + ((lane >> 3) & 1) * 8) * AROWB
                          + (lane >> 4) * 16;

    {
        const int row = t >> 1;
        const size_t g = (size_t)(tokb + q0 + row) * 1024 + colb;
        const uint32_t sr = (uint32_t)row * AROWB;
        #pragma unroll
        for (int i = 0; i < 4; ++i) {
            const int ch = (t & 1) * 4 + i;
            cpa16(sb + sr + ch * 16,           Qhi + g + ch * 8);
            cpa16(sb + ATT_QLO + sr + ch * 16, Qlo + g + ch * 8);
        }
    }

    auto LOADKV = [&](int tile, int s) {
        const int kv0 = tile * 64;
        const int row = t >> 2;
        const int q2  = t & 3;
        const uint32_t st = sb + ATT_KV + s * ATT_STG;
        const size_t gk = (size_t)(tokb + kv0 + row) * 1024 + colb;
        const uint32_t sr = (uint32_t)row * AROWB;
        #pragma unroll
        for (int i = 0; i < 2; ++i) {
            const int ch = q2 * 2 + i;
            cpa16(st +         sr + ch * 16, Khi + gk + ch * 8);
            cpa16(st +  9216 + sr + ch * 16, Klo + gk + ch * 8);
            cpa16(st + 18432 + sr + ch * 16, Vhi + gk + ch * 8);
            cpa16(st + 27648 + sr + ch * 16, Vlo + gk + ch * 8);
        }
        if (t < 64) {
            float* mb = (float*)(smem + ATT_MB) + s * 64;
            mb[t] = (mask[tokb + kv0 + t] == 0) ? -1e30f : 0.0f;
        }
    };

    LOADKV(0, 0); cp_commit();
    LOADKV(1, 1); cp_commit();

    uint32_t qh[4][4], ql[4][4];

    float of[8][4];
    #pragma unroll
    for (int i = 0; i < 8; ++i)
        #pragma unroll
        for (int j = 0; j < 4; ++j) of[i][j] = 0.0f;
    float mA = -1e30f, mB = -1e30f, lA = 0.0f, lB = 0.0f;
    const int c0 = (lane & 3) * 2;

    for (int tile = 0; tile < 32; ++tile) {
        const int s = tile % ATT_NST;
        cp_wait<1>();
        __syncthreads();
        if (tile + 2 < 32) LOADKV(tile + 2, (tile + 2) % ATT_NST);
        cp_commit();

        if (tile == 0) {
            #pragma unroll
            for (int fk = 0; fk < 4; ++fk) {
                const uint32_t ra = sb + (uint32_t)(w * 16) * AROWB + laneA + fk * 32;
                ldm_x4(qh[fk], ra);
                ldm_x4(ql[fk], ra + ATT_QLO);
            }
        }

        const uint32_t kst = sb + ATT_KV + s * ATT_STG;
        const float* mb = (const float*)(smem + ATT_MB) + s * 64;

        float sf[8][4];
        #pragma unroll
        for (int i = 0; i < 8; ++i)
            #pragma unroll
            for (int j = 0; j < 4; ++j) sf[i][j] = 0.0f;

        #pragma unroll
        for (int fk = 0; fk < 4; ++fk) {
            uint32_t kh[8][2], kl[8][2];
            #pragma unroll
            for (int p = 0; p < 4; ++p) {
                uint32_t r0[4], r1[4];
                const uint32_t ra = kst + (uint32_t)(p * 16) * AROWB + laneB + fk * 32;
                ldm_x4(r0, ra);
                ldm_x4(r1, ra + 9216);
                kh[p * 2 + 0][0] = r0[0]; kh[p * 2 + 0][1] = r0[1];
                kh[p * 2 + 1][0] = r0[2]; kh[p * 2 + 1][1] = r0[3];
                kl[p * 2 + 0][0] = r1[0]; kl[p * 2 + 0][1] = r1[1];
                kl[p * 2 + 1][0] = r1[2]; kl[p * 2 + 1][1] = r1[3];
            }
            #pragma unroll
            for (int nf = 0; nf < 8; ++nf) {
                mma16816(sf[nf], qh[fk], kh[nf]);
                mma16816(sf[nf], qh[fk], kl[nf]);
                mma16816(sf[nf], ql[fk], kh[nf]);
            }
        }

        // online softmax in exp2 domain
        float pmA = -1e30f, pmB = -1e30f;
        #pragma unroll
        for (int nf = 0; nf < 8; ++nf) {
            const float m0 = mb[nf * 8 + c0];
            const float m1 = mb[nf * 8 + c0 + 1];
            sf[nf][0] = fmaf(sf[nf][0], SCL2, m0);
            sf[nf][1] = fmaf(sf[nf][1], SCL2, m1);
            sf[nf][2] = fmaf(sf[nf][2], SCL2, m0);
            sf[nf][3] = fmaf(sf[nf][3], SCL2, m1);
            pmA = fmaxf(pmA, fmaxf(sf[nf][0], sf[nf][1]));
            pmB = fmaxf(pmB, fmaxf(sf[nf][2], sf[nf][3]));
        }
        pmA = fmaxf(pmA, __shfl_xor_sync(0xffffffffu, pmA, 1));
        pmA = fmaxf(pmA, __shfl_xor_sync(0xffffffffu, pmA, 2));
        pmB = fmaxf(pmB, __shfl_xor_sync(0xffffffffu, pmB, 1));
        pmB = fmaxf(pmB, __shfl_xor_sync(0xffffffffu, pmB, 2));
        const float mnA = fmaxf(mA, pmA), mnB = fmaxf(mB, pmB);
        const float alA = ex2(mA - mnA), alB = ex2(mB - mnB);
        mA = mnA; mB = mnB;
        float rsA = 0.0f, rsB = 0.0f;
        #pragma unroll
        for (int nf = 0; nf < 8; ++nf) {
            sf[nf][0] = ex2(sf[nf][0] - mnA);
            sf[nf][1] = ex2(sf[nf][1] - mnA);
            sf[nf][2] = ex2(sf[nf][2] - mnB);
            sf[nf][3] = ex2(sf[nf][3] - mnB);
            rsA += sf[nf][0] + sf[nf][1];
            rsB += sf[nf][2] + sf[nf][3];
        }
        rsA += __shfl_xor_sync(0xffffffffu, rsA, 1);
        rsA += __shfl_xor_sync(0xffffffffu, rsA, 2);
        rsB += __shfl_xor_sync(0xffffffffu, rsB, 1);
        rsB += __shfl_xor_sync(0xffffffffu, rsB, 2);
        lA = lA * alA + rsA;
        lB = lB * alB + rsB;
        #pragma unroll
        for (int nf = 0; nf < 8; ++nf) {
            of[nf][0] *= alA; of[nf][1] *= alA;
            of[nf][2] *= alB; of[nf][3] *= alB;
        }

        // O += P @ (Vhi + Vlo): P rounded directly to bf16 (2-product PV)
        #pragma unroll
        for (int fk = 0; fk < 4; ++fk) {
            uint32_t aHi[4];
            aHi[0] = cvt_bf16x2(sf[2 * fk][0],     sf[2 * fk][1]);
            aHi[1] = cvt_bf16x2(sf[2 * fk][2],     sf[2 * fk][3]);
            aHi[2] = cvt_bf16x2(sf[2 * fk + 1][0], sf[2 * fk + 1][1]);
            aHi[3] = cvt_bf16x2(sf[2 * fk + 1][2], sf[2 * fk + 1][3]);
            uint32_t vh[8][2], vl[8][2];
            #pragma unroll
            for (int p = 0; p < 4; ++p) {
                uint32_t r0[4], r1[4];
                const uint32_t ra = kst + 18432 + (uint32_t)(fk * 16) * AROWB
                                  + laneBT + p * 32;
                ldm_x4_t(r0, ra);
                ldm_x4_t(r1, ra + 9216);
                vh[p * 2 + 0][0] = r0[0]; vh[p * 2 + 0][1] = r0[1];
                vh[p * 2 + 1][0] = r0[2]; vh[p * 2 + 1][1] = r0[3];
                vl[p * 2 + 0][0] = r1[0]; vl[p * 2 + 0][1] = r1[1];
                vl[p * 2 + 1][0] = r1[2]; vl[p * 2 + 1][1] = r1[3];
            }
            #pragma unroll
            for (int nf = 0; nf < 8; ++nf) {
                mma16816(of[nf], aHi, vh[nf]);
                mma16816(of[nf], aHi, vl[nf]);
            }
        }
    }

    const float iA = 1.0f / lA, iB = 1.0f / lB;
    const int rA = lane >> 2;
    const int rowA = tokb + q0 + w * 16 + rA;
    #pragma unroll
    for (int nf = 0; nf < 8; ++nf) {
        const int col = colb + nf * 8 + c0;
        uint32_t h0, l0, h1, l1;
        bfsplit2(of[nf][0] * iA, of[nf][1] * iA, h0, l0);
        bfsplit2(of[nf][2] * iB, of[nf][3] * iB, h1, l1);
        *(uint32_t*)&Yhi[(size_t)rowA * 1024 + col]       = h0;
        *(uint32_t*)&Ylo[(size_t)rowA * 1024 + col]       = l0;
        *(uint32_t*)&Yhi[(size_t)(rowA + 8) * 1024 + col] = h1;
        *(uint32_t*)&Ylo[(size_t)(rowA + 8) * 1024 + col] = l1;
    }
}

// ---------------------------------------------------------------------------
// LayerNorm: one row per CTA; optional fused bf16 hi/lo split output
// ---------------------------------------------------------------------------
__global__ __launch_bounds__(256)
void ln_kernel(const float* __restrict__ X, const float* __restrict__ w,
               const float* __restrict__ b, float* __restrict__ out,
               unsigned short* __restrict__ hi, unsigned short* __restrict__ lo)
{
    __shared__ float red[2][8];
    const int t = threadIdx.x;
    const size_t row = blockIdx.x;
    float4 xv = *(const float4*)&X[row * 1024 + t * 4];
    float s  = xv.x + xv.y + xv.z + xv.w;
    float s2 = xv.x * xv.x + xv.y * xv.y + xv.z * xv.z + xv.w * xv.w;
    #pragma unroll
    for (int off = 16; off; off >>= 1) {
        s  += __shfl_xor_sync(0xffffffffu, s,  off);
        s2 += __shfl_xor_sync(0xffffffffu, s2, off);
    }
    if ((t & 31) == 0) { red[0][t >> 5] = s; red[1][t >> 5] = s2; }
    __syncthreads();
    float S = 0.0f, S2 = 0.0f;
    #pragma unroll
    for (int i = 0; i < 8; ++i) { S += red[0][i]; S2 += red[1][i]; }
    const float mean = S * (1.0f / 1024.0f);
    const float var  = S2 * (1.0f / 1024.0f) - mean * mean;
    const float rstd = rsqrtf(var + 1e-5f);
    float4 wv = *(const float4*)&w[t * 4];
    float4 bv = *(const float4*)&b[t * 4];
    float4 r;
    r.x = (xv.x - mean) * rstd * wv.x + bv.x;
    r.y = (xv.y - mean) * rstd * wv.y + bv.y;
    r.z = (xv.z - mean) * rstd * wv.z + bv.z;
    r.w = (xv.w - mean) * rstd * wv.w + bv.w;
    if (out) *(float4*)&out[row * 1024 + t * 4] = r;
    if (hi) {
        uint32_t h0, l0, h1, l1;
        bfsplit2(r.x, r.y, h0, l0);
        bfsplit2(r.z, r.w, h1, l1);
        uint2 hv = make_uint2(h0, h1), lv = make_uint2(l0, l1);
        *(uint2*)&hi[row * 1024 + t * 4] = hv;
        *(uint2*)&lo[row * 1024 + t * 4] = lv;
    }
}

// ---------------------------------------------------------------------------
// launch
// ---------------------------------------------------------------------------
extern "C" void kernel_launch(void* const* d_in, const int* in_sizes, int n_in,
                              void* d_out, int out_size)
{
    (void)in_sizes; (void)n_in; (void)out_size;
    const float* x    = (const float*)d_in[0];
    const int*   mask = (const int*)  d_in[1];
    const float* WQ   = (const float*)d_in[2];
    const float* bQ   = (const float*)d_in[3];
    const float* WK   = (const float*)d_in[4];
    const float* bK   = (const float*)d_in[5];
    const float* WV   = (const float*)d_in[6];
    const float* bV   = (const float*)d_in[7];
    const float* WY   = (const float*)d_in[8];
    const float* bY   = (const float*)d_in[9];
    const float* ln1w = (const float*)d_in[10];
    const float* ln1b = (const float*)d_in[11];
    const float* ln2w = (const float*)d_in[12];
    const float* ln2b = (const float*)d_in[13];
    const float* W1   = (const float*)d_in[14];
    const float* b1   = (const float*)d_in[15];
    const float* W2   = (const float*)d_in[16];
    const float* b2   = (const float*)d_in[17];
    float* out = (float*)d_out;

    float *Qp, *Kp, *Vp, *Yp;
    unsigned short *Ahi, *Alo, *Whi, *Wlo;
    unsigned short *Qhi, *Qlo, *Khi, *Klo, *Vhi, *Vlo;
    cudaGetSymbolAddress((void**)&Qp,  g_Q);
    cudaGetSymbolAddress((void**)&Kp,  g_K);
    cudaGetSymbolAddress((void**)&Vp,  g_V);
    cudaGetSymbolAddress((void**)&Yp,  g_Y);
    cudaGetSymbolAddress((void**)&Ahi, g_Ahi);
    cudaGetSymbolAddress((void**)&Alo, g_Alo);
    cudaGetSymbolAddress((void**)&Whi, g_Whi);
    cudaGetSymbolAddress((void**)&Wlo, g_Wlo);
    cudaGetSymbolAddress((void**)&Qhi, g_Qhi);
    cudaGetSymbolAddress((void**)&Qlo, g_Qlo);
    cudaGetSymbolAddress((void**)&Khi, g_Khi);
    cudaGetSymbolAddress((void**)&Klo, g_Klo);
    cudaGetSymbolAddress((void**)&Vhi, g_Vhi);
    cudaGetSymbolAddress((void**)&Vlo, g_Vlo);

    unsigned short* Yhi = (unsigned short*)Yp;
    unsigned short* Ylo = (unsigned short*)Yp + (size_t)4096 * 1024;

    const size_t MB = (size_t)1024 * 1024;

    cudaFuncSetAttribute(tgemm_kernel<0>,
                         cudaFuncAttributeMaxDynamicSharedMemorySize, TG_SMEM);
    cudaFuncSetAttribute(tgemm_kernel<1>,
                         cudaFuncAttributeMaxDynamicSharedMemorySize, TG_SMEM);
    cudaFuncSetAttribute(tgemm_kernel<2>,
                         cudaFuncAttributeMaxDynamicSharedMemorySize, TG_SMEM);
    cudaFuncSetAttribute(attn_mma_kernel,
                         cudaFuncAttributeMaxDynamicSharedMemorySize, ATT_SMEM);

    dim3 blk(256);

    // all prep (6 weight transposes + x split) in ONE launch
    prep_kernel<<<16384, blk>>>(WQ, WK, WV, WY, W1, W2, x, Whi, Wlo, Ahi, Alo);

    // QKV: all three outputs as bf16 splits (V natural layout)
    tgemm_kernel<0><<<dim3(8, 32, 3), blk, TG_SMEM>>>(
        Ahi, Alo, Whi, Wlo, MB, bQ, bK, bV, nullptr,
        nullptr, nullptr, nullptr,
        Qhi, Khi, Vhi,
        Qlo, Klo, Vlo,
        4096, 1024, 1024);

    // attention -> Yhi/Ylo bf16 (128 q/CTA, 3-stage single-sync, 2-product PV)
    attn_mma_kernel<<<dim3(16, 32), blk, ATT_SMEM>>>(
        Qhi, Qlo, Khi, Klo, Vhi, Vlo, mask, Yhi, Ylo);

    // out-proj + residual x -> fp32 g_Q
    tgemm_kernel<2><<<dim3(8, 32, 1), blk, TG_SMEM>>>(
        Yhi, Ylo, Whi + 3 * MB, Wlo + 3 * MB, 0, bY, bY, bY, x,
        Qp, nullptr, nullptr,
        nullptr, nullptr, nullptr,
        nullptr, nullptr, nullptr,
        4096, 1024, 1024);

    // h = LN1 -> fp32 g_K + bf16 split (Qhi/Qlo reused)
    ln_kernel<<<4096, blk>>>(Qp, ln1w, ln1b, Kp, Qhi, Qlo);

    // FFN1: gelu(h@W1+b1) -> bf16 split only
    tgemm_kernel<1><<<dim3(32, 32, 1), blk, TG_SMEM>>>(
        Qhi, Qlo, Whi + 4 * MB, Wlo + 4 * MB, 0, b1, b1, b1, nullptr,
        nullptr, nullptr, nullptr,
        Ahi, nullptr, nullptr,
        Alo, nullptr, nullptr,
        4096, 4096, 1024);

    // FFN2: ff@W2+b2+h -> fp32 g_V
    tgemm_kernel<2><<<dim3(8, 32, 1), blk, TG_SMEM>>>(
        Ahi, Alo, Whi + 8 * MB, Wlo + 8 * MB, 0, b2, b2, b2, Kp,
        Vp, nullptr, nullptr,
        nullptr, nullptr, nullptr,
        nullptr, nullptr, nullptr,
        4096, 1024, 4096);

    // out = LN2
    ln_kernel<<<4096, blk>>>(Vp, ln2w, ln2b, out, nullptr, nullptr);
}

// round 17
// speedup vs baseline: 1.1796x; 1.0770x over previous
#include <cuda_runtime.h>
#include <cuda_bf16.h>
#include <math.h>
#include <stdint.h>

// ---------------------------------------------------------------------------
// Scratch (__device__ globals; no allocations allowed)
// ---------------------------------------------------------------------------
__device__ float g_Q [(size_t)4096 * 1024];   // out-proj result (a+x)
__device__ float g_K [(size_t)4096 * 1024];   // h = LN1(...)
__device__ float g_V [(size_t)4096 * 1024];   // ffn2 result fp32
__device__ float g_Y [(size_t)4096 * 1024];   // Yhi/Ylo bf16 halves
__device__ unsigned short g_Ahi[(size_t)4096 * 4096];
__device__ unsigned short g_Alo[(size_t)4096 * 4096];
__device__ unsigned short g_Whi[(size_t)12 * 1024 * 1024];
__device__ unsigned short g_Wlo[(size_t)12 * 1024 * 1024];
__device__ unsigned short g_Qhi [(size_t)4096 * 1024];
__device__ unsigned short g_Qlo [(size_t)4096 * 1024];
__device__ unsigned short g_Khi [(size_t)4096 * 1024];
__device__ unsigned short g_Klo [(size_t)4096 * 1024];
__device__ unsigned short g_Vhi [(size_t)4096 * 1024];  // V natural layout
__device__ unsigned short g_Vlo [(size_t)4096 * 1024];

__device__ __forceinline__ uint32_t smem_u32(const void* p) {
    uint32_t a;
    asm("{ .reg .u64 t; cvta.to.shared.u64 t, %1; cvt.u32.u64 %0, t; }"
        : "=r"(a) : "l"(p));
    return a;
}
__device__ __forceinline__ void cpa16(uint32_t s, const void* g) {
    asm volatile("cp.async.cg.shared.global [%0], [%1], 16;"
                 :: "r"(s), "l"(__cvta_generic_to_global(g)) : "memory");
}
__device__ __forceinline__ void cp_commit() {
    asm volatile("cp.async.commit_group;" ::: "memory");
}
template<int N>
__device__ __forceinline__ void cp_wait() {
    asm volatile("cp.async.wait_group %0;" :: "n"(N) : "memory");
}
__device__ __forceinline__ void ldm_x4(uint32_t* r, uint32_t saddr) {
    asm volatile("ldmatrix.sync.aligned.m8n8.x4.shared.b16 {%0,%1,%2,%3}, [%4];"
                 : "=r"(r[0]), "=r"(r[1]), "=r"(r[2]), "=r"(r[3]) : "r"(saddr));
}
__device__ __forceinline__ void ldm_x4_t(uint32_t* r, uint32_t saddr) {
    asm volatile("ldmatrix.sync.aligned.m8n8.x4.trans.shared.b16 {%0,%1,%2,%3}, [%4];"
                 : "=r"(r[0]), "=r"(r[1]), "=r"(r[2]), "=r"(r[3]) : "r"(saddr));
}
__device__ __forceinline__ void mma16816(float* c, const uint32_t* a, const uint32_t* b) {
    asm volatile("mma.sync.aligned.m16n8k16.row.col.f32.bf16.bf16.f32 "
                 "{%0,%1,%2,%3}, {%4,%5,%6,%7}, {%8,%9}, {%0,%1,%2,%3};"
                 : "+f"(c[0]), "+f"(c[1]), "+f"(c[2]), "+f"(c[3])
                 : "r"(a[0]), "r"(a[1]), "r"(a[2]), "r"(a[3]),
                   "r"(b[0]), "r"(b[1]));
}
__device__ __forceinline__ float ex2(float x) {
    float r;
    asm("ex2.approx.f32 %0, %1;" : "=f"(r) : "f"(x));
    return r;
}
__device__ __forceinline__ uint32_t cvt_bf16x2(float lo, float hi) {
    uint32_t r;
    asm("cvt.rn.bf16x2.f32 %0, %1, %2;" : "=r"(r) : "f"(hi), "f"(lo));
    return r;
}
__device__ __forceinline__ float gelu_f(float v) {
    return 0.5f * v * (1.0f + erff(v * 0.70710678118654752f));
}
__device__ __forceinline__ void bfsplit2(float x, float y, uint32_t& hi, uint32_t& lo) {
    __nv_bfloat16 hx = __float2bfloat16(x), hy = __float2bfloat16(y);
    hi = ((uint32_t)(*(unsigned short*)&hy) << 16) | (uint32_t)(*(unsigned short*)&hx);
    __nv_bfloat16 lx = __float2bfloat16(x - __bfloat162float(hx));
    __nv_bfloat16 ly = __float2bfloat16(y - __bfloat162float(hy));
    lo = ((uint32_t)(*(unsigned short*)&ly) << 16) | (uint32_t)(*(unsigned short*)&lx);
}
__device__ __forceinline__ void split1(float v, unsigned short& h, unsigned short& l) {
    __nv_bfloat16 hb = __float2bfloat16(v);
    __nv_bfloat16 lb = __float2bfloat16(v - __bfloat162float(hb));
    h = *(unsigned short*)&hb;
    l = *(unsigned short*)&lb;
}

// ---------------------------------------------------------------------------
// Tensor-core dense GEMM (R13/R15 best config; epilogue lo-store now
// guarded on Cl so producers can emit hi-only bf16 outputs).
// ---------------------------------------------------------------------------
#define ROWB   80
#define TILEB  (128 * ROWB)
#define STAGEB (4 * TILEB)
#define NSTAGE 2
#define TG_SMEM (NSTAGE * STAGEB)    // 81920 -> 2 CTAs/SM

template<int EPI>
__global__ __launch_bounds__(256, 2)
void tgemm_kernel(const unsigned short* __restrict__ Ahi16,
                  const unsigned short* __restrict__ Alo16,
                  const unsigned short* __restrict__ Whi16,
                  const unsigned short* __restrict__ Wlo16,
                  size_t wz,
                  const float* __restrict__ bias0, const float* __restrict__ bias1,
                  const float* __restrict__ bias2,
                  const float* __restrict__ R,
                  float* __restrict__ Cf0, float* __restrict__ Cf1, float* __restrict__ Cf2,
                  unsigned short* __restrict__ Ch0, unsigned short* __restrict__ Ch1,
                  unsigned short* __restrict__ Ch2,
                  unsigned short* __restrict__ Cl0, unsigned short* __restrict__ Cl1,
                  unsigned short* __restrict__ Cl2,
                  int M, int N, int K)
{
    extern __shared__ __align__(128) char smem[];
    const int z = blockIdx.z;
    const unsigned short* Bh = Whi16 + wz * z;
    const unsigned short* Bl = Wlo16 + wz * z;
    const float* bias = (z == 0) ? bias0 : (z == 1) ? bias1 : bias2;
    float*          Cf = (z == 0) ? Cf0 : (z == 1) ? Cf1 : Cf2;
    unsigned short* Ch = (z == 0) ? Ch0 : (z == 1) ? Ch1 : Ch2;
    unsigned short* Cl = (z == 0) ? Cl0 : (z == 1) ? Cl1 : Cl2;

    const uint32_t sbase = smem_u32(smem);
    const int t    = threadIdx.x;
    const int wid  = t >> 5;
    const int lane = t & 31;
    const int m0   = blockIdx.y * 128;
    const int n0   = blockIdx.x * 128;
    const int wm   = (wid & 1) * 64;
    const int wn   = (wid >> 1) * 32;

    const int lrow = t >> 1;
    const int lu   = (t & 1) * 2;
    const unsigned short* pAh = Ahi16 + (size_t)(m0 + lrow) * K + lu * 8;
    const unsigned short* pAl = Alo16 + (size_t)(m0 + lrow) * K + lu * 8;
    const unsigned short* pBh = Bh    + (size_t)(n0 + lrow) * K + lu * 8;
    const unsigned short* pBl = Bl    + (size_t)(n0 + lrow) * K + lu * 8;
    const uint32_t sRow = (uint32_t)lrow * ROWB + lu * 16;

    #define LOAD_STAGE(cc, ss) do {                                        \
        const uint32_t sb_ = sbase + (ss) * STAGEB + sRow;                  \
        const size_t  ko_ = (size_t)(cc) * 32;                              \
        cpa16(sb_ + 0 * TILEB,      pAh + ko_);                             \
        cpa16(sb_ + 0 * TILEB + 16, pAh + ko_ + 8);                         \
        cpa16(sb_ + 1 * TILEB,      pAl + ko_);                             \
        cpa16(sb_ + 1 * TILEB + 16, pAl + ko_ + 8);                         \
        cpa16(sb_ + 2 * TILEB,      pBh + ko_);                             \
        cpa16(sb_ + 2 * TILEB + 16, pBh + ko_ + 8);                         \
        cpa16(sb_ + 3 * TILEB,      pBl + ko_);                             \
        cpa16(sb_ + 3 * TILEB + 16, pBl + ko_ + 8);                         \
    } while (0)

    const uint32_t laneA = (uint32_t)(lane & 15) * ROWB + (lane >> 4) * 16;
    const uint32_t laneB = (uint32_t)((lane & 7) + ((lane >> 4) << 3)) * ROWB
                         + ((lane >> 3) & 1) * 16;

    float acc[4][4][4];
    #pragma unroll
    for (int i = 0; i < 4; ++i)
        #pragma unroll
        for (int j = 0; j < 4; ++j)
            #pragma unroll
            for (int q = 0; q < 4; ++q) acc[i][j][q] = 0.0f;

    const int NC = K >> 5;
    LOAD_STAGE(0, 0); cp_commit();

    for (int c = 0; c < NC; ++c) {
        const int s = c & 1;
        cp_wait<0>();
        __syncthreads();
        if (c + 1 < NC) LOAD_STAGE(c + 1, s ^ 1);
        cp_commit();

        const uint32_t stg = sbase + s * STAGEB;
        #pragma unroll
        for (int ks = 0; ks < 2; ++ks) {
            const uint32_t kb = ks * 32;
            uint32_t bh[4][2], bl[4][2];
            #pragma unroll
            for (int p = 0; p < 2; ++p) {
                uint32_t rb[4], rl[4];
                const uint32_t ra = stg + (uint32_t)(wn + p * 16) * ROWB + laneB + kb;
                ldm_x4(rb, ra + 2 * TILEB);
                ldm_x4(rl, ra + 3 * TILEB);
                bh[p * 2 + 0][0] = rb[0]; bh[p * 2 + 0][1] = rb[1];
                bh[p * 2 + 1][0] = rb[2]; bh[p * 2 + 1][1] = rb[3];
                bl[p * 2 + 0][0] = rl[0]; bl[p * 2 + 0][1] = rl[1];
                bl[p * 2 + 1][0] = rl[2]; bl[p * 2 + 1][1] = rl[3];
            }
            #pragma unroll
            for (int mf = 0; mf < 4; ++mf) {
                uint32_t ah[4], al[4];
                const uint32_t ra = stg + (uint32_t)(wm + mf * 16) * ROWB + laneA + kb;
                ldm_x4(ah, ra + 0 * TILEB);
                ldm_x4(al, ra + 1 * TILEB);
                #pragma unroll
                for (int nf = 0; nf < 4; ++nf) {
                    mma16816(acc[mf][nf], ah, bh[nf]);
                    mma16816(acc[mf][nf], ah, bl[nf]);
                    mma16816(acc[mf][nf], al, bh[nf]);
                }
            }
        }
    }

    const int rbase = lane >> 2;
    const int cbase = (lane & 3) * 2;
    #pragma unroll
    for (int mf = 0; mf < 4; ++mf) {
        #pragma unroll
        for (int nf = 0; nf < 4; ++nf) {
            const int col = n0 + wn + nf * 8 + cbase;
            const float2 bb = *(const float2*)&bias[col];
            #pragma unroll
            for (int h = 0; h < 2; ++h) {
                const int row = m0 + wm + mf * 16 + rbase + h * 8;
                float2 rv;
                rv.x = acc[mf][nf][h * 2 + 0] + bb.x;
                rv.y = acc[mf][nf][h * 2 + 1] + bb.y;
                if (EPI == 1) { rv.x = gelu_f(rv.x); rv.y = gelu_f(rv.y); }
                if (EPI == 2) {
                    const float2 rr = *(const float2*)&R[(size_t)row * N + col];
                    rv.x += rr.x; rv.y += rr.y;
                }
                if (Cf) *(float2*)&Cf[(size_t)row * N + col] = rv;
                if (Ch) {
                    if (Cl) {
                        uint32_t hi, lo;
                        bfsplit2(rv.x, rv.y, hi, lo);
                        *(uint32_t*)&Ch[(size_t)row * N + col] = hi;
                        *(uint32_t*)&Cl[(size_t)row * N + col] = lo;
                    } else {
                        *(uint32_t*)&Ch[(size_t)row * N + col] = cvt_bf16x2(rv.x, rv.y);
                    }
                }
            }
        }
    }
    #undef LOAD_STAGE
}

// ---------------------------------------------------------------------------
// Fused prep kernel (R15 — unchanged): all weight transposes + x split.
// ---------------------------------------------------------------------------
__global__ __launch_bounds__(256)
void prep_kernel(const float* __restrict__ WQ, const float* __restrict__ WK,
                 const float* __restrict__ WV, const float* __restrict__ WY,
                 const float* __restrict__ W1, const float* __restrict__ W2,
                 const float* __restrict__ x,
                 unsigned short* __restrict__ Whi, unsigned short* __restrict__ Wlo,
                 unsigned short* __restrict__ Ahi, unsigned short* __restrict__ Alo)
{
    __shared__ float s[32][33];
    const int bx = blockIdx.x;
    const int t  = threadIdx.x;
    const size_t MB = (size_t)1024 * 1024;

    if (bx >= 12288) {
        const int i = (bx - 12288) * 256 + t;
        float4 v = ((const float4*)x)[i];
        ushort4 h, l;
        split1(v.x, h.x, l.x); split1(v.y, h.y, l.y);
        split1(v.z, h.z, l.z); split1(v.w, h.w, l.w);
        ((ushort4*)Ahi)[i] = h;
        ((ushort4*)Alo)[i] = l;
        return;
    }

    const float* W;
    unsigned short *Th, *Tl;
    int K, N, nb, kb;
    if (bx < 4096) {
        const int z   = bx >> 10;
        const int blk = bx & 1023;
        W  = (z == 0) ? WQ : (z == 1) ? WK : (z == 2) ? WV : WY;
        Th = Whi + MB * z;  Tl = Wlo + MB * z;
        K = 1024; N = 1024;
        nb = (blk & 31) * 32; kb = (blk >> 5) * 32;
    } else if (bx < 8192) {
        const int blk = bx - 4096;
        W = W1; Th = Whi + 4 * MB; Tl = Wlo + 4 * MB;
        K = 1024; N = 4096;
        nb = (blk & 127) * 32; kb = (blk >> 7) * 32;
    } else {
        const int blk = bx - 8192;
        W = W2; Th = Whi + 8 * MB; Tl = Wlo + 8 * MB;
        K = 4096; N = 1024;
        nb = (blk & 31) * 32; kb = (blk >> 5) * 32;
    }

    const int tx = t & 31, ty = t >> 5;
    #pragma unroll
    for (int i = 0; i < 4; ++i)
        s[ty + i * 8][tx] = W[(size_t)(kb + ty + i * 8) * N + nb + tx];
    __syncthreads();
    #pragma unroll
    for (int i = 0; i < 4; ++i) {
        const float v = s[tx][ty + i * 8];
        unsigned short h, l;
        split1(v, h, l);
        const size_t o = (size_t)(nb + ty + i * 8) * K + kb + tx;
        Th[o] = h; Tl[o] = l;
    }
}

// ---------------------------------------------------------------------------
// Flash attention via mma.sync; V natural layout (ldmatrix.trans).
// 256 threads / 128 queries, 3-stage KV pipeline, single sync per tile.
// Precision: S = Qhi*(Khi+Klo) [2-product], PV = P*Vhi [1-product].
// SMEM: Qhi 18KB + 3 stages x {Khi,Klo,Vhi} 27KB + mask.
// ---------------------------------------------------------------------------
#define AROWB   144
#define ATT_KV  18432                      // Q-hi region size
#define ATT_STG 27648                      // 3 tiles * 64*144
#define ATT_NST 3
#define ATT_MB  (ATT_KV + ATT_NST * ATT_STG)   // 101376
#define ATT_SMEM (ATT_MB + 1024)
#define SCL2    0.18033688011112042591f    // 0.125 * log2(e)

__global__ __launch_bounds__(256, 1)
void attn_mma_kernel(const unsigned short* __restrict__ Qhi,
                     const unsigned short* __restrict__ Khi,
                     const unsigned short* __restrict__ Klo,
                     const unsigned short* __restrict__ Vhi,
                     const int* __restrict__ mask,
                     unsigned short* __restrict__ Yhi,
                     unsigned short* __restrict__ Ylo)
{
    extern __shared__ __align__(128) char smem[];
    const uint32_t sb = smem_u32(smem);
    const int t    = threadIdx.x;
    const int lane = t & 31;
    const int w    = t >> 5;
    const int q0   = blockIdx.x * 128;
    const int bh   = blockIdx.y;
    const int tokb = (bh >> 4) * 2048;
    const int colb = (bh & 15) * 64;

    const uint32_t laneA = (uint32_t)(lane & 15) * AROWB + (lane >> 4) * 16;
    const uint32_t laneB = (uint32_t)((lane & 7) + ((lane >> 4) << 3)) * AROWB
                         + ((lane >> 3) & 1) * 16;
    const uint32_t laneBT = (uint32_t)((lane & 7) + ((lane >> 3) & 1) * 8) * AROWB
                          + (lane >> 4) * 16;

    // Q-hi tile: 128 rows x 128B; 256 threads, 4 chunks each
    {
        const int row = t >> 1;
        const size_t g = (size_t)(tokb + q0 + row) * 1024 + colb;
        const uint32_t sr = (uint32_t)row * AROWB;
        #pragma unroll
        for (int i = 0; i < 4; ++i) {
            const int ch = (t & 1) * 4 + i;
            cpa16(sb + sr + ch * 16, Qhi + g + ch * 8);
        }
    }

    auto LOADKV = [&](int tile, int s) {
        const int kv0 = tile * 64;
        const int row = t >> 2;
        const int q2  = t & 3;
        const uint32_t st = sb + ATT_KV + s * ATT_STG;
        const size_t gk = (size_t)(tokb + kv0 + row) * 1024 + colb;
        const uint32_t sr = (uint32_t)row * AROWB;
        #pragma unroll
        for (int i = 0; i < 2; ++i) {
            const int ch = q2 * 2 + i;
            cpa16(st +         sr + ch * 16, Khi + gk + ch * 8);
            cpa16(st +  9216 + sr + ch * 16, Klo + gk + ch * 8);
            cpa16(st + 18432 + sr + ch * 16, Vhi + gk + ch * 8);
        }
        if (t < 64) {
            float* mb = (float*)(smem + ATT_MB) + s * 64;
            mb[t] = (mask[tokb + kv0 + t] == 0) ? -1e30f : 0.0f;
        }
    };

    LOADKV(0, 0); cp_commit();
    LOADKV(1, 1); cp_commit();

    uint32_t qh[4][4];

    float of[8][4];
    #pragma unroll
    for (int i = 0; i < 8; ++i)
        #pragma unroll
        for (int j = 0; j < 4; ++j) of[i][j] = 0.0f;
    float mA = -1e30f, mB = -1e30f, lA = 0.0f, lB = 0.0f;
    const int c0 = (lane & 3) * 2;

    for (int tile = 0; tile < 32; ++tile) {
        const int s = tile % ATT_NST;
        cp_wait<1>();
        __syncthreads();
        if (tile + 2 < 32) LOADKV(tile + 2, (tile + 2) % ATT_NST);
        cp_commit();

        if (tile == 0) {
            #pragma unroll
            for (int fk = 0; fk < 4; ++fk) {
                const uint32_t ra = sb + (uint32_t)(w * 16) * AROWB + laneA + fk * 32;
                ldm_x4(qh[fk], ra);
            }
        }

        const uint32_t kst = sb + ATT_KV + s * ATT_STG;
        const float* mb = (const float*)(smem + ATT_MB) + s * 64;

        float sf[8][4];
        #pragma unroll
        for (int i = 0; i < 8; ++i)
            #pragma unroll
            for (int j = 0; j < 4; ++j) sf[i][j] = 0.0f;

        // S = Qhi * (Khi + Klo): 2-product
        #pragma unroll
        for (int fk = 0; fk < 4; ++fk) {
            uint32_t kh[8][2], kl[8][2];
            #pragma unroll
            for (int p = 0; p < 4; ++p) {
                uint32_t r0[4], r1[4];
                const uint32_t ra = kst + (uint32_t)(p * 16) * AROWB + laneB + fk * 32;
                ldm_x4(r0, ra);
                ldm_x4(r1, ra + 9216);
                kh[p * 2 + 0][0] = r0[0]; kh[p * 2 + 0][1] = r0[1];
                kh[p * 2 + 1][0] = r0[2]; kh[p * 2 + 1][1] = r0[3];
                kl[p * 2 + 0][0] = r1[0]; kl[p * 2 + 0][1] = r1[1];
                kl[p * 2 + 1][0] = r1[2]; kl[p * 2 + 1][1] = r1[3];
            }
            #pragma unroll
            for (int nf = 0; nf < 8; ++nf) {
                mma16816(sf[nf], qh[fk], kh[nf]);
                mma16816(sf[nf], qh[fk], kl[nf]);
            }
        }

        // online softmax in exp2 domain
        float pmA = -1e30f, pmB = -1e30f;
        #pragma unroll
        for (int nf = 0; nf < 8; ++nf) {
            const float m0 = mb[nf * 8 + c0];
            const float m1 = mb[nf * 8 + c0 + 1];
            sf[nf][0] = fmaf(sf[nf][0], SCL2, m0);
            sf[nf][1] = fmaf(sf[nf][1], SCL2, m1);
            sf[nf][2] = fmaf(sf[nf][2], SCL2, m0);
            sf[nf][3] = fmaf(sf[nf][3], SCL2, m1);
            pmA = fmaxf(pmA, fmaxf(sf[nf][0], sf[nf][1]));
            pmB = fmaxf(pmB, fmaxf(sf[nf][2], sf[nf][3]));
        }
        pmA = fmaxf(pmA, __shfl_xor_sync(0xffffffffu, pmA, 1));
        pmA = fmaxf(pmA, __shfl_xor_sync(0xffffffffu, pmA, 2));
        pmB = fmaxf(pmB, __shfl_xor_sync(0xffffffffu, pmB, 1));
        pmB = fmaxf(pmB, __shfl_xor_sync(0xffffffffu, pmB, 2));
        const float mnA = fmaxf(mA, pmA), mnB = fmaxf(mB, pmB);
        const float alA = ex2(mA - mnA), alB = ex2(mB - mnB);
        mA = mnA; mB = mnB;
        float rsA = 0.0f, rsB = 0.0f;
        #pragma unroll
        for (int nf = 0; nf < 8; ++nf) {
            sf[nf][0] = ex2(sf[nf][0] - mnA);
            sf[nf][1] = ex2(sf[nf][1] - mnA);
            sf[nf][2] = ex2(sf[nf][2] - mnB);
            sf[nf][3] = ex2(sf[nf][3] - mnB);
            rsA += sf[nf][0] + sf[nf][1];
            rsB += sf[nf][2] + sf[nf][3];
        }
        rsA += __shfl_xor_sync(0xffffffffu, rsA, 1);
        rsA += __shfl_xor_sync(0xffffffffu, rsA, 2);
        rsB += __shfl_xor_sync(0xffffffffu, rsB, 1);
        rsB += __shfl_xor_sync(0xffffffffu, rsB, 2);
        lA = lA * alA + rsA;
        lB = lB * alB + rsB;
        #pragma unroll
        for (int nf = 0; nf < 8; ++nf) {
            of[nf][0] *= alA; of[nf][1] *= alA;
            of[nf][2] *= alB; of[nf][3] *= alB;
        }

        // O += P @ Vhi: single product
        #pragma unroll
        for (int fk = 0; fk < 4; ++fk) {
            uint32_t aHi[4];
            aHi[0] = cvt_bf16x2(sf[2 * fk][0],     sf[2 * fk][1]);
            aHi[1] = cvt_bf16x2(sf[2 * fk][2],     sf[2 * fk][3]);
            aHi[2] = cvt_bf16x2(sf[2 * fk + 1][0], sf[2 * fk + 1][1]);
            aHi[3] = cvt_bf16x2(sf[2 * fk + 1][2], sf[2 * fk + 1][3]);
            uint32_t vh[8][2];
            #pragma unroll
            for (int p = 0; p < 4; ++p) {
                uint32_t r0[4];
                const uint32_t ra = kst + 18432 + (uint32_t)(fk * 16) * AROWB
                                  + laneBT + p * 32;
                ldm_x4_t(r0, ra);
                vh[p * 2 + 0][0] = r0[0]; vh[p * 2 + 0][1] = r0[1];
                vh[p * 2 + 1][0] = r0[2]; vh[p * 2 + 1][1] = r0[3];
            }
            #pragma unroll
            for (int nf = 0; nf < 8; ++nf)
                mma16816(of[nf], aHi, vh[nf]);
        }
    }

    const float iA = 1.0f / lA, iB = 1.0f / lB;
    const int rA = lane >> 2;
    const int rowA = tokb + q0 + w * 16 + rA;
    #pragma unroll
    for (int nf = 0; nf < 8; ++nf) {
        const int col = colb + nf * 8 + c0;
        uint32_t h0, l0, h1, l1;
        bfsplit2(of[nf][0] * iA, of[nf][1] * iA, h0, l0);
        bfsplit2(of[nf][2] * iB, of[nf][3] * iB, h1, l1);
        *(uint32_t*)&Yhi[(size_t)rowA * 1024 + col]       = h0;
        *(uint32_t*)&Ylo[(size_t)rowA * 1024 + col]       = l0;
        *(uint32_t*)&Yhi[(size_t)(rowA + 8) * 1024 + col] = h1;
        *(uint32_t*)&Ylo[(size_t)(rowA + 8) * 1024 + col] = l1;
    }
}

// ---------------------------------------------------------------------------
// LayerNorm: one row per CTA; optional fused bf16 hi/lo split output
// ---------------------------------------------------------------------------
__global__ __launch_bounds__(256)
void ln_kernel(const float* __restrict__ X, const float* __restrict__ w,
               const float* __restrict__ b, float* __restrict__ out,
               unsigned short* __restrict__ hi, unsigned short* __restrict__ lo)
{
    __shared__ float red[2][8];
    const int t = threadIdx.x;
    const size_t row = blockIdx.x;
    float4 xv = *(const float4*)&X[row * 1024 + t * 4];
    float s  = xv.x + xv.y + xv.z + xv.w;
    float s2 = xv.x * xv.x + xv.y * xv.y + xv.z * xv.z + xv.w * xv.w;
    #pragma unroll
    for (int off = 16; off; off >>= 1) {
        s  += __shfl_xor_sync(0xffffffffu, s,  off);
        s2 += __shfl_xor_sync(0xffffffffu, s2, off);
    }
    if ((t & 31) == 0) { red[0][t >> 5] = s; red[1][t >> 5] = s2; }
    __syncthreads();
    float S = 0.0f, S2 = 0.0f;
    #pragma unroll
    for (int i = 0; i < 8; ++i) { S += red[0][i]; S2 += red[1][i]; }
    const float mean = S * (1.0f / 1024.0f);
    const float var  = S2 * (1.0f / 1024.0f) - mean * mean;
    const float rstd = rsqrtf(var + 1e-5f);
    float4 wv = *(const float4*)&w[t * 4];
    float4 bv = *(const float4*)&b[t * 4];
    float4 r;
    r.x = (xv.x - mean) * rstd * wv.x + bv.x;
    r.y = (xv.y - mean) * rstd * wv.y + bv.y;
    r.z = (xv.z - mean) * rstd * wv.z + bv.z;
    r.w = (xv.w - mean) * rstd * wv.w + bv.w;
    if (out) *(float4*)&out[row * 1024 + t * 4] = r;
    if (hi) {
        uint32_t h0, l0, h1, l1;
        bfsplit2(r.x, r.y, h0, l0);
        bfsplit2(r.z, r.w, h1, l1);
        uint2 hv = make_uint2(h0, h1), lv = make_uint2(l0, l1);
        *(uint2*)&hi[row * 1024 + t * 4] = hv;
        *(uint2*)&lo[row * 1024 + t * 4] = lv;
    }
}

// ---------------------------------------------------------------------------
// launch
// ---------------------------------------------------------------------------
extern "C" void kernel_launch(void* const* d_in, const int* in_sizes, int n_in,
                              void* d_out, int out_size)
{
    (void)in_sizes; (void)n_in; (void)out_size;
    const float* x    = (const float*)d_in[0];
    const int*   mask = (const int*)  d_in[1];
    const float* WQ   = (const float*)d_in[2];
    const float* bQ   = (const float*)d_in[3];
    const float* WK   = (const float*)d_in[4];
    const float* bK   = (const float*)d_in[5];
    const float* WV   = (const float*)d_in[6];
    const float* bV   = (const float*)d_in[7];
    const float* WY   = (const float*)d_in[8];
    const float* bY   = (const float*)d_in[9];
    const float* ln1w = (const float*)d_in[10];
    const float* ln1b = (const float*)d_in[11];
    const float* ln2w = (const float*)d_in[12];
    const float* ln2b = (const float*)d_in[13];
    const float* W1   = (const float*)d_in[14];
    const float* b1   = (const float*)d_in[15];
    const float* W2   = (const float*)d_in[16];
    const float* b2   = (const float*)d_in[17];
    float* out = (float*)d_out;

    float *Qp, *Kp, *Vp, *Yp;
    unsigned short *Ahi, *Alo, *Whi, *Wlo;
    unsigned short *Qhi, *Qlo, *Khi, *Klo, *Vhi;
    cudaGetSymbolAddress((void**)&Qp,  g_Q);
    cudaGetSymbolAddress((void**)&Kp,  g_K);
    cudaGetSymbolAddress((void**)&Vp,  g_V);
    cudaGetSymbolAddress((void**)&Yp,  g_Y);
    cudaGetSymbolAddress((void**)&Ahi, g_Ahi);
    cudaGetSymbolAddress((void**)&Alo, g_Alo);
    cudaGetSymbolAddress((void**)&Whi, g_Whi);
    cudaGetSymbolAddress((void**)&Wlo, g_Wlo);
    cudaGetSymbolAddress((void**)&Qhi, g_Qhi);
    cudaGetSymbolAddress((void**)&Qlo, g_Qlo);
    cudaGetSymbolAddress((void**)&Khi, g_Khi);
    cudaGetSymbolAddress((void**)&Klo, g_Klo);
    cudaGetSymbolAddress((void**)&Vhi, g_Vhi);

    unsigned short* Yhi = (unsigned short*)Yp;
    unsigned short* Ylo = (unsigned short*)Yp + (size_t)4096 * 1024;

    const size_t MB = (size_t)1024 * 1024;

    cudaFuncSetAttribute(tgemm_kernel<0>,
                         cudaFuncAttributeMaxDynamicSharedMemorySize, TG_SMEM);
    cudaFuncSetAttribute(tgemm_kernel<1>,
                         cudaFuncAttributeMaxDynamicSharedMemorySize, TG_SMEM);
    cudaFuncSetAttribute(tgemm_kernel<2>,
                         cudaFuncAttributeMaxDynamicSharedMemorySize, TG_SMEM);
    cudaFuncSetAttribute(attn_mma_kernel,
                         cudaFuncAttributeMaxDynamicSharedMemorySize, ATT_SMEM);

    dim3 blk(256);

    // all prep (6 weight transposes + x split) in ONE launch
    prep_kernel<<<16384, blk>>>(WQ, WK, WV, WY, W1, W2, x, Whi, Wlo, Ahi, Alo);

    // QKV: Q -> hi only; K -> hi+lo; V -> hi only (natural layout)
    tgemm_kernel<0><<<dim3(8, 32, 3), blk, TG_SMEM>>>(
        Ahi, Alo, Whi, Wlo, MB, bQ, bK, bV, nullptr,
        nullptr, nullptr, nullptr,
        Qhi, Khi, Vhi,
        nullptr, Klo, nullptr,
        4096, 1024, 1024);

    // attention -> Yhi/Ylo bf16
    attn_mma_kernel<<<dim3(16, 32), blk, ATT_SMEM>>>(
        Qhi, Khi, Klo, Vhi, mask, Yhi, Ylo);

    // out-proj + residual x -> fp32 g_Q
    tgemm_kernel<2><<<dim3(8, 32, 1), blk, TG_SMEM>>>(
        Yhi, Ylo, Whi + 3 * MB, Wlo + 3 * MB, 0, bY, bY, bY, x,
        Qp, nullptr, nullptr,
        nullptr, nullptr, nullptr,
        nullptr, nullptr, nullptr,
        4096, 1024, 1024);

    // h = LN1 -> fp32 g_K + bf16 split (Qhi/Qlo reused)
    ln_kernel<<<4096, blk>>>(Qp, ln1w, ln1b, Kp, Qhi, Qlo);

    // FFN1: gelu(h@W1+b1) -> bf16 split only
    tgemm_kernel<1><<<dim3(32, 32, 1), blk, TG_SMEM>>>(
        Qhi, Qlo, Whi + 4 * MB, Wlo + 4 * MB, 0, b1, b1, b1, nullptr,
        nullptr, nullptr, nullptr,
        Ahi, nullptr, nullptr,
        Alo, nullptr, nullptr,
        4096, 4096, 1024);

    // FFN2: ff@W2+b2+h -> fp32 g_V
    tgemm_kernel<2><<<dim3(8, 32, 1), blk, TG_SMEM>>>(
        Ahi, Alo, Whi + 8 * MB, Wlo + 8 * MB, 0, b2, b2, b2, Kp,
        Vp, nullptr, nullptr,
        nullptr, nullptr, nullptr,
        nullptr, nullptr, nullptr,
        4096, 1024, 4096);

    // out = LN2
    ln_kernel<<<4096, blk>>>(Vp, ln2w, ln2b, out, nullptr, nullptr);
}